// round 2
// baseline (speedup 1.0000x reference)
#include <cuda_runtime.h>
#include <math.h>

#define Bb 2
#define Nn 2048
#define Kk 48
#define Cc 128
#define FFdim 512
#define NODES (Bb*Nn)          /* 4096 */
#define EPSf 1e-5f
#define INV_SCALE (1.0f/30.0f)

// scratch (device globals; no allocations allowed)
__device__ float g_hV1[NODES*Cc];
__device__ float g_hV2[NODES*Cc];

// ---------------- packed fp32 helpers (fma.rn.f32x2: 2x FFMA rate) ----------
static __device__ __forceinline__ unsigned long long dup2(float x){
    unsigned long long r;
    asm("mov.b64 %0, {%1, %1};" : "=l"(r) : "f"(x));
    return r;
}
static __device__ __forceinline__ unsigned long long pk2(float a, float b){
    unsigned long long r;
    asm("mov.b64 %0, {%1, %2};" : "=l"(r) : "f"(a), "f"(b));
    return r;
}
static __device__ __forceinline__ void fma2(unsigned long long &d,
                                            unsigned long long a,
                                            unsigned long long b){
    asm("fma.rn.f32x2 %0, %1, %2, %0;" : "+l"(d) : "l"(a), "l"(b));
}
static __device__ __forceinline__ float2 un2(unsigned long long v){
    float lo, hi;
    asm("mov.b64 {%0, %1}, %2;" : "=f"(lo), "=f"(hi) : "l"(v));
    return make_float2(lo, hi);
}
static __device__ __forceinline__ float gelu_f(float x){
    return 0.5f * x * (1.0f + erff(x * 0.70710678118654752440f));
}
static __device__ __forceinline__ float warp_sum(float v){
    #pragma unroll
    for (int o = 16; o; o >>= 1) v += __shfl_xor_sync(0xffffffffu, v, o);
    return v;
}

// ---------------- 48x128 GEMM tile: 256 thr, 6 rows x 4 cols per thread -----
static __device__ __forceinline__ void gemm_e(
    const float* __restrict__ Xs, int xld, int kc,
    const float* __restrict__ W,   // row-major [kc, 128]
    int txm, int txn,
    unsigned long long acc[6][2])
{
    const float* x0 = Xs + (txm*6+0)*xld;
    const float* x1 = Xs + (txm*6+1)*xld;
    const float* x2 = Xs + (txm*6+2)*xld;
    const float* x3 = Xs + (txm*6+3)*xld;
    const float* x4 = Xs + (txm*6+4)*xld;
    const float* x5 = Xs + (txm*6+5)*xld;
    const float* wp = W + txn*4;
    #pragma unroll 2
    for (int k = 0; k < kc; k += 2){
        ulonglong2 w0 = *(const ulonglong2*)(wp);
        ulonglong2 w1 = *(const ulonglong2*)(wp + 128);
        wp += 256;
        float2 v0 = *(const float2*)(x0 + k);
        float2 v1 = *(const float2*)(x1 + k);
        float2 v2 = *(const float2*)(x2 + k);
        float2 v3 = *(const float2*)(x3 + k);
        float2 v4 = *(const float2*)(x4 + k);
        float2 v5 = *(const float2*)(x5 + k);
        unsigned long long a;
        a = dup2(v0.x); fma2(acc[0][0], a, w0.x); fma2(acc[0][1], a, w0.y);
        a = dup2(v0.y); fma2(acc[0][0], a, w1.x); fma2(acc[0][1], a, w1.y);
        a = dup2(v1.x); fma2(acc[1][0], a, w0.x); fma2(acc[1][1], a, w0.y);
        a = dup2(v1.y); fma2(acc[1][0], a, w1.x); fma2(acc[1][1], a, w1.y);
        a = dup2(v2.x); fma2(acc[2][0], a, w0.x); fma2(acc[2][1], a, w0.y);
        a = dup2(v2.y); fma2(acc[2][0], a, w1.x); fma2(acc[2][1], a, w1.y);
        a = dup2(v3.x); fma2(acc[3][0], a, w0.x); fma2(acc[3][1], a, w0.y);
        a = dup2(v3.y); fma2(acc[3][0], a, w1.x); fma2(acc[3][1], a, w1.y);
        a = dup2(v4.x); fma2(acc[4][0], a, w0.x); fma2(acc[4][1], a, w0.y);
        a = dup2(v4.y); fma2(acc[4][0], a, w1.x); fma2(acc[4][1], a, w1.y);
        a = dup2(v5.x); fma2(acc[5][0], a, w0.x); fma2(acc[5][1], a, w0.y);
        a = dup2(v5.y); fma2(acc[5][0], a, w1.x); fma2(acc[5][1], a, w1.y);
    }
}

// ---------------- edge MLP kernel (MODE 0: node message; MODE 1: edge upd) --
// smem layout (floats): ctr[128] | ctrv[128] | Xs[48*260] | bufA[48*132] | bufB[48*132]
#define XLD 260
#define HLD 132
#define SMEM_E_FLOATS (256 + 48*XLD + 2*48*HLD)

template<int MODE>
__global__ void __launch_bounds__(256) edge_mlp_kernel(
    const float* __restrict__ nodes_in,   // h_V (MODE0); ignored in MODE1 (uses g_hV2)
    const float* __restrict__ hE,
    const int*   __restrict__ Eidx,
    const float* __restrict__ maskA,
    const float* __restrict__ Wa, const float* __restrict__ ba,
    const float* __restrict__ Wb, const float* __restrict__ bb,
    const float* __restrict__ Wc, const float* __restrict__ bc,
    const float* __restrict__ resid,      // MODE0: h_V (LN residual)
    const float* __restrict__ gam, const float* __restrict__ bet,
    float* __restrict__ outp)             // MODE1: h_E output; MODE0 writes g_hV1
{
    extern __shared__ float sm[];
    float* ctr  = sm;
    float* ctrv = sm + 128;
    float* Xs   = sm + 256;
    float* bufA = Xs + 48*XLD;
    float* bufB = bufA + 48*HLD;
    __shared__ int   sidx[48];
    __shared__ float s_s[4], s_q[4];

    const float* nodes = (MODE == 0) ? nodes_in : (const float*)g_hV2;

    const int t    = threadIdx.x;
    const int node = blockIdx.x;
    const int bidx = node >> 11;          // N = 2048
    const int txn  = t & 31;
    const int txm  = t >> 5;

    if (t < 48)  sidx[t] = Eidx[node*48 + t];
    if (t < 128) ctr[t]  = nodes[node*128 + t];
    __syncthreads();

    // fill Xs: cols [0,128) = h_E, cols [128,256) = gathered neighbor
    for (int idx = t; idx < 48*128; idx += 256){
        int k = idx >> 7, c = idx & 127;
        Xs[k*XLD + c]       = hE[(node*48 + k)*128 + c];
        Xs[k*XLD + 128 + c] = nodes[(bidx*2048 + sidx[k])*128 + c];
    }
    // center contribution matvec: ctrv[c] = sum_{k<128} ctr[k]*Wa[k,c]
    {
        int c = t & 127, h = t >> 7;
        const float* wcol = Wa + c;
        float s = 0.f;
        #pragma unroll 8
        for (int k = h*64; k < h*64 + 64; ++k)
            s = fmaf(ctr[k], wcol[k*128], s);
        bufB[h*128 + c] = s;
    }
    __syncthreads();
    if (t < 128) ctrv[t] = bufB[t] + bufB[128 + t];
    __syncthreads();

    unsigned long long acc[6][2];
    const int c0 = txn*4;

    // GEMM1: [48,256] x [256,128] (W rows 128..383) + ctrv + bias, gelu -> bufA
    {
        unsigned long long i0 = pk2(ctrv[c0]   + ba[c0],   ctrv[c0+1] + ba[c0+1]);
        unsigned long long i1 = pk2(ctrv[c0+2] + ba[c0+2], ctrv[c0+3] + ba[c0+3]);
        #pragma unroll
        for (int i = 0; i < 6; ++i){ acc[i][0] = i0; acc[i][1] = i1; }
        gemm_e(Xs, XLD, 256, Wa + 128*128, txm, txn, acc);
        #pragma unroll
        for (int i = 0; i < 6; ++i){
            float2 a = un2(acc[i][0]), b = un2(acc[i][1]);
            float* row = bufA + (txm*6+i)*HLD + c0;
            row[0] = gelu_f(a.x); row[1] = gelu_f(a.y);
            row[2] = gelu_f(b.x); row[3] = gelu_f(b.y);
        }
    }
    __syncthreads();

    // GEMM2: [48,128] x [128,128] + bias, gelu -> bufB
    {
        unsigned long long i0 = pk2(bb[c0], bb[c0+1]);
        unsigned long long i1 = pk2(bb[c0+2], bb[c0+3]);
        #pragma unroll
        for (int i = 0; i < 6; ++i){ acc[i][0] = i0; acc[i][1] = i1; }
        gemm_e(bufA, HLD, 128, Wb, txm, txn, acc);
        #pragma unroll
        for (int i = 0; i < 6; ++i){
            float2 a = un2(acc[i][0]), b = un2(acc[i][1]);
            float* row = bufB + (txm*6+i)*HLD + c0;
            row[0] = gelu_f(a.x); row[1] = gelu_f(a.y);
            row[2] = gelu_f(b.x); row[3] = gelu_f(b.y);
        }
    }
    __syncthreads();

    // GEMM3: [48,128] x [128,128] + bias -> msg (in regs)
    {
        unsigned long long i0 = pk2(bc[c0], bc[c0+1]);
        unsigned long long i1 = pk2(bc[c0+2], bc[c0+3]);
        #pragma unroll
        for (int i = 0; i < 6; ++i){ acc[i][0] = i0; acc[i][1] = i1; }
        gemm_e(bufB, HLD, 128, Wc, txm, txn, acc);
    }

    if (MODE == 0){
        // masked sum over K, /30, + residual, LN -> g_hV1
        float p0 = 0.f, p1 = 0.f, p2 = 0.f, p3 = 0.f;
        #pragma unroll
        for (int i = 0; i < 6; ++i){
            int r = txm*6 + i;
            float m = maskA[node*48 + r];
            float2 a = un2(acc[i][0]), b = un2(acc[i][1]);
            p0 = fmaf(m, a.x, p0); p1 = fmaf(m, a.y, p1);
            p2 = fmaf(m, b.x, p2); p3 = fmaf(m, b.y, p3);
        }
        float* red = bufA;             // bufA free after GEMM2 consumed it
        red[txm*HLD + c0 + 0] = p0;
        red[txm*HLD + c0 + 1] = p1;
        red[txm*HLD + c0 + 2] = p2;
        red[txm*HLD + c0 + 3] = p3;
        __syncthreads();
        float xv = 0.f;
        if (t < 128){
            float s = 0.f;
            #pragma unroll
            for (int m = 0; m < 8; ++m) s += red[m*HLD + t];
            xv = resid[node*128 + t] + s * INV_SCALE;
            float ws = warp_sum(xv);
            float wq = warp_sum(xv*xv);
            if ((t & 31) == 0){ s_s[t>>5] = ws; s_q[t>>5] = wq; }
        }
        __syncthreads();
        if (t < 128){
            float mean = (s_s[0]+s_s[1]+s_s[2]+s_s[3]) * 0.0078125f;
            float var  = (s_q[0]+s_q[1]+s_q[2]+s_q[3]) * 0.0078125f - mean*mean;
            float y = gam[t] * (xv - mean) * rsqrtf(var + EPSf) + bet[t];
            g_hV1[node*128 + t] = y;
        }
    } else {
        // per-edge: h_E + msg, LN over C -> outp
        float* Ms = bufA;
        #pragma unroll
        for (int i = 0; i < 6; ++i){
            float2 a = un2(acc[i][0]), b = un2(acc[i][1]);
            float* row = Ms + (txm*6+i)*HLD + c0;
            row[0] = a.x; row[1] = a.y; row[2] = b.x; row[3] = b.y;
        }
        __syncthreads();
        const int wid = t >> 5, lane = t & 31;
        for (int r = wid; r < 48; r += 8){
            const float* eRow = hE + (size_t)(node*48 + r)*128;
            const float* mRow = Ms + r*HLD;
            float x0 = eRow[lane]      + mRow[lane];
            float x1 = eRow[lane+32]   + mRow[lane+32];
            float x2 = eRow[lane+64]   + mRow[lane+64];
            float x3 = eRow[lane+96]   + mRow[lane+96];
            float s = warp_sum(x0+x1+x2+x3);
            float q = warp_sum(x0*x0 + x1*x1 + x2*x2 + x3*x3);
            float mean = s * 0.0078125f;
            float var  = q * 0.0078125f - mean*mean;
            float rs = rsqrtf(var + EPSf);
            float* oRow = outp + (size_t)(node*48 + r)*128;
            oRow[lane]    = gam[lane]   *(x0-mean)*rs + bet[lane];
            oRow[lane+32] = gam[lane+32]*(x1-mean)*rs + bet[lane+32];
            oRow[lane+64] = gam[lane+64]*(x2-mean)*rs + bet[lane+64];
            oRow[lane+96] = gam[lane+96]*(x3-mean)*rs + bet[lane+96];
        }
    }
}

// ---------------- FFN + LN2 + mask kernel (16 nodes per CTA) ----------------
#define FTILE 16
#define HLD2 516
#define SMEM_F_FLOATS (FTILE*HLD + FTILE*HLD2)

__global__ void __launch_bounds__(256) ffn_kernel(
    const float* __restrict__ Win, const float* __restrict__ bin,
    const float* __restrict__ Wout, const float* __restrict__ bout,
    const float* __restrict__ gam, const float* __restrict__ bet,
    const float* __restrict__ maskV,
    float* __restrict__ outV)
{
    extern __shared__ float sm[];
    float* Xs = sm;                  // [16][132]  (h_V1, then residual+ffn)
    float* Hs = sm + FTILE*HLD;      // [16][516]  hidden
    const int t = threadIdx.x;
    const int base = blockIdx.x * FTILE;
    const int tn = t & 31, tm = t >> 5;

    for (int idx = t; idx < FTILE*128; idx += 256){
        int r = idx >> 7, c = idx & 127;
        Xs[r*HLD + c] = g_hV1[(base + r)*128 + c];
    }
    __syncthreads();

    // hidden = gelu(X @ Win + bin): M=16, N=512, K=128
    {
        unsigned long long acc[2][4][2];
        #pragma unroll
        for (int p = 0; p < 4; ++p){
            int c0 = p*128 + tn*4;
            unsigned long long i0 = pk2(bin[c0],   bin[c0+1]);
            unsigned long long i1 = pk2(bin[c0+2], bin[c0+3]);
            acc[0][p][0] = i0; acc[0][p][1] = i1;
            acc[1][p][0] = i0; acc[1][p][1] = i1;
        }
        const float* x0 = Xs + (tm*2+0)*HLD;
        const float* x1 = Xs + (tm*2+1)*HLD;
        const float* wp = Win + tn*4;
        for (int k = 0; k < 128; ++k){
            unsigned long long a0 = dup2(x0[k]);
            unsigned long long a1 = dup2(x1[k]);
            #pragma unroll
            for (int p = 0; p < 4; ++p){
                ulonglong2 w = *(const ulonglong2*)(wp + p*128);
                fma2(acc[0][p][0], a0, w.x); fma2(acc[0][p][1], a0, w.y);
                fma2(acc[1][p][0], a1, w.x); fma2(acc[1][p][1], a1, w.y);
            }
            wp += 512;
        }
        #pragma unroll
        for (int i = 0; i < 2; ++i)
            #pragma unroll
            for (int p = 0; p < 4; ++p){
                float2 a = un2(acc[i][p][0]), b = un2(acc[i][p][1]);
                float* row = Hs + (tm*2+i)*HLD2 + p*128 + tn*4;
                row[0] = gelu_f(a.x); row[1] = gelu_f(a.y);
                row[2] = gelu_f(b.x); row[3] = gelu_f(b.y);
            }
    }
    __syncthreads();

    // out = H @ Wout + bout; residual into Xs
    {
        unsigned long long acc[2][2];
        int c0 = tn*4;
        acc[0][0] = pk2(bout[c0],   bout[c0+1]);
        acc[0][1] = pk2(bout[c0+2], bout[c0+3]);
        acc[1][0] = acc[0][0]; acc[1][1] = acc[0][1];
        const float* h0 = Hs + (tm*2+0)*HLD2;
        const float* h1 = Hs + (tm*2+1)*HLD2;
        const float* wp = Wout + c0;
        #pragma unroll 4
        for (int k = 0; k < 512; ++k){
            unsigned long long a0 = dup2(h0[k]);
            unsigned long long a1 = dup2(h1[k]);
            ulonglong2 w = *(const ulonglong2*)(wp);
            wp += 128;
            fma2(acc[0][0], a0, w.x); fma2(acc[0][1], a0, w.y);
            fma2(acc[1][0], a1, w.x); fma2(acc[1][1], a1, w.y);
        }
        #pragma unroll
        for (int i = 0; i < 2; ++i){
            int r = tm*2 + i;
            float2 a = un2(acc[i][0]), b = un2(acc[i][1]);
            float* xr = Xs + r*HLD + c0;
            xr[0] += a.x; xr[1] += a.y; xr[2] += b.x; xr[3] += b.y;
        }
    }
    __syncthreads();

    // per-row LN + mask -> d_out hV section AND g_hV2
    {
        const int wid = t >> 5, lane = t & 31;
        for (int r = wid; r < FTILE; r += 8){
            int node = base + r;
            float x0 = Xs[r*HLD + lane],    x1 = Xs[r*HLD + lane+32];
            float x2 = Xs[r*HLD + lane+64], x3 = Xs[r*HLD + lane+96];
            float s = warp_sum(x0+x1+x2+x3);
            float q = warp_sum(x0*x0 + x1*x1 + x2*x2 + x3*x3);
            float mean = s * 0.0078125f;
            float var  = q * 0.0078125f - mean*mean;
            float rs = rsqrtf(var + EPSf);
            float mv = maskV[node];
            float y0 = mv*(gam[lane]   *(x0-mean)*rs + bet[lane]);
            float y1 = mv*(gam[lane+32]*(x1-mean)*rs + bet[lane+32]);
            float y2 = mv*(gam[lane+64]*(x2-mean)*rs + bet[lane+64]);
            float y3 = mv*(gam[lane+96]*(x3-mean)*rs + bet[lane+96]);
            float* o = outV + (size_t)node*128;
            o[lane] = y0; o[lane+32] = y1; o[lane+64] = y2; o[lane+96] = y3;
            float* g = g_hV2 + (size_t)node*128;
            g[lane] = y0; g[lane+32] = y1; g[lane+64] = y2; g[lane+96] = y3;
        }
    }
}

// ---------------------------------------------------------------------------
extern "C" void kernel_launch(void* const* d_in, const int* in_sizes, int n_in,
                              void* d_out, int out_size)
{
    const float* hV    = (const float*)d_in[0];
    const float* hE    = (const float*)d_in[1];
    const int*   Eidx  = (const int*)  d_in[2];
    const float* maskV = (const float*)d_in[3];
    const float* maskA = (const float*)d_in[4];
    const float* W1w   = (const float*)d_in[5];  const float* W1b  = (const float*)d_in[6];
    const float* W2w   = (const float*)d_in[7];  const float* W2b  = (const float*)d_in[8];
    const float* W3w   = (const float*)d_in[9];  const float* W3b  = (const float*)d_in[10];
    const float* W11w  = (const float*)d_in[11]; const float* W11b = (const float*)d_in[12];
    const float* W12w  = (const float*)d_in[13]; const float* W12b = (const float*)d_in[14];
    const float* W13w  = (const float*)d_in[15]; const float* W13b = (const float*)d_in[16];
    const float* Winw  = (const float*)d_in[17]; const float* Winb = (const float*)d_in[18];
    const float* Woutw = (const float*)d_in[19]; const float* Woutb= (const float*)d_in[20];
    const float* g1    = (const float*)d_in[21]; const float* b1   = (const float*)d_in[22];
    const float* g2    = (const float*)d_in[23]; const float* b2   = (const float*)d_in[24];
    const float* g3    = (const float*)d_in[25]; const float* b3   = (const float*)d_in[26];

    float* out  = (float*)d_out;
    float* outV = out;
    float* outE = out + (size_t)NODES*Cc;

    const int smem_e = SMEM_E_FLOATS * 4;
    const int smem_f = SMEM_F_FLOATS * 4;
    cudaFuncSetAttribute(edge_mlp_kernel<0>, cudaFuncAttributeMaxDynamicSharedMemorySize, smem_e);
    cudaFuncSetAttribute(edge_mlp_kernel<1>, cudaFuncAttributeMaxDynamicSharedMemorySize, smem_e);
    cudaFuncSetAttribute(ffn_kernel,         cudaFuncAttributeMaxDynamicSharedMemorySize, smem_f);

    // 1) edge MLP on nodes -> masked sum -> /30 -> +h_V -> LN1 -> g_hV1
    edge_mlp_kernel<0><<<NODES, 256, smem_e>>>(
        hV, hE, Eidx, maskA,
        W1w, W1b, W2w, W2b, W3w, W3b,
        hV, g1, b1, nullptr);

    // 2) FFN + LN2 + mask_V -> outV and g_hV2
    ffn_kernel<<<NODES/FTILE, 256, smem_f>>>(
        Winw, Winb, Woutw, Woutb, g2, b2, maskV, outV);

    // 3) edge MLP on updated nodes -> +h_E -> LN3 -> outE
    edge_mlp_kernel<1><<<NODES, 256, smem_e>>>(
        hV, hE, Eidx, maskA,
        W11w, W11b, W12w, W12b, W13w, W13b,
        hE, g3, b3, outE);
}

// round 3
// speedup vs baseline: 1.9277x; 1.9277x over previous
#include <cuda_runtime.h>
#include <math.h>

#define Bb 2
#define Nn 2048
#define Kk 48
#define Cc 128
#define NODES (Bb*Nn)          /* 4096 */
#define EDGES (NODES*Kk)       /* 196608 */
#define EPSf 1e-5f
#define INV_SCALE (1.0f/30.0f)

// device scratch (no allocations allowed)
__device__ float g_hV1[NODES*Cc];
__device__ float g_hV2[NODES*Cc];
__device__ float g_P[NODES*Cc];   // neighbor-block precompute
__device__ float g_Q[NODES*Cc];   // center-block precompute (+bias)

// ---------------- packed fp32 helpers (fma.rn.f32x2) ------------------------
static __device__ __forceinline__ unsigned long long dup2(float x){
    unsigned long long r;
    asm("mov.b64 %0, {%1, %1};" : "=l"(r) : "f"(x));
    return r;
}
static __device__ __forceinline__ unsigned long long pk2(float a, float b){
    unsigned long long r;
    asm("mov.b64 %0, {%1, %2};" : "=l"(r) : "f"(a), "f"(b));
    return r;
}
static __device__ __forceinline__ void fma2(unsigned long long &d,
                                            unsigned long long a,
                                            unsigned long long b){
    asm("fma.rn.f32x2 %0, %1, %2, %0;" : "+l"(d) : "l"(a), "l"(b));
}
static __device__ __forceinline__ float2 un2(unsigned long long v){
    float lo, hi;
    asm("mov.b64 {%0, %1}, %2;" : "=f"(lo), "=f"(hi) : "l"(v));
    return make_float2(lo, hi);
}
static __device__ __forceinline__ float gelu_f(float x){
    return 0.5f * x * (1.0f + erff(x * 0.70710678118654752440f));
}
static __device__ __forceinline__ float warp_sum(float v){
    #pragma unroll
    for (int o = 16; o; o >>= 1) v += __shfl_xor_sync(0xffffffffu, v, o);
    return v;
}

// ======================= precompute P,Q per node ============================
// gQ = x @ W[0:128]  + bias ;  gP = x @ W[256:384]
// grid = NODES/32, 256 threads, each thread: 4 rows x 4 cols, both outputs.
#define PQ_SMEM_FLOATS (32*128 + 2*128*128)
__global__ void __launch_bounds__(256) pq_kernel(
    const float* __restrict__ nodes,
    const float* __restrict__ Wa, const float* __restrict__ ba)
{
    extern __shared__ float sm[];
    float* Xs = sm;                 // [32][128]
    float* Wq = sm + 32*128;        // [128][128]
    float* Wp = Wq + 128*128;       // [128][128]

    const int t  = threadIdx.x;
    const int n0 = blockIdx.x * 32;
    const int tn = t & 31, tm = t >> 5;
    const int c0 = tn * 4;

    // fill X and stage both weight blocks
    {
        const float4* src = (const float4*)(nodes + (size_t)n0*128);
        float4* dst = (float4*)Xs;
        for (int i = t; i < 32*32; i += 256) dst[i] = src[i];
        const float4* wq = (const float4*)(Wa);
        const float4* wp = (const float4*)(Wa + 256*128);
        float4* dq = (float4*)Wq; float4* dp = (float4*)Wp;
        for (int i = t; i < 4096; i += 256){ dq[i] = wq[i]; dp[i] = wp[i]; }
    }
    __syncthreads();

    unsigned long long qa[4][2], pa[4][2];
    {
        unsigned long long b0 = pk2(ba[c0], ba[c0+1]);
        unsigned long long b1 = pk2(ba[c0+2], ba[c0+3]);
        #pragma unroll
        for (int i = 0; i < 4; ++i){
            qa[i][0] = b0; qa[i][1] = b1;
            pa[i][0] = 0ull; pa[i][1] = 0ull;
        }
    }
    const float* x0 = Xs + (tm*4+0)*128;
    const float* x1 = Xs + (tm*4+1)*128;
    const float* x2 = Xs + (tm*4+2)*128;
    const float* x3 = Xs + (tm*4+3)*128;
    const float* wqp = Wq + c0;
    const float* wpp = Wp + c0;
    #pragma unroll 2
    for (int k = 0; k < 128; k += 2){
        float2 v0 = *(const float2*)(x0 + k);
        float2 v1 = *(const float2*)(x1 + k);
        float2 v2 = *(const float2*)(x2 + k);
        float2 v3 = *(const float2*)(x3 + k);
        ulonglong2 q0 = *(const ulonglong2*)(wqp);
        ulonglong2 q1 = *(const ulonglong2*)(wqp + 128);
        ulonglong2 p0 = *(const ulonglong2*)(wpp);
        ulonglong2 p1 = *(const ulonglong2*)(wpp + 128);
        wqp += 256; wpp += 256;
        unsigned long long a;
        a = dup2(v0.x); fma2(qa[0][0],a,q0.x); fma2(qa[0][1],a,q0.y); fma2(pa[0][0],a,p0.x); fma2(pa[0][1],a,p0.y);
        a = dup2(v0.y); fma2(qa[0][0],a,q1.x); fma2(qa[0][1],a,q1.y); fma2(pa[0][0],a,p1.x); fma2(pa[0][1],a,p1.y);
        a = dup2(v1.x); fma2(qa[1][0],a,q0.x); fma2(qa[1][1],a,q0.y); fma2(pa[1][0],a,p0.x); fma2(pa[1][1],a,p0.y);
        a = dup2(v1.y); fma2(qa[1][0],a,q1.x); fma2(qa[1][1],a,q1.y); fma2(pa[1][0],a,p1.x); fma2(pa[1][1],a,p1.y);
        a = dup2(v2.x); fma2(qa[2][0],a,q0.x); fma2(qa[2][1],a,q0.y); fma2(pa[2][0],a,p0.x); fma2(pa[2][1],a,p0.y);
        a = dup2(v2.y); fma2(qa[2][0],a,q1.x); fma2(qa[2][1],a,q1.y); fma2(pa[2][0],a,p1.x); fma2(pa[2][1],a,p1.y);
        a = dup2(v3.x); fma2(qa[3][0],a,q0.x); fma2(qa[3][1],a,q0.y); fma2(pa[3][0],a,p0.x); fma2(pa[3][1],a,p0.y);
        a = dup2(v3.y); fma2(qa[3][0],a,q1.x); fma2(qa[3][1],a,q1.y); fma2(pa[3][0],a,p1.x); fma2(pa[3][1],a,p1.y);
    }
    #pragma unroll
    for (int i = 0; i < 4; ++i){
        int row = n0 + tm*4 + i;
        float2 a = un2(qa[i][0]), b = un2(qa[i][1]);
        float4 q4 = make_float4(a.x, a.y, b.x, b.y);
        *(float4*)(g_Q + (size_t)row*128 + c0) = q4;
        a = un2(pa[i][0]); b = un2(pa[i][1]);
        float4 p4 = make_float4(a.x, a.y, b.x, b.y);
        *(float4*)(g_P + (size_t)row*128 + c0) = p4;
    }
}

// ======================= edge pass: 96 rows (2 nodes) per CTA ===============
// smem: X[96*128] | H[96*128] | Ws[128*128]
#define EP_SMEM_FLOATS (96*128*2 + 128*128)

static __device__ __forceinline__ void gemm96(
    const float* __restrict__ Xs, const float* __restrict__ Ws,
    int r0, int c0, unsigned long long acc[6][2])
{
    const float* xb = Xs + r0*128;
    const float* wp = Ws + c0;
    #pragma unroll 2
    for (int k = 0; k < 128; k += 4){
        float4 v0 = *(const float4*)(xb + 0*128 + k);
        float4 v1 = *(const float4*)(xb + 1*128 + k);
        float4 v2 = *(const float4*)(xb + 2*128 + k);
        float4 v3 = *(const float4*)(xb + 3*128 + k);
        float4 v4 = *(const float4*)(xb + 4*128 + k);
        float4 v5 = *(const float4*)(xb + 5*128 + k);
        ulonglong2 w0 = *(const ulonglong2*)(wp);
        ulonglong2 w1 = *(const ulonglong2*)(wp + 128);
        ulonglong2 w2 = *(const ulonglong2*)(wp + 256);
        ulonglong2 w3 = *(const ulonglong2*)(wp + 384);
        wp += 512;
        unsigned long long a;
        a=dup2(v0.x); fma2(acc[0][0],a,w0.x); fma2(acc[0][1],a,w0.y);
        a=dup2(v0.y); fma2(acc[0][0],a,w1.x); fma2(acc[0][1],a,w1.y);
        a=dup2(v0.z); fma2(acc[0][0],a,w2.x); fma2(acc[0][1],a,w2.y);
        a=dup2(v0.w); fma2(acc[0][0],a,w3.x); fma2(acc[0][1],a,w3.y);
        a=dup2(v1.x); fma2(acc[1][0],a,w0.x); fma2(acc[1][1],a,w0.y);
        a=dup2(v1.y); fma2(acc[1][0],a,w1.x); fma2(acc[1][1],a,w1.y);
        a=dup2(v1.z); fma2(acc[1][0],a,w2.x); fma2(acc[1][1],a,w2.y);
        a=dup2(v1.w); fma2(acc[1][0],a,w3.x); fma2(acc[1][1],a,w3.y);
        a=dup2(v2.x); fma2(acc[2][0],a,w0.x); fma2(acc[2][1],a,w0.y);
        a=dup2(v2.y); fma2(acc[2][0],a,w1.x); fma2(acc[2][1],a,w1.y);
        a=dup2(v2.z); fma2(acc[2][0],a,w2.x); fma2(acc[2][1],a,w2.y);
        a=dup2(v2.w); fma2(acc[2][0],a,w3.x); fma2(acc[2][1],a,w3.y);
        a=dup2(v3.x); fma2(acc[3][0],a,w0.x); fma2(acc[3][1],a,w0.y);
        a=dup2(v3.y); fma2(acc[3][0],a,w1.x); fma2(acc[3][1],a,w1.y);
        a=dup2(v3.z); fma2(acc[3][0],a,w2.x); fma2(acc[3][1],a,w2.y);
        a=dup2(v3.w); fma2(acc[3][0],a,w3.x); fma2(acc[3][1],a,w3.y);
        a=dup2(v4.x); fma2(acc[4][0],a,w0.x); fma2(acc[4][1],a,w0.y);
        a=dup2(v4.y); fma2(acc[4][0],a,w1.x); fma2(acc[4][1],a,w1.y);
        a=dup2(v4.z); fma2(acc[4][0],a,w2.x); fma2(acc[4][1],a,w2.y);
        a=dup2(v4.w); fma2(acc[4][0],a,w3.x); fma2(acc[4][1],a,w3.y);
        a=dup2(v5.x); fma2(acc[5][0],a,w0.x); fma2(acc[5][1],a,w0.y);
        a=dup2(v5.y); fma2(acc[5][0],a,w1.x); fma2(acc[5][1],a,w1.y);
        a=dup2(v5.z); fma2(acc[5][0],a,w2.x); fma2(acc[5][1],a,w2.y);
        a=dup2(v5.w); fma2(acc[5][0],a,w3.x); fma2(acc[5][1],a,w3.y);
    }
}

static __device__ __forceinline__ void stageW(float* Ws, const float* __restrict__ W, int t){
    const float4* s = (const float4*)W;
    float4* d = (float4*)Ws;
    #pragma unroll
    for (int i = 0; i < 8; ++i) d[t + i*512] = s[t + i*512];
}

template<int MODE>
__global__ void __launch_bounds__(512) edge_pass(
    const float* __restrict__ hE,
    const int*   __restrict__ Eidx,
    const float* __restrict__ maskA,
    const float* __restrict__ W1mid,
    const float* __restrict__ Wb, const float* __restrict__ bb,
    const float* __restrict__ Wc, const float* __restrict__ bc,
    const float* __restrict__ residV,            // MODE0: hV
    const float* __restrict__ gam, const float* __restrict__ bet,
    float* __restrict__ outp)                    // MODE0: g_hV1 ; MODE1: outE
{
    extern __shared__ float sm[];
    float* Xs = sm;                  // [96][128]
    float* Hs = sm + 96*128;         // [96][128]
    float* Ws = Hs + 96*128;         // [128][128]
    __shared__ int   sidx[96];
    __shared__ float s_s[2][4], s_q[2][4];

    const int t   = threadIdx.x;
    const int blk = blockIdx.x;
    const int node0 = blk * 2;
    const int base  = (node0 >> 11) << 11;       // batch offset in nodes
    const int txn = t & 31, txm = t >> 5;
    const int r0 = txm * 6, c0 = txn * 4;

    if (t < 96) sidx[t] = Eidx[(size_t)blk*96 + t];
    __syncthreads();

    // fill X (= h_E tile) and H (= preadd: Q[node] + P[nbr], bias folded in Q)
    {
        const float4* eSrc = (const float4*)(hE + (size_t)blk*96*128);
        float4* xD = (float4*)Xs;
        float4* hD = (float4*)Hs;
        #pragma unroll
        for (int i = 0; i < 6; ++i){
            int idx = t + i*512;                 // over 3072 float4
            int row = idx >> 5, cc = idx & 31;
            xD[idx] = eSrc[idx];
            const float4* qR = (const float4*)(g_Q + (size_t)(node0 + (row >= 48))*128);
            const float4* pR = (const float4*)(g_P + (size_t)(base + sidx[row])*128);
            float4 q = qR[cc], p = pR[cc];
            hD[idx] = make_float4(q.x+p.x, q.y+p.y, q.z+p.z, q.w+p.w);
        }
        stageW(Ws, W1mid, t);
    }
    __syncthreads();

    unsigned long long acc[6][2];

    // --- layer 1: acc = preadd(H) + X @ W1mid ; gelu -> H -------------------
    #pragma unroll
    for (int i = 0; i < 6; ++i){
        const float* h = Hs + (r0+i)*128 + c0;
        acc[i][0] = pk2(h[0], h[1]);
        acc[i][1] = pk2(h[2], h[3]);
    }
    gemm96(Xs, Ws, r0, c0, acc);
    #pragma unroll
    for (int i = 0; i < 6; ++i){
        float2 a = un2(acc[i][0]), b = un2(acc[i][1]);
        float* h = Hs + (r0+i)*128 + c0;
        h[0]=gelu_f(a.x); h[1]=gelu_f(a.y); h[2]=gelu_f(b.x); h[3]=gelu_f(b.y);
    }
    __syncthreads();
    stageW(Ws, Wb, t);
    __syncthreads();

    // --- layer 2: H @ Wb + bb ; gelu -> X -----------------------------------
    {
        unsigned long long b0 = pk2(bb[c0], bb[c0+1]);
        unsigned long long b1 = pk2(bb[c0+2], bb[c0+3]);
        #pragma unroll
        for (int i = 0; i < 6; ++i){ acc[i][0]=b0; acc[i][1]=b1; }
    }
    gemm96(Hs, Ws, r0, c0, acc);
    __syncthreads();                 // Xs reads (none since layer1) - protect writes vs layer1? X unused; but Ws restage below
    #pragma unroll
    for (int i = 0; i < 6; ++i){
        float2 a = un2(acc[i][0]), b = un2(acc[i][1]);
        float* x = Xs + (r0+i)*128 + c0;
        x[0]=gelu_f(a.x); x[1]=gelu_f(a.y); x[2]=gelu_f(b.x); x[3]=gelu_f(b.y);
    }
    __syncthreads();
    stageW(Ws, Wc, t);
    __syncthreads();

    // --- layer 3: X @ Wc + bc -> msg in regs --------------------------------
    {
        unsigned long long b0 = pk2(bc[c0], bc[c0+1]);
        unsigned long long b1 = pk2(bc[c0+2], bc[c0+3]);
        #pragma unroll
        for (int i = 0; i < 6; ++i){ acc[i][0]=b0; acc[i][1]=b1; }
    }
    gemm96(Xs, Ws, r0, c0, acc);

    if (MODE == 0){
        // masked per-node sum over K=48 rows, /30, +resid, LN -> g_hV1
        float p0=0.f, p1=0.f, p2=0.f, p3=0.f;
        #pragma unroll
        for (int i = 0; i < 6; ++i){
            int row = r0 + i;
            float m = maskA[(size_t)blk*96 + row];
            float2 a = un2(acc[i][0]), b = un2(acc[i][1]);
            p0 = fmaf(m, a.x, p0); p1 = fmaf(m, a.y, p1);
            p2 = fmaf(m, b.x, p2); p3 = fmaf(m, b.y, p3);
        }
        __syncthreads();             // all GEMM3 X reads done before reuse
        float* red = Xs;             // [16][132]
        red[txm*132 + c0 + 0] = p0;
        red[txm*132 + c0 + 1] = p1;
        red[txm*132 + c0 + 2] = p2;
        red[txm*132 + c0 + 3] = p3;
        __syncthreads();
        float xv = 0.f;
        if (t < 256){
            int nl = t >> 7, c = t & 127;
            float s = 0.f;
            #pragma unroll
            for (int m = 0; m < 8; ++m) s += red[(nl*8 + m)*132 + c];
            xv = residV[(size_t)(node0 + nl)*128 + c] + s * INV_SCALE;
            float ws = warp_sum(xv);
            float wq = warp_sum(xv*xv);
            int wl = (t >> 5) & 3;
            if ((t & 31) == 0){ s_s[nl][wl] = ws; s_q[nl][wl] = wq; }
        }
        __syncthreads();
        if (t < 256){
            int nl = t >> 7, c = t & 127;
            float mean = (s_s[nl][0]+s_s[nl][1]+s_s[nl][2]+s_s[nl][3]) * 0.0078125f;
            float var  = (s_q[nl][0]+s_q[nl][1]+s_q[nl][2]+s_q[nl][3]) * 0.0078125f - mean*mean;
            float y = gam[c] * (xv - mean) * rsqrtf(var + EPSf) + bet[c];
            outp[(size_t)(node0 + nl)*128 + c] = y;
        }
    } else {
        // per-edge LN(h_E + msg) -> outE. warp = txm owns 6 full rows.
        const float4 gm = *(const float4*)(gam + c0);
        const float4 bt = *(const float4*)(bet + c0);
        #pragma unroll
        for (int i = 0; i < 6; ++i){
            int row = r0 + i;
            float4 e = *(const float4*)(hE + ((size_t)blk*96 + row)*128 + c0);
            float2 a = un2(acc[i][0]), b = un2(acc[i][1]);
            float x0 = e.x + a.x, x1 = e.y + a.y, x2 = e.z + b.x, x3 = e.w + b.y;
            float s = warp_sum(x0+x1+x2+x3);
            float q = warp_sum(x0*x0 + x1*x1 + x2*x2 + x3*x3);
            float mean = s * 0.0078125f;
            float var  = q * 0.0078125f - mean*mean;
            float rs = rsqrtf(var + EPSf);
            float4 o;
            o.x = gm.x*(x0-mean)*rs + bt.x;
            o.y = gm.y*(x1-mean)*rs + bt.y;
            o.z = gm.z*(x2-mean)*rs + bt.z;
            o.w = gm.w*(x3-mean)*rs + bt.w;
            *(float4*)(outp + ((size_t)blk*96 + row)*128 + c0) = o;
        }
    }
}

// ---------------- FFN + LN2 + mask kernel (16 nodes per CTA) ----------------
#define HLD 132
#define FTILE 16
#define HLD2 516
#define SMEM_F_FLOATS (FTILE*HLD + FTILE*HLD2)

__global__ void __launch_bounds__(256) ffn_kernel(
    const float* __restrict__ Win, const float* __restrict__ bin,
    const float* __restrict__ Wout, const float* __restrict__ bout,
    const float* __restrict__ gam, const float* __restrict__ bet,
    const float* __restrict__ maskV,
    float* __restrict__ outV)
{
    extern __shared__ float sm[];
    float* Xs = sm;                  // [16][132]
    float* Hs = sm + FTILE*HLD;      // [16][516]
    const int t = threadIdx.x;
    const int base = blockIdx.x * FTILE;
    const int tn = t & 31, tm = t >> 5;

    for (int idx = t; idx < FTILE*128; idx += 256){
        int r = idx >> 7, c = idx & 127;
        Xs[r*HLD + c] = g_hV1[(size_t)(base + r)*128 + c];
    }
    __syncthreads();

    {
        unsigned long long acc[2][4][2];
        #pragma unroll
        for (int p = 0; p < 4; ++p){
            int c0 = p*128 + tn*4;
            unsigned long long i0 = pk2(bin[c0],   bin[c0+1]);
            unsigned long long i1 = pk2(bin[c0+2], bin[c0+3]);
            acc[0][p][0] = i0; acc[0][p][1] = i1;
            acc[1][p][0] = i0; acc[1][p][1] = i1;
        }
        const float* x0 = Xs + (tm*2+0)*HLD;
        const float* x1 = Xs + (tm*2+1)*HLD;
        const float* wp = Win + tn*4;
        for (int k = 0; k < 128; ++k){
            unsigned long long a0 = dup2(x0[k]);
            unsigned long long a1 = dup2(x1[k]);
            #pragma unroll
            for (int p = 0; p < 4; ++p){
                ulonglong2 w = *(const ulonglong2*)(wp + p*128);
                fma2(acc[0][p][0], a0, w.x); fma2(acc[0][p][1], a0, w.y);
                fma2(acc[1][p][0], a1, w.x); fma2(acc[1][p][1], a1, w.y);
            }
            wp += 512;
        }
        #pragma unroll
        for (int i = 0; i < 2; ++i)
            #pragma unroll
            for (int p = 0; p < 4; ++p){
                float2 a = un2(acc[i][p][0]), b = un2(acc[i][p][1]);
                float* row = Hs + (tm*2+i)*HLD2 + p*128 + tn*4;
                row[0] = gelu_f(a.x); row[1] = gelu_f(a.y);
                row[2] = gelu_f(b.x); row[3] = gelu_f(b.y);
            }
    }
    __syncthreads();

    {
        unsigned long long acc[2][2];
        int c0 = tn*4;
        acc[0][0] = pk2(bout[c0],   bout[c0+1]);
        acc[0][1] = pk2(bout[c0+2], bout[c0+3]);
        acc[1][0] = acc[0][0]; acc[1][1] = acc[0][1];
        const float* h0 = Hs + (tm*2+0)*HLD2;
        const float* h1 = Hs + (tm*2+1)*HLD2;
        const float* wp = Wout + c0;
        #pragma unroll 4
        for (int k = 0; k < 512; ++k){
            unsigned long long a0 = dup2(h0[k]);
            unsigned long long a1 = dup2(h1[k]);
            ulonglong2 w = *(const ulonglong2*)(wp);
            wp += 128;
            fma2(acc[0][0], a0, w.x); fma2(acc[0][1], a0, w.y);
            fma2(acc[1][0], a1, w.x); fma2(acc[1][1], a1, w.y);
        }
        #pragma unroll
        for (int i = 0; i < 2; ++i){
            int r = tm*2 + i;
            float2 a = un2(acc[i][0]), b = un2(acc[i][1]);
            float* xr = Xs + r*HLD + c0;
            xr[0] += a.x; xr[1] += a.y; xr[2] += b.x; xr[3] += b.y;
        }
    }
    __syncthreads();

    {
        const int wid = t >> 5, lane = t & 31;
        for (int r = wid; r < FTILE; r += 8){
            int node = base + r;
            float x0 = Xs[r*HLD + lane],    x1 = Xs[r*HLD + lane+32];
            float x2 = Xs[r*HLD + lane+64], x3 = Xs[r*HLD + lane+96];
            float s = warp_sum(x0+x1+x2+x3);
            float q = warp_sum(x0*x0 + x1*x1 + x2*x2 + x3*x3);
            float mean = s * 0.0078125f;
            float var  = q * 0.0078125f - mean*mean;
            float rs = rsqrtf(var + EPSf);
            float mv = maskV[node];
            float y0 = mv*(gam[lane]   *(x0-mean)*rs + bet[lane]);
            float y1 = mv*(gam[lane+32]*(x1-mean)*rs + bet[lane+32]);
            float y2 = mv*(gam[lane+64]*(x2-mean)*rs + bet[lane+64]);
            float y3 = mv*(gam[lane+96]*(x3-mean)*rs + bet[lane+96]);
            float* o = outV + (size_t)node*128;
            o[lane] = y0; o[lane+32] = y1; o[lane+64] = y2; o[lane+96] = y3;
            float* g = g_hV2 + (size_t)node*128;
            g[lane] = y0; g[lane+32] = y1; g[lane+64] = y2; g[lane+96] = y3;
        }
    }
}

// ---------------------------------------------------------------------------
extern "C" void kernel_launch(void* const* d_in, const int* in_sizes, int n_in,
                              void* d_out, int out_size)
{
    const float* hV    = (const float*)d_in[0];
    const float* hE    = (const float*)d_in[1];
    const int*   Eidx  = (const int*)  d_in[2];
    const float* maskV = (const float*)d_in[3];
    const float* maskA = (const float*)d_in[4];
    const float* W1w   = (const float*)d_in[5];  const float* W1b  = (const float*)d_in[6];
    const float* W2w   = (const float*)d_in[7];  const float* W2b  = (const float*)d_in[8];
    const float* W3w   = (const float*)d_in[9];  const float* W3b  = (const float*)d_in[10];
    const float* W11w  = (const float*)d_in[11]; const float* W11b = (const float*)d_in[12];
    const float* W12w  = (const float*)d_in[13]; const float* W12b = (const float*)d_in[14];
    const float* W13w  = (const float*)d_in[15]; const float* W13b = (const float*)d_in[16];
    const float* Winw  = (const float*)d_in[17]; const float* Winb = (const float*)d_in[18];
    const float* Woutw = (const float*)d_in[19]; const float* Woutb= (const float*)d_in[20];
    const float* g1    = (const float*)d_in[21]; const float* b1   = (const float*)d_in[22];
    const float* g2    = (const float*)d_in[23]; const float* b2   = (const float*)d_in[24];
    const float* g3    = (const float*)d_in[25]; const float* b3   = (const float*)d_in[26];

    float* out  = (float*)d_out;
    float* outV = out;
    float* outE = out + (size_t)NODES*Cc;

    float* hV1p; cudaGetSymbolAddress((void**)&hV1p, g_hV1);

    const int smem_pq = PQ_SMEM_FLOATS * 4;
    const int smem_ep = EP_SMEM_FLOATS * 4;
    const int smem_f  = SMEM_F_FLOATS * 4;
    cudaFuncSetAttribute(pq_kernel,   cudaFuncAttributeMaxDynamicSharedMemorySize, smem_pq);
    cudaFuncSetAttribute(edge_pass<0>,cudaFuncAttributeMaxDynamicSharedMemorySize, smem_ep);
    cudaFuncSetAttribute(edge_pass<1>,cudaFuncAttributeMaxDynamicSharedMemorySize, smem_ep);
    cudaFuncSetAttribute(ffn_kernel,  cudaFuncAttributeMaxDynamicSharedMemorySize, smem_f);

    // pass 1: node message
    pq_kernel<<<NODES/32, 256, smem_pq>>>(hV, W1w, W1b);
    edge_pass<0><<<NODES/2, 512, smem_ep>>>(
        hE, Eidx, maskA, W1w + 128*128, W2w, W2b, W3w, W3b,
        hV, g1, b1, hV1p);

    // FFN + LN2 + mask
    ffn_kernel<<<NODES/FTILE, 256, smem_f>>>(
        Winw, Winb, Woutw, Woutb, g2, b2, maskV, outV);

    // pass 2: edge update (uses g_hV2 written by ffn_kernel)
    float* hV2p; cudaGetSymbolAddress((void**)&hV2p, g_hV2);
    pq_kernel<<<NODES/32, 256, smem_pq>>>(hV2p, W11w, W11b);
    edge_pass<1><<<NODES/2, 512, smem_ep>>>(
        hE, Eidx, maskA, W11w + 128*128, W12w, W12b, W13w, W13b,
        hV2p, g3, b3, outE);
}

// round 5
// speedup vs baseline: 2.3642x; 1.2264x over previous
#include <cuda_runtime.h>
#include <cuda_bf16.h>
#include <math.h>
#include <stdint.h>

#define Bb 2
#define Nn 2048
#define Kk 48
#define Cc 128
#define NODES (Bb*Nn)          /* 4096 */
#define EPSf 1e-5f
#define INV_SCALE (1.0f/30.0f)

// device scratch (no allocations allowed)
__device__ float g_hV1[NODES*Cc];
__device__ float g_hV2[NODES*Cc];
__device__ float g_P[NODES*Cc];                 // neighbor-block precompute
__device__ float g_Q[NODES*Cc];                 // center-block precompute (+bias)
__device__ __nv_bfloat16 g_Wimg[6*32768];       // 6 matrices x (hi 16384 + lo 16384)

// ---------------- packed fp32 helpers (fma.rn.f32x2) ------------------------
static __device__ __forceinline__ unsigned long long dup2(float x){
    unsigned long long r; asm("mov.b64 %0, {%1, %1};" : "=l"(r) : "f"(x)); return r;
}
static __device__ __forceinline__ unsigned long long pk2(float a, float b){
    unsigned long long r; asm("mov.b64 %0, {%1, %2};" : "=l"(r) : "f"(a), "f"(b)); return r;
}
static __device__ __forceinline__ void fma2(unsigned long long &d, unsigned long long a, unsigned long long b){
    asm("fma.rn.f32x2 %0, %1, %2, %0;" : "+l"(d) : "l"(a), "l"(b));
}
static __device__ __forceinline__ float2 un2(unsigned long long v){
    float lo, hi; asm("mov.b64 {%0, %1}, %2;" : "=f"(lo), "=f"(hi) : "l"(v));
    return make_float2(lo, hi);
}
static __device__ __forceinline__ float gelu_f(float x){
    return 0.5f * x * (1.0f + erff(x * 0.70710678118654752440f));
}
static __device__ __forceinline__ float warp_sum(float v){
    #pragma unroll
    for (int o = 16; o; o >>= 1) v += __shfl_xor_sync(0xffffffffu, v, o);
    return v;
}
static __device__ __forceinline__ uint32_t smem_u32(const void* p){
    uint32_t a;
    asm("{ .reg .u64 t; cvta.to.shared.u64 t, %1; cvt.u32.u64 %0, t; }" : "=r"(a) : "l"(p));
    return a;
}

// ---------------- mma.sync / ldmatrix helpers -------------------------------
static __device__ __forceinline__ void ldsm4(uint32_t* r, uint32_t addr){
    asm volatile("ldmatrix.sync.aligned.m8n8.x4.shared.b16 {%0,%1,%2,%3}, [%4];"
        : "=r"(r[0]), "=r"(r[1]), "=r"(r[2]), "=r"(r[3]) : "r"(addr));
}
static __device__ __forceinline__ void mma16816(float* c, const uint32_t* a, uint32_t b0, uint32_t b1){
    asm volatile("mma.sync.aligned.m16n8k16.row.col.f32.bf16.bf16.f32 "
        "{%0,%1,%2,%3},{%4,%5,%6,%7},{%8,%9},{%0,%1,%2,%3};"
        : "+f"(c[0]), "+f"(c[1]), "+f"(c[2]), "+f"(c[3])
        : "r"(a[0]), "r"(a[1]), "r"(a[2]), "r"(a[3]), "r"(b0), "r"(b1));
}
// swizzled byte offset inside a [128 rows x 128 bf16] tile (256B rows, 16B xor)
static __device__ __forceinline__ uint32_t sw_off(int row, int k){
    return (uint32_t)(row*256 + ((((k >> 3) ^ (row & 7))) << 4) + (k & 7)*2);
}
static __device__ __forceinline__ uint32_t pack_bf(float a, float b){
    __nv_bfloat162 h = __floats2bfloat162_rn(a, b);
    return *reinterpret_cast<uint32_t*>(&h);
}
static __device__ __forceinline__ void split_pair(float a, float b, uint32_t &hi, uint32_t &lo){
    __nv_bfloat16 ha = __float2bfloat16(a);
    __nv_bfloat16 hb = __float2bfloat16(b);
    __nv_bfloat162 H; H.x = ha; H.y = hb;
    hi = *reinterpret_cast<uint32_t*>(&H);
    lo = pack_bf(a - __bfloat162float(ha), b - __bfloat162float(hb));
}

// ===================== weight prep: transpose + bf16 split + swizzle ========
// image[n][k] = W[k][n], hi then lo, each 16384 bf16 (32KB).
__global__ void __launch_bounds__(256) prep_w(
    const float* __restrict__ m0, const float* __restrict__ m1,
    const float* __restrict__ m2, const float* __restrict__ m3,
    const float* __restrict__ m4, const float* __restrict__ m5)
{
    extern __shared__ float ws[];   // [128][128]
    const float* W;
    switch (blockIdx.x){
        case 0: W = m0; break; case 1: W = m1; break; case 2: W = m2; break;
        case 3: W = m3; break; case 4: W = m4; break; default: W = m5; break;
    }
    const int t = threadIdx.x;
    for (int i = t; i < 4096; i += 256)
        ((float4*)ws)[i] = ((const float4*)W)[i];
    __syncthreads();

    __nv_bfloat16* hi = g_Wimg + (size_t)blockIdx.x * 32768;
    __nv_bfloat16* lo = hi + 16384;
    for (int c = t; c < 2048; c += 256){
        int row = c >> 4;            // n
        int k0  = (c & 15) << 3;     // k
        union { uint32_t u[4]; uint4 q; } H, L;
        #pragma unroll
        for (int j = 0; j < 4; ++j){
            float w0 = ws[(k0 + 2*j    )*128 + row];
            float w1 = ws[(k0 + 2*j + 1)*128 + row];
            split_pair(w0, w1, H.u[j], L.u[j]);
        }
        uint32_t off = (uint32_t)(row*256 + (((k0 >> 3) ^ (row & 7)) << 4));
        *(uint4*)((char*)hi + off) = H.q;
        *(uint4*)((char*)lo + off) = L.q;
    }
}

// ======================= precompute P,Q per node (fp32 FFMA2) ===============
#define PQ_SMEM_FLOATS (32*128 + 2*128*128)
__global__ void __launch_bounds__(256) pq_kernel(
    const float* __restrict__ nodes,
    const float* __restrict__ Wa, const float* __restrict__ ba)
{
    extern __shared__ float sm[];
    float* Xs = sm;
    float* Wq = sm + 32*128;
    float* Wp = Wq + 128*128;

    const int t  = threadIdx.x;
    const int n0 = blockIdx.x * 32;
    const int tn = t & 31, tm = t >> 5;
    const int c0 = tn * 4;

    {
        const float4* src = (const float4*)(nodes + (size_t)n0*128);
        float4* dst = (float4*)Xs;
        for (int i = t; i < 32*32; i += 256) dst[i] = src[i];
        const float4* wq = (const float4*)(Wa);
        const float4* wp = (const float4*)(Wa + 256*128);
        float4* dq = (float4*)Wq; float4* dp = (float4*)Wp;
        for (int i = t; i < 4096; i += 256){ dq[i] = wq[i]; dp[i] = wp[i]; }
    }
    __syncthreads();

    unsigned long long qa[4][2], pa[4][2];
    {
        unsigned long long b0 = pk2(ba[c0], ba[c0+1]);
        unsigned long long b1 = pk2(ba[c0+2], ba[c0+3]);
        #pragma unroll
        for (int i = 0; i < 4; ++i){
            qa[i][0] = b0; qa[i][1] = b1;
            pa[i][0] = 0ull; pa[i][1] = 0ull;
        }
    }
    const float* x0 = Xs + (tm*4+0)*128;
    const float* x1 = Xs + (tm*4+1)*128;
    const float* x2 = Xs + (tm*4+2)*128;
    const float* x3 = Xs + (tm*4+3)*128;
    const float* wqp = Wq + c0;
    const float* wpp = Wp + c0;
    #pragma unroll 2
    for (int k = 0; k < 128; k += 2){
        float2 v0 = *(const float2*)(x0 + k);
        float2 v1 = *(const float2*)(x1 + k);
        float2 v2 = *(const float2*)(x2 + k);
        float2 v3 = *(const float2*)(x3 + k);
        ulonglong2 q0 = *(const ulonglong2*)(wqp);
        ulonglong2 q1 = *(const ulonglong2*)(wqp + 128);
        ulonglong2 p0 = *(const ulonglong2*)(wpp);
        ulonglong2 p1 = *(const ulonglong2*)(wpp + 128);
        wqp += 256; wpp += 256;
        unsigned long long a;
        a = dup2(v0.x); fma2(qa[0][0],a,q0.x); fma2(qa[0][1],a,q0.y); fma2(pa[0][0],a,p0.x); fma2(pa[0][1],a,p0.y);
        a = dup2(v0.y); fma2(qa[0][0],a,q1.x); fma2(qa[0][1],a,q1.y); fma2(pa[0][0],a,p1.x); fma2(pa[0][1],a,p1.y);
        a = dup2(v1.x); fma2(qa[1][0],a,q0.x); fma2(qa[1][1],a,q0.y); fma2(pa[1][0],a,p0.x); fma2(pa[1][1],a,p0.y);
        a = dup2(v1.y); fma2(qa[1][0],a,q1.x); fma2(qa[1][1],a,q1.y); fma2(pa[1][0],a,p1.x); fma2(pa[1][1],a,p1.y);
        a = dup2(v2.x); fma2(qa[2][0],a,q0.x); fma2(qa[2][1],a,q0.y); fma2(pa[2][0],a,p0.x); fma2(pa[2][1],a,p0.y);
        a = dup2(v2.y); fma2(qa[2][0],a,q1.x); fma2(qa[2][1],a,q1.y); fma2(pa[2][0],a,p1.x); fma2(pa[2][1],a,p1.y);
        a = dup2(v3.x); fma2(qa[3][0],a,q0.x); fma2(qa[3][1],a,q0.y); fma2(pa[3][0],a,p0.x); fma2(pa[3][1],a,p0.y);
        a = dup2(v3.y); fma2(qa[3][0],a,q1.x); fma2(qa[3][1],a,q1.y); fma2(pa[3][0],a,p1.x); fma2(pa[3][1],a,p1.y);
    }
    #pragma unroll
    for (int i = 0; i < 4; ++i){
        int row = n0 + tm*4 + i;
        float2 a = un2(qa[i][0]), b = un2(qa[i][1]);
        *(float4*)(g_Q + (size_t)row*128 + c0) = make_float4(a.x, a.y, b.x, b.y);
        a = un2(pa[i][0]); b = un2(pa[i][1]);
        *(float4*)(g_P + (size_t)row*128 + c0) = make_float4(a.x, a.y, b.x, b.y);
    }
}

// ======================= edge pass: mma.sync, 2 nodes (96 rows, M pad 128) ==
// dyn smem: header 1KB | AH 32KB | AL 32KB | BH 32KB | BL 32KB = 132096 B
#define EDGE_SMEM 132096

template<int MODE>
__global__ void __launch_bounds__(256) edge_mma(
    const float* __restrict__ hE,
    const int*   __restrict__ Eidx,
    const float* __restrict__ maskA,
    const __nv_bfloat16* __restrict__ Wimg,   // 3 layer slots x 32768 bf16
    const float* __restrict__ bb, const float* __restrict__ bc,
    const float* __restrict__ residV,
    const float* __restrict__ gam, const float* __restrict__ bet,
    float* __restrict__ outp)                 // MODE0: g_hV1 ; MODE1: outE
{
    extern __shared__ char smc[];
    const uint32_t SM_AH = 1024u, SM_AL = 33792u, SM_BH = 66560u, SM_BL = 99328u;
    const uint32_t su = smem_u32(smc);
    int*   sidx = (int*)smc;                 // 96 ints
    float* s_s  = (float*)(smc + 384);       // [2][4]
    float* s_q  = (float*)(smc + 448);       // [2][4]

    const int t = threadIdx.x, lane = t & 31, wid = t >> 5;
    const int blk = blockIdx.x, node0 = blk*2;
    const int nbase = (node0 >> 11) << 11;

    if (t < 96) sidx[t] = Eidx[(size_t)blk*96 + t];

    // ---- stage A (h_E split; rows 96..127 zero) + B layer 0 ----------------
    for (int c = t; c < 2048; c += 256){
        int row = c >> 4, k0 = (c & 15) << 3;
        uint32_t off = (uint32_t)(row*256 + (((k0 >> 3) ^ (row & 7)) << 4));
        union { uint32_t u[4]; uint4 q; } H, L;
        if (row < 96){
            const float4* s = (const float4*)(hE + ((size_t)blk*96 + row)*128 + k0);
            float4 v0 = s[0], v1 = s[1];
            split_pair(v0.x, v0.y, H.u[0], L.u[0]);
            split_pair(v0.z, v0.w, H.u[1], L.u[1]);
            split_pair(v1.x, v1.y, H.u[2], L.u[2]);
            split_pair(v1.z, v1.w, H.u[3], L.u[3]);
        } else {
            H.q = make_uint4(0u,0u,0u,0u); L.q = H.q;
        }
        *(uint4*)(smc + SM_AH + off) = H.q;
        *(uint4*)(smc + SM_AL + off) = L.q;
    }
    {
        const uint4* sH = (const uint4*)Wimg;
        const uint4* sL = sH + 2048;
        uint4* dH = (uint4*)(smc + SM_BH);
        uint4* dL = (uint4*)(smc + SM_BL);
        #pragma unroll
        for (int i = 0; i < 8; ++i){ dH[t + i*256] = sH[t + i*256]; dL[t + i*256] = sL[t + i*256]; }
    }
    __syncthreads();

    // lane -> fragment geometry
    const int m0   = wid*16;
    const int qrow = lane >> 2, qcol = (lane & 3)*2;
    const int rowA = m0 + qrow, rowB = rowA + 8;
    const int sel  = lane >> 3, la7 = lane & 7;
    const uint32_t a_rbase = (uint32_t)((m0 + la7 + ((sel & 1) << 3)) * 256);
    const uint32_t a_rx    = (uint32_t)((m0 + la7 + ((sel & 1) << 3)) & 7);
    const int a_k8 = (sel >> 1);
    const int b_nin = la7 + ((sel >> 1) << 3);
    const int b_k8 = (sel & 1);

    float acc[16][4];

    #pragma unroll 1
    for (int l = 0; l < 3; ++l){
        // ---- init accumulators ---------------------------------------------
        if (l == 0){
            if (rowA < 96){
                const float* qA = g_Q + (size_t)(node0 + (rowA >= 48))*128;
                const float* pA = g_P + (size_t)(nbase + sidx[rowA])*128;
                const float* qB = g_Q + (size_t)(node0 + (rowB >= 48))*128;
                const float* pB = g_P + (size_t)(nbase + sidx[rowB])*128;
                #pragma unroll
                for (int i = 0; i < 16; ++i){
                    int n = i*8 + qcol;
                    float2 q0 = *(const float2*)(qA + n), p0 = *(const float2*)(pA + n);
                    float2 q1 = *(const float2*)(qB + n), p1 = *(const float2*)(pB + n);
                    acc[i][0] = q0.x + p0.x; acc[i][1] = q0.y + p0.y;
                    acc[i][2] = q1.x + p1.x; acc[i][3] = q1.y + p1.y;
                }
            } else {
                #pragma unroll
                for (int i = 0; i < 16; ++i){
                    acc[i][0] = acc[i][1] = acc[i][2] = acc[i][3] = 0.f;
                }
            }
        } else {
            const float* bias = (l == 1) ? bb : bc;
            #pragma unroll
            for (int i = 0; i < 16; ++i){
                float2 b2 = *(const float2*)(bias + i*8 + qcol);
                acc[i][0] = b2.x; acc[i][1] = b2.y;
                acc[i][2] = b2.x; acc[i][3] = b2.y;
            }
        }

        // ---- mainloop: K=128 in 8 ksteps, bf16 double-split ----------------
        #pragma unroll 1
        for (int ks = 0; ks < 8; ++ks){
            uint32_t ah[4], al[4];
            uint32_t ak3 = (uint32_t)(ks*2 + a_k8);
            uint32_t aoff = a_rbase + ((ak3 ^ a_rx) << 4);
            ldsm4(ah, su + SM_AH + aoff);
            ldsm4(al, su + SM_AL + aoff);
            uint32_t bk3 = (uint32_t)(ks*2 + b_k8);
            #pragma unroll
            for (int np = 0; np < 8; ++np){
                int brow = np*16 + b_nin;
                uint32_t boff = (uint32_t)(brow*256) + ((bk3 ^ (uint32_t)(brow & 7)) << 4);
                uint32_t bh[4], bl[4];
                ldsm4(bh, su + SM_BH + boff);
                ldsm4(bl, su + SM_BL + boff);
                mma16816(acc[2*np],   ah, bh[0], bh[1]);
                mma16816(acc[2*np+1], ah, bh[2], bh[3]);
                mma16816(acc[2*np],   ah, bl[0], bl[1]);
                mma16816(acc[2*np+1], ah, bl[2], bl[3]);
                mma16816(acc[2*np],   al, bh[0], bh[1]);
                mma16816(acc[2*np+1], al, bh[2], bh[3]);
            }
        }

        if (l < 2){
            __syncthreads();     // all A/B reads done before overwrite
            // gelu + re-split into A tiles
            #pragma unroll
            for (int i = 0; i < 16; ++i){
                int n = i*8 + qcol;
                float g0 = gelu_f(acc[i][0]), g1 = gelu_f(acc[i][1]);
                float g2 = gelu_f(acc[i][2]), g3 = gelu_f(acc[i][3]);
                uint32_t hA, lA, hB, lB;
                split_pair(g0, g1, hA, lA);
                split_pair(g2, g3, hB, lB);
                uint32_t offA = sw_off(rowA, n);
                uint32_t offB = sw_off(rowB, n);
                *(uint32_t*)(smc + SM_AH + offA) = hA;
                *(uint32_t*)(smc + SM_AL + offA) = lA;
                *(uint32_t*)(smc + SM_AH + offB) = hB;
                *(uint32_t*)(smc + SM_AL + offB) = lB;
            }
            // restage B for next layer
            {
                const uint4* sH = (const uint4*)(Wimg + (size_t)(l + 1)*32768);
                const uint4* sL = sH + 2048;
                uint4* dH = (uint4*)(smc + SM_BH);
                uint4* dL = (uint4*)(smc + SM_BL);
                #pragma unroll
                for (int i = 0; i < 8; ++i){ dH[t + i*256] = sH[t + i*256]; dL[t + i*256] = sL[t + i*256]; }
            }
            __syncthreads();
        }
    }

    // ======================= final epilogue ================================
    if (MODE == 0){
        // masked sum over K=48 rows per node, /30, +resid, LN -> outp
        __syncthreads();                       // B region reads done; reuse
        float* part = (float*)(smc + SM_BH);   // [8][132]
        float mA = (rowA < 96) ? maskA[(size_t)blk*96 + rowA] : 0.f;
        float mB = (rowA < 96) ? maskA[(size_t)blk*96 + rowB] : 0.f;
        #pragma unroll
        for (int i = 0; i < 16; ++i){
            float p0 = mA*acc[i][0] + mB*acc[i][2];
            float p1 = mA*acc[i][1] + mB*acc[i][3];
            #pragma unroll
            for (int o = 4; o <= 16; o <<= 1){
                p0 += __shfl_xor_sync(0xffffffffu, p0, o);
                p1 += __shfl_xor_sync(0xffffffffu, p1, o);
            }
            if (lane < 4){
                part[wid*132 + i*8 + qcol]     = p0;
                part[wid*132 + i*8 + qcol + 1] = p1;
            }
        }
        __syncthreads();
        {
            int nl = t >> 7, c = t & 127;
            float s = part[(nl*3+0)*132 + c] + part[(nl*3+1)*132 + c] + part[(nl*3+2)*132 + c];
            float xv = residV[(size_t)(node0 + nl)*128 + c] + s * INV_SCALE;
            float ws = warp_sum(xv), wq = warp_sum(xv*xv);
            if (lane == 0){ s_s[nl*4 + (wid & 3)] = ws; s_q[nl*4 + (wid & 3)] = wq; }
            __syncthreads();
            float mean = (s_s[nl*4] + s_s[nl*4+1] + s_s[nl*4+2] + s_s[nl*4+3]) * 0.0078125f;
            float var  = (s_q[nl*4] + s_q[nl*4+1] + s_q[nl*4+2] + s_q[nl*4+3]) * 0.0078125f - mean*mean;
            outp[(size_t)(node0 + nl)*128 + c] =
                gam[c]*(xv - mean)*rsqrtf(var + EPSf) + bet[c];
        }
    } else {
        // per-edge LN(h_E + msg) -> outp
        float sA = 0.f, qA = 0.f, sB = 0.f, qB = 0.f;
        if (rowA < 96){
            const float* eA = hE + ((size_t)blk*96 + rowA)*128;
            const float* eB = hE + ((size_t)blk*96 + rowB)*128;
            #pragma unroll
            for (int i = 0; i < 16; ++i){
                int n = i*8 + qcol;
                float2 e0 = *(const float2*)(eA + n);
                float2 e1 = *(const float2*)(eB + n);
                float v0 = e0.x + acc[i][0], v1 = e0.y + acc[i][1];
                float v2 = e1.x + acc[i][2], v3 = e1.y + acc[i][3];
                acc[i][0] = v0; acc[i][1] = v1; acc[i][2] = v2; acc[i][3] = v3;
                sA += v0 + v1; qA += v0*v0 + v1*v1;
                sB += v2 + v3; qB += v2*v2 + v3*v3;
            }
        }
        sA += __shfl_xor_sync(0xffffffffu, sA, 1); sA += __shfl_xor_sync(0xffffffffu, sA, 2);
        qA += __shfl_xor_sync(0xffffffffu, qA, 1); qA += __shfl_xor_sync(0xffffffffu, qA, 2);
        sB += __shfl_xor_sync(0xffffffffu, sB, 1); sB += __shfl_xor_sync(0xffffffffu, sB, 2);
        qB += __shfl_xor_sync(0xffffffffu, qB, 1); qB += __shfl_xor_sync(0xffffffffu, qB, 2);
        if (rowA < 96){
            float meanA = sA * 0.0078125f;
            float varA  = qA * 0.0078125f - meanA*meanA;
            float rsA   = rsqrtf(varA + EPSf);
            float meanB = sB * 0.0078125f;
            float varB  = qB * 0.0078125f - meanB*meanB;
            float rsB   = rsqrtf(varB + EPSf);
            float* oA = outp + ((size_t)blk*96 + rowA)*128;
            float* oB = outp + ((size_t)blk*96 + rowB)*128;
            #pragma unroll
            for (int i = 0; i < 16; ++i){
                int n = i*8 + qcol;
                float2 g = *(const float2*)(gam + n);
                float2 b = *(const float2*)(bet + n);
                float2 o0, o1;
                o0.x = g.x*(acc[i][0] - meanA)*rsA + b.x;
                o0.y = g.y*(acc[i][1] - meanA)*rsA + b.y;
                o1.x = g.x*(acc[i][2] - meanB)*rsB + b.x;
                o1.y = g.y*(acc[i][3] - meanB)*rsB + b.y;
                *(float2*)(oA + n) = o0;
                *(float2*)(oB + n) = o1;
            }
        }
    }
}

// ---------------- FFN + LN2 + mask kernel (16 nodes per CTA) ----------------
#define HLD 132
#define FTILE 16
#define HLD2 516
#define SMEM_F_FLOATS (FTILE*HLD + FTILE*HLD2)

__global__ void __launch_bounds__(256) ffn_kernel(
    const float* __restrict__ Win, const float* __restrict__ bin,
    const float* __restrict__ Wout, const float* __restrict__ bout,
    const float* __restrict__ gam, const float* __restrict__ bet,
    const float* __restrict__ maskV,
    float* __restrict__ outV)
{
    extern __shared__ float sm[];
    float* Xs = sm;
    float* Hs = sm + FTILE*HLD;
    const int t = threadIdx.x;
    const int base = blockIdx.x * FTILE;
    const int tn = t & 31, tm = t >> 5;

    for (int idx = t; idx < FTILE*128; idx += 256){
        int r = idx >> 7, c = idx & 127;
        Xs[r*HLD + c] = g_hV1[(size_t)(base + r)*128 + c];
    }
    __syncthreads();

    {
        unsigned long long acc[2][4][2];
        #pragma unroll
        for (int p = 0; p < 4; ++p){
            int c0 = p*128 + tn*4;
            unsigned long long i0 = pk2(bin[c0],   bin[c0+1]);
            unsigned long long i1 = pk2(bin[c0+2], bin[c0+3]);
            acc[0][p][0] = i0; acc[0][p][1] = i1;
            acc[1][p][0] = i0; acc[1][p][1] = i1;
        }
        const float* x0 = Xs + (tm*2+0)*HLD;
        const float* x1 = Xs + (tm*2+1)*HLD;
        const float* wp = Win + tn*4;
        for (int k = 0; k < 128; ++k){
            unsigned long long a0 = dup2(x0[k]);
            unsigned long long a1 = dup2(x1[k]);
            #pragma unroll
            for (int p = 0; p < 4; ++p){
                ulonglong2 w = *(const ulonglong2*)(wp + p*128);
                fma2(acc[0][p][0], a0, w.x); fma2(acc[0][p][1], a0, w.y);
                fma2(acc[1][p][0], a1, w.x); fma2(acc[1][p][1], a1, w.y);
            }
            wp += 512;
        }
        #pragma unroll
        for (int i = 0; i < 2; ++i)
            #pragma unroll
            for (int p = 0; p < 4; ++p){
                float2 a = un2(acc[i][p][0]), b = un2(acc[i][p][1]);
                float* row = Hs + (tm*2+i)*HLD2 + p*128 + tn*4;
                row[0] = gelu_f(a.x); row[1] = gelu_f(a.y);
                row[2] = gelu_f(b.x); row[3] = gelu_f(b.y);
            }
    }
    __syncthreads();

    {
        unsigned long long acc[2][2];
        int c0 = tn*4;
        acc[0][0] = pk2(bout[c0],   bout[c0+1]);
        acc[0][1] = pk2(bout[c0+2], bout[c0+3]);
        acc[1][0] = acc[0][0]; acc[1][1] = acc[0][1];
        const float* h0 = Hs + (tm*2+0)*HLD2;
        const float* h1 = Hs + (tm*2+1)*HLD2;
        const float* wp = Wout + c0;
        #pragma unroll 4
        for (int k = 0; k < 512; ++k){
            unsigned long long a0 = dup2(h0[k]);
            unsigned long long a1 = dup2(h1[k]);
            ulonglong2 w = *(const ulonglong2*)(wp);
            wp += 128;
            fma2(acc[0][0], a0, w.x); fma2(acc[0][1], a0, w.y);
            fma2(acc[1][0], a1, w.x); fma2(acc[1][1], a1, w.y);
        }
        #pragma unroll
        for (int i = 0; i < 2; ++i){
            int r = tm*2 + i;
            float2 a = un2(acc[i][0]), b = un2(acc[i][1]);
            float* xr = Xs + r*HLD + c0;
            xr[0] += a.x; xr[1] += a.y; xr[2] += b.x; xr[3] += b.y;
        }
    }
    __syncthreads();

    {
        const int wid = t >> 5, lane = t & 31;
        for (int r = wid; r < FTILE; r += 8){
            int node = base + r;
            float x0 = Xs[r*HLD + lane],    x1 = Xs[r*HLD + lane+32];
            float x2 = Xs[r*HLD + lane+64], x3 = Xs[r*HLD + lane+96];
            float s = warp_sum(x0+x1+x2+x3);
            float q = warp_sum(x0*x0 + x1*x1 + x2*x2 + x3*x3);
            float mean = s * 0.0078125f;
            float var  = q * 0.0078125f - mean*mean;
            float rs = rsqrtf(var + EPSf);
            float mv = maskV[node];
            float y0 = mv*(gam[lane]   *(x0-mean)*rs + bet[lane]);
            float y1 = mv*(gam[lane+32]*(x1-mean)*rs + bet[lane+32]);
            float y2 = mv*(gam[lane+64]*(x2-mean)*rs + bet[lane+64]);
            float y3 = mv*(gam[lane+96]*(x3-mean)*rs + bet[lane+96]);
            float* o = outV + (size_t)node*128;
            o[lane] = y0; o[lane+32] = y1; o[lane+64] = y2; o[lane+96] = y3;
            float* g = g_hV2 + (size_t)node*128;
            g[lane] = y0; g[lane+32] = y1; g[lane+64] = y2; g[lane+96] = y3;
        }
    }
}

// ---------------------------------------------------------------------------
extern "C" void kernel_launch(void* const* d_in, const int* in_sizes, int n_in,
                              void* d_out, int out_size)
{
    const float* hV    = (const float*)d_in[0];
    const float* hE    = (const float*)d_in[1];
    const int*   Eidx  = (const int*)  d_in[2];
    const float* maskV = (const float*)d_in[3];
    const float* maskA = (const float*)d_in[4];
    const float* W1w   = (const float*)d_in[5];  const float* W1b  = (const float*)d_in[6];
    const float* W2w   = (const float*)d_in[7];  const float* W2b  = (const float*)d_in[8];
    const float* W3w   = (const float*)d_in[9];  const float* W3b  = (const float*)d_in[10];
    const float* W11w  = (const float*)d_in[11]; const float* W11b = (const float*)d_in[12];
    const float* W12w  = (const float*)d_in[13]; const float* W12b = (const float*)d_in[14];
    const float* W13w  = (const float*)d_in[15]; const float* W13b = (const float*)d_in[16];
    const float* Winw  = (const float*)d_in[17]; const float* Winb = (const float*)d_in[18];
    const float* Woutw = (const float*)d_in[19]; const float* Woutb= (const float*)d_in[20];
    const float* g1    = (const float*)d_in[21]; const float* b1   = (const float*)d_in[22];
    const float* g2    = (const float*)d_in[23]; const float* b2   = (const float*)d_in[24];
    const float* g3    = (const float*)d_in[25]; const float* b3   = (const float*)d_in[26];

    float* out  = (float*)d_out;
    float* outV = out;
    float* outE = out + (size_t)NODES*Cc;

    float* hV1p; cudaGetSymbolAddress((void**)&hV1p, g_hV1);
    float* hV2p; cudaGetSymbolAddress((void**)&hV2p, g_hV2);
    __nv_bfloat16* wimg; cudaGetSymbolAddress((void**)&wimg, g_Wimg);

    const int smem_pq = PQ_SMEM_FLOATS * 4;
    const int smem_f  = SMEM_F_FLOATS * 4;
    cudaFuncSetAttribute(prep_w,      cudaFuncAttributeMaxDynamicSharedMemorySize, 65536);
    cudaFuncSetAttribute(pq_kernel,   cudaFuncAttributeMaxDynamicSharedMemorySize, smem_pq);
    cudaFuncSetAttribute(edge_mma<0>, cudaFuncAttributeMaxDynamicSharedMemorySize, EDGE_SMEM);
    cudaFuncSetAttribute(edge_mma<1>, cudaFuncAttributeMaxDynamicSharedMemorySize, EDGE_SMEM);
    cudaFuncSetAttribute(ffn_kernel,  cudaFuncAttributeMaxDynamicSharedMemorySize, smem_f);

    // weight images: slots 0-2 = pass1 (W1mid, W2, W3), 3-5 = pass2
    prep_w<<<6, 256, 65536>>>(W1w + 128*128, W2w, W3w, W11w + 128*128, W12w, W13w);

    // pass 1: node message
    pq_kernel<<<NODES/32, 256, smem_pq>>>(hV, W1w, W1b);
    edge_mma<0><<<NODES/2, 256, EDGE_SMEM>>>(
        hE, Eidx, maskA, wimg, W2b, W3b, hV, g1, b1, hV1p);

    // FFN + LN2 + mask
    ffn_kernel<<<NODES/FTILE, 256, smem_f>>>(
        Winw, Winb, Woutw, Woutb, g2, b2, maskV, outV);

    // pass 2: edge update
    pq_kernel<<<NODES/32, 256, smem_pq>>>(hV2p, W11w, W11b);
    edge_mma<1><<<NODES/2, 256, EDGE_SMEM>>>(
        hE, Eidx, maskA, wimg + 3*32768, W12b, W13b, hE, g3, b3, outE);
}

// round 6
// speedup vs baseline: 3.4573x; 1.4624x over previous
#include <cuda_runtime.h>
#include <cuda_bf16.h>
#include <math.h>
#include <stdint.h>

#define Bb 2
#define Nn 2048
#define Kk 48
#define Cc 128
#define NODES (Bb*Nn)          /* 4096 */
#define EPSf 1e-5f
#define INV_SCALE (1.0f/30.0f)

// device scratch (no allocations allowed)
__device__ float g_hV1[NODES*Cc];
__device__ float g_hV2[NODES*Cc];
__device__ float g_P[NODES*Cc];
__device__ float g_Q[NODES*Cc];
__device__ __nv_bfloat16 g_Wimg[18*32768];   // 18 images x (hi 16384 + lo 16384)

// ---------------- helpers ---------------------------------------------------
static __device__ __forceinline__ float gelu_f(float x){
    return 0.5f * x * (1.0f + erff(x * 0.70710678118654752440f));
}
static __device__ __forceinline__ float warp_sum(float v){
    #pragma unroll
    for (int o = 16; o; o >>= 1) v += __shfl_xor_sync(0xffffffffu, v, o);
    return v;
}
static __device__ __forceinline__ uint32_t smem_u32(const void* p){
    uint32_t a;
    asm("{ .reg .u64 t; cvta.to.shared.u64 t, %1; cvt.u32.u64 %0, t; }" : "=r"(a) : "l"(p));
    return a;
}
static __device__ __forceinline__ void ldsm4(uint32_t* r, uint32_t addr){
    asm volatile("ldmatrix.sync.aligned.m8n8.x4.shared.b16 {%0,%1,%2,%3}, [%4];"
        : "=r"(r[0]), "=r"(r[1]), "=r"(r[2]), "=r"(r[3]) : "r"(addr));
}
static __device__ __forceinline__ void mma16816(float* c, const uint32_t* a, uint32_t b0, uint32_t b1){
    asm volatile("mma.sync.aligned.m16n8k16.row.col.f32.bf16.bf16.f32 "
        "{%0,%1,%2,%3},{%4,%5,%6,%7},{%8,%9},{%0,%1,%2,%3};"
        : "+f"(c[0]), "+f"(c[1]), "+f"(c[2]), "+f"(c[3])
        : "r"(a[0]), "r"(a[1]), "r"(a[2]), "r"(a[3]), "r"(b0), "r"(b1));
}
// swizzled byte offset inside a [rows x 128 bf16] tile (256B rows, 16B xor)
static __device__ __forceinline__ uint32_t sw_off(int row, int k){
    return (uint32_t)(row*256 + ((((k >> 3) ^ (row & 7))) << 4) + (k & 7)*2);
}
static __device__ __forceinline__ uint32_t pack_bf(float a, float b){
    __nv_bfloat162 h = __floats2bfloat162_rn(a, b);
    return *reinterpret_cast<uint32_t*>(&h);
}
static __device__ __forceinline__ void split_pair(float a, float b, uint32_t &hi, uint32_t &lo){
    __nv_bfloat16 ha = __float2bfloat16(a);
    __nv_bfloat16 hb = __float2bfloat16(b);
    __nv_bfloat162 H; H.x = ha; H.y = hb;
    hi = *reinterpret_cast<uint32_t*>(&H);
    lo = pack_bf(a - __bfloat162float(ha), b - __bfloat162float(hb));
}

// templated warp GEMM: 16 rows x (NP*16) cols, K=128, 3 split terms
template<int NP>
static __device__ __forceinline__ void gemm_warp(
    uint32_t su, uint32_t offAH, uint32_t offAL, uint32_t offBH, uint32_t offBL,
    uint32_t a_rbase, uint32_t a_rx, int a_k8, int b_nin, int b_k8, int ncol0,
    float (*acc)[4])
{
    #pragma unroll 1
    for (int ks = 0; ks < 8; ++ks){
        uint32_t ah[4], al[4];
        uint32_t ak3 = (uint32_t)(ks*2 + a_k8);
        uint32_t aoff = a_rbase + ((ak3 ^ a_rx) << 4);
        ldsm4(ah, su + offAH + aoff);
        ldsm4(al, su + offAL + aoff);
        uint32_t bk3 = (uint32_t)(ks*2 + b_k8);
        #pragma unroll
        for (int np = 0; np < NP; ++np){
            int brow = ncol0 + np*16 + b_nin;
            uint32_t boff = (uint32_t)(brow*256) + ((bk3 ^ (uint32_t)(brow & 7)) << 4);
            uint32_t bh[4], bl[4];
            ldsm4(bh, su + offBH + boff);
            ldsm4(bl, su + offBL + boff);
            mma16816(acc[2*np],   ah, bh[0], bh[1]);
            mma16816(acc[2*np+1], ah, bh[2], bh[3]);
            mma16816(acc[2*np],   ah, bl[0], bl[1]);
            mma16816(acc[2*np+1], ah, bl[2], bl[3]);
            mma16816(acc[2*np],   al, bh[0], bh[1]);
            mma16816(acc[2*np+1], al, bh[2], bh[3]);
        }
    }
}

// ===================== weight prep: 18 transposed split images ==============
// img[n][k] (swizzled, hi/lo) so ldmatrix gives B^T fragments.
__global__ void __launch_bounds__(256) prep_w(
    const float* __restrict__ W1w,  const float* __restrict__ W2w,
    const float* __restrict__ W3w,  const float* __restrict__ W11w,
    const float* __restrict__ W12w, const float* __restrict__ W13w,
    const float* __restrict__ Winw, const float* __restrict__ Woutw)
{
    extern __shared__ float ws[];   // [128][128]
    const int b = blockIdx.x;
    const float* ptr; int ld = 128;
    switch (b){
        case 0: ptr = W1w + 128*128; break;
        case 1: ptr = W2w;  break;
        case 2: ptr = W3w;  break;
        case 3: ptr = W11w + 128*128; break;
        case 4: ptr = W12w; break;
        case 5: ptr = W13w; break;
        case 6: ptr = W1w;  break;
        case 7: ptr = W1w + 256*128; break;
        case 8: ptr = W11w; break;
        case 9: ptr = W11w + 256*128; break;
        case 10: case 11: case 12: case 13:
            ptr = Winw + (b - 10)*128; ld = 512; break;
        default: // 14..17
            ptr = Woutw + (size_t)(b - 14)*128*128; break;
    }
    const int t = threadIdx.x;
    for (int idx = t; idx < 4096; idx += 256){
        int k = idx >> 5, n4 = (idx & 31)*4;
        *(float4*)(ws + k*128 + n4) = *(const float4*)(ptr + (size_t)k*ld + n4);
    }
    __syncthreads();

    __nv_bfloat16* hi = g_Wimg + (size_t)b * 32768;
    __nv_bfloat16* lo = hi + 16384;
    for (int c = t; c < 2048; c += 256){
        int row = c >> 4;            // n
        int k0  = (c & 15) << 3;     // k
        union { uint32_t u[4]; uint4 q; } H, L;
        #pragma unroll
        for (int j = 0; j < 4; ++j){
            float w0 = ws[(k0 + 2*j    )*128 + row];
            float w1 = ws[(k0 + 2*j + 1)*128 + row];
            split_pair(w0, w1, H.u[j], L.u[j]);
        }
        uint32_t off = (uint32_t)(row*256 + (((k0 >> 3) ^ (row & 7)) << 4));
        *(uint4*)((char*)hi + off) = H.q;
        *(uint4*)((char*)lo + off) = L.q;
    }
}

// ===================== node kernel: PQ (MODE 0) / FFN (MODE 1) ==============
// 32 rows per CTA, 128 threads (4 warps: warp = 16 rows x 64 cols)
#define NODE_SMEM 115200
// smem byte offsets
#define N_AH 0u
#define N_AL 8192u
#define N_HH 16384u
#define N_HL 24576u
#define N_BH 32768u
#define N_BL 65536u
#define N_SCR 98304u

template<int MODE>
__global__ void __launch_bounds__(128) node_mma(
    const float* __restrict__ src,            // PQ: nodes ; FFN: g_hV1
    const __nv_bfloat16* __restrict__ imgQ,   // PQ: Wq img ; FFN: WinT chunk base
    const __nv_bfloat16* __restrict__ imgP,   // PQ: Wp img ; FFN: WoutT chunk base
    const float* __restrict__ ba,             // PQ: W1b ; FFN: bin
    const float* __restrict__ bout,
    const float* __restrict__ gam, const float* __restrict__ bet,
    const float* __restrict__ maskV,
    float* __restrict__ outQ, float* __restrict__ outP,   // PQ outputs
    float* __restrict__ outV)                              // FFN output
{
    extern __shared__ char smc[];
    const uint32_t su = smem_u32(smc);
    const int t = threadIdx.x, lane = t & 31, w = t >> 5;
    const int blk = blockIdx.x;
    const int r0g = blk*32;                     // first row (node) of this CTA

    // warp geometry
    const int m0 = (w & 1)*16, ncol0 = (w >> 1)*64;
    const int qrow = lane >> 2, qcol = (lane & 3)*2;
    const int rowA = m0 + qrow, rowB = rowA + 8;
    const int sel = lane >> 3, la7 = lane & 7;
    const int a_row = m0 + la7 + ((sel & 1) << 3);
    const uint32_t a_rbase = (uint32_t)(a_row*256);
    const uint32_t a_rx = (uint32_t)(a_row & 7);
    const int a_k8 = sel >> 1;
    const int b_nin = la7 + ((sel >> 1) << 3);
    const int b_k8 = sel & 1;

    // ---- stage A (32 rows of src, split) -----------------------------------
    for (int c = t; c < 512; c += 128){
        int row = c >> 4, k0 = (c & 15) << 3;
        const float4* s = (const float4*)(src + (size_t)(r0g + row)*128 + k0);
        float4 v0 = s[0], v1 = s[1];
        union { uint32_t u[4]; uint4 q; } H, L;
        split_pair(v0.x, v0.y, H.u[0], L.u[0]);
        split_pair(v0.z, v0.w, H.u[1], L.u[1]);
        split_pair(v1.x, v1.y, H.u[2], L.u[2]);
        split_pair(v1.z, v1.w, H.u[3], L.u[3]);
        uint32_t off = (uint32_t)(row*256 + (((k0 >> 3) ^ (row & 7)) << 4));
        *(uint4*)(smc + N_AH + off) = H.q;
        *(uint4*)(smc + N_AL + off) = L.q;
    }

    if (MODE == 0){
        // ------------------- PQ: two GEMMs ----------------------------------
        #pragma unroll 1
        for (int m = 0; m < 2; ++m){
            __syncthreads();
            const __nv_bfloat16* img = m ? imgP : imgQ;
            {
                const uint4* sH = (const uint4*)img;
                const uint4* sL = sH + 2048;
                uint4* dH = (uint4*)(smc + N_BH);
                uint4* dL = (uint4*)(smc + N_BL);
                #pragma unroll
                for (int i = 0; i < 16; ++i){ dH[t + i*128] = sH[t + i*128]; dL[t + i*128] = sL[t + i*128]; }
            }
            __syncthreads();
            float acc[8][4];
            #pragma unroll
            for (int i = 0; i < 8; ++i){
                if (m == 0){
                    float2 b2 = *(const float2*)(ba + ncol0 + i*8 + qcol);
                    acc[i][0] = b2.x; acc[i][1] = b2.y; acc[i][2] = b2.x; acc[i][3] = b2.y;
                } else {
                    acc[i][0] = acc[i][1] = acc[i][2] = acc[i][3] = 0.f;
                }
            }
            gemm_warp<4>(su, N_AH, N_AL, N_BH, N_BL, a_rbase, a_rx, a_k8, b_nin, b_k8, ncol0, acc);
            float* dst = m ? outP : outQ;
            #pragma unroll
            for (int i = 0; i < 8; ++i){
                int n = ncol0 + i*8 + qcol;
                *(float2*)(dst + (size_t)(r0g + rowA)*128 + n) = make_float2(acc[i][0], acc[i][1]);
                *(float2*)(dst + (size_t)(r0g + rowB)*128 + n) = make_float2(acc[i][2], acc[i][3]);
            }
        }
    } else {
        // ------------------- FFN: 4 chunks of hidden ------------------------
        float out_acc[8][4];
        #pragma unroll
        for (int i = 0; i < 8; ++i){
            float2 b2 = *(const float2*)(bout + ncol0 + i*8 + qcol);
            out_acc[i][0] = b2.x; out_acc[i][1] = b2.y;
            out_acc[i][2] = b2.x; out_acc[i][3] = b2.y;
        }
        #pragma unroll 1
        for (int c = 0; c < 4; ++c){
            __syncthreads();
            {
                const uint4* sH = (const uint4*)(imgQ + (size_t)c*32768);
                const uint4* sL = sH + 2048;
                uint4* dH = (uint4*)(smc + N_BH);
                uint4* dL = (uint4*)(smc + N_BL);
                #pragma unroll
                for (int i = 0; i < 16; ++i){ dH[t + i*128] = sH[t + i*128]; dL[t + i*128] = sL[t + i*128]; }
            }
            __syncthreads();
            float h_acc[8][4];
            #pragma unroll
            for (int i = 0; i < 8; ++i){
                float2 b2 = *(const float2*)(ba + c*128 + ncol0 + i*8 + qcol);
                h_acc[i][0] = b2.x; h_acc[i][1] = b2.y;
                h_acc[i][2] = b2.x; h_acc[i][3] = b2.y;
            }
            gemm_warp<4>(su, N_AH, N_AL, N_BH, N_BL, a_rbase, a_rx, a_k8, b_nin, b_k8, ncol0, h_acc);
            // gelu + split into H tiles
            #pragma unroll
            for (int i = 0; i < 8; ++i){
                int n = ncol0 + i*8 + qcol;
                float g0 = gelu_f(h_acc[i][0]), g1 = gelu_f(h_acc[i][1]);
                float g2v = gelu_f(h_acc[i][2]), g3v = gelu_f(h_acc[i][3]);
                uint32_t hA, lA, hB, lB;
                split_pair(g0, g1, hA, lA);
                split_pair(g2v, g3v, hB, lB);
                uint32_t offA = sw_off(rowA, n), offB = sw_off(rowB, n);
                *(uint32_t*)(smc + N_HH + offA) = hA;
                *(uint32_t*)(smc + N_HL + offA) = lA;
                *(uint32_t*)(smc + N_HH + offB) = hB;
                *(uint32_t*)(smc + N_HL + offB) = lB;
            }
            __syncthreads();
            {
                const uint4* sH = (const uint4*)(imgP + (size_t)c*32768);
                const uint4* sL = sH + 2048;
                uint4* dH = (uint4*)(smc + N_BH);
                uint4* dL = (uint4*)(smc + N_BL);
                #pragma unroll
                for (int i = 0; i < 16; ++i){ dH[t + i*128] = sH[t + i*128]; dL[t + i*128] = sL[t + i*128]; }
            }
            __syncthreads();
            gemm_warp<4>(su, N_HH, N_HL, N_BH, N_BL, a_rbase, a_rx, a_k8, b_nin, b_k8, ncol0, out_acc);
        }
        // ---- epilogue: residual + LN + mask -> outV, g_hV2 -----------------
        __syncthreads();
        float* scr = (float*)(smc + N_SCR);   // [32][132]
        #pragma unroll
        for (int i = 0; i < 8; ++i){
            int n = ncol0 + i*8 + qcol;
            float2 rA = *(const float2*)(src + (size_t)(r0g + rowA)*128 + n);
            float2 rB = *(const float2*)(src + (size_t)(r0g + rowB)*128 + n);
            scr[rowA*132 + n]     = rA.x + out_acc[i][0];
            scr[rowA*132 + n + 1] = rA.y + out_acc[i][1];
            scr[rowB*132 + n]     = rB.x + out_acc[i][2];
            scr[rowB*132 + n + 1] = rB.y + out_acc[i][3];
        }
        __syncthreads();
        #pragma unroll 1
        for (int r8 = 0; r8 < 8; ++r8){
            int r = w*8 + r8;
            int node = r0g + r;
            float x0 = scr[r*132 + lane],      x1 = scr[r*132 + lane + 32];
            float x2 = scr[r*132 + lane + 64], x3 = scr[r*132 + lane + 96];
            float s = warp_sum(x0 + x1 + x2 + x3);
            float q = warp_sum(x0*x0 + x1*x1 + x2*x2 + x3*x3);
            float mean = s * 0.0078125f;
            float var  = q * 0.0078125f - mean*mean;
            float rs = rsqrtf(var + EPSf);
            float mv = maskV[node];
            float y0 = mv*(gam[lane]     *(x0 - mean)*rs + bet[lane]);
            float y1 = mv*(gam[lane + 32]*(x1 - mean)*rs + bet[lane + 32]);
            float y2 = mv*(gam[lane + 64]*(x2 - mean)*rs + bet[lane + 64]);
            float y3 = mv*(gam[lane + 96]*(x3 - mean)*rs + bet[lane + 96]);
            float* o = outV + (size_t)node*128;
            o[lane] = y0; o[lane+32] = y1; o[lane+64] = y2; o[lane+96] = y3;
            float* g = g_hV2 + (size_t)node*128;
            g[lane] = y0; g[lane+32] = y1; g[lane+64] = y2; g[lane+96] = y3;
        }
    }
}

// ======================= edge pass: 4 nodes (192 rows) per CTA ==============
#define EDGE_SMEM 164864
#define E_AH 1024u
#define E_AL 50176u
#define E_BH 99328u
#define E_BL 132096u

template<int MODE>
__global__ void __launch_bounds__(384) edge_mma(
    const float* __restrict__ hE,
    const int*   __restrict__ Eidx,
    const float* __restrict__ maskA,
    const __nv_bfloat16* __restrict__ Wimg,   // 3 layer slots x 32768 bf16
    const float* __restrict__ bb, const float* __restrict__ bc,
    const float* __restrict__ residV,
    const float* __restrict__ gam, const float* __restrict__ bet,
    float* __restrict__ outp)                 // MODE0: g_hV1 ; MODE1: outE
{
    extern __shared__ char smc[];
    const uint32_t su = smem_u32(smc);
    int*   sidx = (int*)smc;                  // 192 ints
    float* s_s  = (float*)(smc + 768);        // [4][4]
    float* s_q  = (float*)(smc + 832);        // [4][4]

    const int t = threadIdx.x, lane = t & 31, wid = t >> 5;
    const int blk = blockIdx.x, node0 = blk*4;
    const int nbase = (node0 >> 11) << 11;

    if (t < 192) sidx[t] = Eidx[(size_t)blk*192 + t];

    // ---- stage A (h_E, 192 rows split) + B layer 0 -------------------------
    for (int c = t; c < 3072; c += 384){
        int row = c >> 4, k0 = (c & 15) << 3;
        const float4* s = (const float4*)(hE + ((size_t)blk*192 + row)*128 + k0);
        float4 v0 = s[0], v1 = s[1];
        union { uint32_t u[4]; uint4 q; } H, L;
        split_pair(v0.x, v0.y, H.u[0], L.u[0]);
        split_pair(v0.z, v0.w, H.u[1], L.u[1]);
        split_pair(v1.x, v1.y, H.u[2], L.u[2]);
        split_pair(v1.z, v1.w, H.u[3], L.u[3]);
        uint32_t off = (uint32_t)(row*256 + (((k0 >> 3) ^ (row & 7)) << 4));
        *(uint4*)(smc + E_AH + off) = H.q;
        *(uint4*)(smc + E_AL + off) = L.q;
    }
    {
        const uint4* sH = (const uint4*)Wimg;
        const uint4* sL = sH + 2048;
        uint4* dH = (uint4*)(smc + E_BH);
        uint4* dL = (uint4*)(smc + E_BL);
        for (int i = t; i < 2048; i += 384){ dH[i] = sH[i]; dL[i] = sL[i]; }
    }
    __syncthreads();

    // warp geometry (warp covers 16 rows x all 128 cols)
    const int m0 = wid*16;
    const int qrow = lane >> 2, qcol = (lane & 3)*2;
    const int rowA = m0 + qrow, rowB = rowA + 8;
    const int sel = lane >> 3, la7 = lane & 7;
    const int a_row = m0 + la7 + ((sel & 1) << 3);
    const uint32_t a_rbase = (uint32_t)(a_row*256);
    const uint32_t a_rx = (uint32_t)(a_row & 7);
    const int a_k8 = sel >> 1;
    const int b_nin = la7 + ((sel >> 1) << 3);
    const int b_k8 = sel & 1;

    float acc[16][4];

    #pragma unroll 1
    for (int l = 0; l < 3; ++l){
        // ---- init accumulators ---------------------------------------------
        if (l == 0){
            const float* qA = g_Q + (size_t)(node0 + rowA/48)*128;
            const float* pA = g_P + (size_t)(nbase + sidx[rowA])*128;
            const float* qB = g_Q + (size_t)(node0 + rowB/48)*128;
            const float* pB = g_P + (size_t)(nbase + sidx[rowB])*128;
            #pragma unroll
            for (int i = 0; i < 16; ++i){
                int n = i*8 + qcol;
                float2 q0 = *(const float2*)(qA + n), p0 = *(const float2*)(pA + n);
                float2 q1 = *(const float2*)(qB + n), p1 = *(const float2*)(pB + n);
                acc[i][0] = q0.x + p0.x; acc[i][1] = q0.y + p0.y;
                acc[i][2] = q1.x + p1.x; acc[i][3] = q1.y + p1.y;
            }
        } else {
            const float* bias = (l == 1) ? bb : bc;
            #pragma unroll
            for (int i = 0; i < 16; ++i){
                float2 b2 = *(const float2*)(bias + i*8 + qcol);
                acc[i][0] = b2.x; acc[i][1] = b2.y;
                acc[i][2] = b2.x; acc[i][3] = b2.y;
            }
        }

        gemm_warp<8>(su, E_AH, E_AL, E_BH, E_BL, a_rbase, a_rx, a_k8, b_nin, b_k8, 0, acc);

        if (l < 2){
            __syncthreads();     // all A/B reads done before overwrite
            #pragma unroll
            for (int i = 0; i < 16; ++i){
                int n = i*8 + qcol;
                float g0 = gelu_f(acc[i][0]), g1 = gelu_f(acc[i][1]);
                float g2v = gelu_f(acc[i][2]), g3v = gelu_f(acc[i][3]);
                uint32_t hA, lA, hB, lB;
                split_pair(g0, g1, hA, lA);
                split_pair(g2v, g3v, hB, lB);
                uint32_t offA = sw_off(rowA, n), offB = sw_off(rowB, n);
                *(uint32_t*)(smc + E_AH + offA) = hA;
                *(uint32_t*)(smc + E_AL + offA) = lA;
                *(uint32_t*)(smc + E_AH + offB) = hB;
                *(uint32_t*)(smc + E_AL + offB) = lB;
            }
            {
                const uint4* sH = (const uint4*)(Wimg + (size_t)(l + 1)*32768);
                const uint4* sL = sH + 2048;
                uint4* dH = (uint4*)(smc + E_BH);
                uint4* dL = (uint4*)(smc + E_BL);
                for (int i = t; i < 2048; i += 384){ dH[i] = sH[i]; dL[i] = sL[i]; }
            }
            __syncthreads();
        }
    }

    // ======================= final epilogue ================================
    if (MODE == 0){
        __syncthreads();                       // B reads done; reuse as scratch
        float* part = (float*)(smc + E_BH);    // [12][132]
        float* xs   = (float*)(smc + E_BH + 8192);  // [512]
        float mA = maskA[(size_t)blk*192 + rowA];
        float mB = maskA[(size_t)blk*192 + rowB];
        #pragma unroll
        for (int i = 0; i < 16; ++i){
            float p0 = mA*acc[i][0] + mB*acc[i][2];
            float p1 = mA*acc[i][1] + mB*acc[i][3];
            #pragma unroll
            for (int o = 4; o <= 16; o <<= 1){
                p0 += __shfl_xor_sync(0xffffffffu, p0, o);
                p1 += __shfl_xor_sync(0xffffffffu, p1, o);
            }
            if (lane < 4){
                part[wid*132 + i*8 + qcol]     = p0;
                part[wid*132 + i*8 + qcol + 1] = p1;
            }
        }
        __syncthreads();
        for (int idx = t; idx < 512; idx += 384){
            int nl = idx >> 7, c = idx & 127;
            float s = part[(nl*3+0)*132 + c] + part[(nl*3+1)*132 + c] + part[(nl*3+2)*132 + c];
            float xv = residV[(size_t)(node0 + nl)*128 + c] + s * INV_SCALE;
            xs[idx] = xv;
            float ws = warp_sum(xv), wq = warp_sum(xv*xv);
            if (lane == 0){ s_s[nl*4 + ((idx >> 5) & 3)] = ws; s_q[nl*4 + ((idx >> 5) & 3)] = wq; }
        }
        __syncthreads();
        for (int idx = t; idx < 512; idx += 384){
            int nl = idx >> 7, c = idx & 127;
            float mean = (s_s[nl*4] + s_s[nl*4+1] + s_s[nl*4+2] + s_s[nl*4+3]) * 0.0078125f;
            float var  = (s_q[nl*4] + s_q[nl*4+1] + s_q[nl*4+2] + s_q[nl*4+3]) * 0.0078125f - mean*mean;
            outp[(size_t)(node0 + nl)*128 + c] =
                gam[c]*(xs[idx] - mean)*rsqrtf(var + EPSf) + bet[c];
        }
    } else {
        // per-edge LN(h_E + msg) -> outp
        float sA = 0.f, qA = 0.f, sB = 0.f, qB = 0.f;
        const float* eA = hE + ((size_t)blk*192 + rowA)*128;
        const float* eB = hE + ((size_t)blk*192 + rowB)*128;
        #pragma unroll
        for (int i = 0; i < 16; ++i){
            int n = i*8 + qcol;
            float2 e0 = *(const float2*)(eA + n);
            float2 e1 = *(const float2*)(eB + n);
            float v0 = e0.x + acc[i][0], v1 = e0.y + acc[i][1];
            float v2 = e1.x + acc[i][2], v3 = e1.y + acc[i][3];
            acc[i][0] = v0; acc[i][1] = v1; acc[i][2] = v2; acc[i][3] = v3;
            sA += v0 + v1; qA += v0*v0 + v1*v1;
            sB += v2 + v3; qB += v2*v2 + v3*v3;
        }
        sA += __shfl_xor_sync(0xffffffffu, sA, 1); sA += __shfl_xor_sync(0xffffffffu, sA, 2);
        qA += __shfl_xor_sync(0xffffffffu, qA, 1); qA += __shfl_xor_sync(0xffffffffu, qA, 2);
        sB += __shfl_xor_sync(0xffffffffu, sB, 1); sB += __shfl_xor_sync(0xffffffffu, sB, 2);
        qB += __shfl_xor_sync(0xffffffffu, qB, 1); qB += __shfl_xor_sync(0xffffffffu, qB, 2);
        {
            float meanA = sA * 0.0078125f;
            float varA  = qA * 0.0078125f - meanA*meanA;
            float rsA   = rsqrtf(varA + EPSf);
            float meanB = sB * 0.0078125f;
            float varB  = qB * 0.0078125f - meanB*meanB;
            float rsB   = rsqrtf(varB + EPSf);
            float* oA = outp + ((size_t)blk*192 + rowA)*128;
            float* oB = outp + ((size_t)blk*192 + rowB)*128;
            #pragma unroll
            for (int i = 0; i < 16; ++i){
                int n = i*8 + qcol;
                float2 g = *(const float2*)(gam + n);
                float2 b = *(const float2*)(bet + n);
                float2 o0, o1;
                o0.x = g.x*(acc[i][0] - meanA)*rsA + b.x;
                o0.y = g.y*(acc[i][1] - meanA)*rsA + b.y;
                o1.x = g.x*(acc[i][2] - meanB)*rsB + b.x;
                o1.y = g.y*(acc[i][3] - meanB)*rsB + b.y;
                *(float2*)(oA + n) = o0;
                *(float2*)(oB + n) = o1;
            }
        }
    }
}

// ---------------------------------------------------------------------------
extern "C" void kernel_launch(void* const* d_in, const int* in_sizes, int n_in,
                              void* d_out, int out_size)
{
    const float* hV    = (const float*)d_in[0];
    const float* hE    = (const float*)d_in[1];
    const int*   Eidx  = (const int*)  d_in[2];
    const float* maskV = (const float*)d_in[3];
    const float* maskA = (const float*)d_in[4];
    const float* W1w   = (const float*)d_in[5];  const float* W1b  = (const float*)d_in[6];
    const float* W2w   = (const float*)d_in[7];  const float* W2b  = (const float*)d_in[8];
    const float* W3w   = (const float*)d_in[9];  const float* W3b  = (const float*)d_in[10];
    const float* W11w  = (const float*)d_in[11]; const float* W11b = (const float*)d_in[12];
    const float* W12w  = (const float*)d_in[13]; const float* W12b = (const float*)d_in[14];
    const float* W13w  = (const float*)d_in[15]; const float* W13b = (const float*)d_in[16];
    const float* Winw  = (const float*)d_in[17]; const float* Winb = (const float*)d_in[18];
    const float* Woutw = (const float*)d_in[19]; const float* Woutb= (const float*)d_in[20];
    const float* g1    = (const float*)d_in[21]; const float* b1   = (const float*)d_in[22];
    const float* g2    = (const float*)d_in[23]; const float* b2   = (const float*)d_in[24];
    const float* g3    = (const float*)d_in[25]; const float* b3   = (const float*)d_in[26];

    float* out  = (float*)d_out;
    float* outV = out;
    float* outE = out + (size_t)NODES*Cc;

    float* hV1p; cudaGetSymbolAddress((void**)&hV1p, g_hV1);
    float* hV2p; cudaGetSymbolAddress((void**)&hV2p, g_hV2);
    float* gQp;  cudaGetSymbolAddress((void**)&gQp,  g_Q);
    float* gPp;  cudaGetSymbolAddress((void**)&gPp,  g_P);
    __nv_bfloat16* wimg; cudaGetSymbolAddress((void**)&wimg, g_Wimg);

    cudaFuncSetAttribute(prep_w,      cudaFuncAttributeMaxDynamicSharedMemorySize, 65536);
    cudaFuncSetAttribute(node_mma<0>, cudaFuncAttributeMaxDynamicSharedMemorySize, NODE_SMEM);
    cudaFuncSetAttribute(node_mma<1>, cudaFuncAttributeMaxDynamicSharedMemorySize, NODE_SMEM);
    cudaFuncSetAttribute(edge_mma<0>, cudaFuncAttributeMaxDynamicSharedMemorySize, EDGE_SMEM);
    cudaFuncSetAttribute(edge_mma<1>, cudaFuncAttributeMaxDynamicSharedMemorySize, EDGE_SMEM);

    prep_w<<<18, 256, 65536>>>(W1w, W2w, W3w, W11w, W12w, W13w, Winw, Woutw);

    // pass 1: node message
    node_mma<0><<<NODES/32, 128, NODE_SMEM>>>(
        hV, wimg + (size_t)6*32768, wimg + (size_t)7*32768,
        W1b, nullptr, nullptr, nullptr, nullptr, gQp, gPp, nullptr);
    edge_mma<0><<<NODES/4, 384, EDGE_SMEM>>>(
        hE, Eidx, maskA, wimg, W2b, W3b, hV, g1, b1, hV1p);

    // FFN + LN2 + mask
    node_mma<1><<<NODES/32, 128, NODE_SMEM>>>(
        hV1p, wimg + (size_t)10*32768, wimg + (size_t)14*32768,
        Winb, Woutb, g2, b2, maskV, nullptr, nullptr, outV);

    // pass 2: edge update
    node_mma<0><<<NODES/32, 128, NODE_SMEM>>>(
        hV2p, wimg + (size_t)8*32768, wimg + (size_t)9*32768,
        W11b, nullptr, nullptr, nullptr, nullptr, gQp, gPp, nullptr);
    edge_mma<1><<<NODES/4, 384, EDGE_SMEM>>>(
        hE, Eidx, maskA, wimg + (size_t)3*32768, W12b, W13b, hE, g3, b3, outE);
}

// round 8
// speedup vs baseline: 3.5433x; 1.0249x over previous
#include <cuda_runtime.h>
#include <cuda_bf16.h>
#include <math.h>
#include <stdint.h>

#define Bb 2
#define Nn 2048
#define Kk 48
#define Cc 128
#define NODES (Bb*Nn)          /* 4096 */
#define EPSf 1e-5f
#define INV_SCALE (1.0f/30.0f)

// device scratch (no allocations allowed)
__device__ float g_hV1[NODES*Cc];
__device__ float g_hV2[NODES*Cc];
__device__ float g_P[NODES*Cc];
__device__ float g_Q[NODES*Cc];
__device__ __nv_bfloat16 g_Wimg[18*32768];   // 18 images x (hi 16384 + lo 16384)

// ---------------- helpers ---------------------------------------------------
static __device__ __forceinline__ float gelu_f(float x){
    return 0.5f * x * (1.0f + erff(x * 0.70710678118654752440f));
}
static __device__ __forceinline__ float warp_sum(float v){
    #pragma unroll
    for (int o = 16; o; o >>= 1) v += __shfl_xor_sync(0xffffffffu, v, o);
    return v;
}
static __device__ __forceinline__ uint32_t smem_u32(const void* p){
    uint32_t a;
    asm("{ .reg .u64 t; cvta.to.shared.u64 t, %1; cvt.u32.u64 %0, t; }" : "=r"(a) : "l"(p));
    return a;
}
static __device__ __forceinline__ void ldsm4(uint32_t* r, uint32_t addr){
    asm volatile("ldmatrix.sync.aligned.m8n8.x4.shared.b16 {%0,%1,%2,%3}, [%4];"
        : "=r"(r[0]), "=r"(r[1]), "=r"(r[2]), "=r"(r[3]) : "r"(addr));
}
static __device__ __forceinline__ void mma16816(float* c, const uint32_t* a, uint32_t b0, uint32_t b1){
    asm volatile("mma.sync.aligned.m16n8k16.row.col.f32.bf16.bf16.f32 "
        "{%0,%1,%2,%3},{%4,%5,%6,%7},{%8,%9},{%0,%1,%2,%3};"
        : "+f"(c[0]), "+f"(c[1]), "+f"(c[2]), "+f"(c[3])
        : "r"(a[0]), "r"(a[1]), "r"(a[2]), "r"(a[3]), "r"(b0), "r"(b1));
}
// swizzled byte offset inside a [rows x 128 bf16] tile (256B rows, 16B xor)
static __device__ __forceinline__ uint32_t sw_off(int row, int k){
    return (uint32_t)(row*256 + ((((k >> 3) ^ (row & 7))) << 4) + (k & 7)*2);
}
static __device__ __forceinline__ uint32_t pack_bf(float a, float b){
    __nv_bfloat162 h = __floats2bfloat162_rn(a, b);
    return *reinterpret_cast<uint32_t*>(&h);
}
static __device__ __forceinline__ void split_pair(float a, float b, uint32_t &hi, uint32_t &lo){
    __nv_bfloat16 ha = __float2bfloat16(a);
    __nv_bfloat16 hb = __float2bfloat16(b);
    __nv_bfloat162 H; H.x = ha; H.y = hb;
    hi = *reinterpret_cast<uint32_t*>(&H);
    lo = pack_bf(a - __bfloat162float(ha), b - __bfloat162float(hb));
}

// templated warp GEMM: 16 rows x (NP*16) cols, K=128, 3 split terms.
// Term-sweep order: all np with ah*bh, then ah*bl, then al*bh -> same-acc RAW
// distance is 2*NP mma issues instead of 2.
template<int NP>
static __device__ __forceinline__ void gemm_warp(
    uint32_t su, uint32_t offAH, uint32_t offAL, uint32_t offBH, uint32_t offBL,
    uint32_t a_rbase, uint32_t a_rx, int a_k8, int b_nin, int b_k8, int ncol0,
    float (*acc)[4])
{
    #pragma unroll 1
    for (int ks = 0; ks < 8; ++ks){
        uint32_t ah[4], al[4];
        uint32_t ak3 = (uint32_t)(ks*2 + a_k8);
        uint32_t aoff = a_rbase + ((ak3 ^ a_rx) << 4);
        ldsm4(ah, su + offAH + aoff);
        ldsm4(al, su + offAL + aoff);
        uint32_t bk3 = (uint32_t)(ks*2 + b_k8);
        uint32_t boffs[NP];
        #pragma unroll
        for (int np = 0; np < NP; ++np){
            int brow = ncol0 + np*16 + b_nin;
            boffs[np] = (uint32_t)(brow*256) + ((bk3 ^ (uint32_t)(brow & 7)) << 4);
        }
        uint32_t bfr[NP][4];
        // sweep 1: ah x bh
        #pragma unroll
        for (int np = 0; np < NP; ++np) ldsm4(bfr[np], su + offBH + boffs[np]);
        #pragma unroll
        for (int np = 0; np < NP; ++np){
            mma16816(acc[2*np],   ah, bfr[np][0], bfr[np][1]);
            mma16816(acc[2*np+1], ah, bfr[np][2], bfr[np][3]);
        }
        // sweep 2: ah x bl
        #pragma unroll
        for (int np = 0; np < NP; ++np) ldsm4(bfr[np], su + offBL + boffs[np]);
        #pragma unroll
        for (int np = 0; np < NP; ++np){
            mma16816(acc[2*np],   ah, bfr[np][0], bfr[np][1]);
            mma16816(acc[2*np+1], ah, bfr[np][2], bfr[np][3]);
        }
        // sweep 3: al x bh
        #pragma unroll
        for (int np = 0; np < NP; ++np) ldsm4(bfr[np], su + offBH + boffs[np]);
        #pragma unroll
        for (int np = 0; np < NP; ++np){
            mma16816(acc[2*np],   al, bfr[np][0], bfr[np][1]);
            mma16816(acc[2*np+1], al, bfr[np][2], bfr[np][3]);
        }
    }
}

// ===================== weight prep: 18 transposed split images ==============
__global__ void __launch_bounds__(256) prep_w(
    const float* __restrict__ W1w,  const float* __restrict__ W2w,
    const float* __restrict__ W3w,  const float* __restrict__ W11w,
    const float* __restrict__ W12w, const float* __restrict__ W13w,
    const float* __restrict__ Winw, const float* __restrict__ Woutw)
{
    extern __shared__ float ws[];   // [128][128]
    const int b = blockIdx.x;
    const float* ptr; int ld = 128;
    switch (b){
        case 0: ptr = W1w + 128*128; break;
        case 1: ptr = W2w;  break;
        case 2: ptr = W3w;  break;
        case 3: ptr = W11w + 128*128; break;
        case 4: ptr = W12w; break;
        case 5: ptr = W13w; break;
        case 6: ptr = W1w;  break;
        case 7: ptr = W1w + 256*128; break;
        case 8: ptr = W11w; break;
        case 9: ptr = W11w + 256*128; break;
        case 10: case 11: case 12: case 13:
            ptr = Winw + (b - 10)*128; ld = 512; break;
        default: // 14..17
            ptr = Woutw + (size_t)(b - 14)*128*128; break;
    }
    const int t = threadIdx.x;
    for (int idx = t; idx < 4096; idx += 256){
        int k = idx >> 5, n4 = (idx & 31)*4;
        *(float4*)(ws + k*128 + n4) = *(const float4*)(ptr + (size_t)k*ld + n4);
    }
    __syncthreads();

    __nv_bfloat16* hi = g_Wimg + (size_t)b * 32768;
    __nv_bfloat16* lo = hi + 16384;
    for (int c = t; c < 2048; c += 256){
        int row = c >> 4;            // n
        int k0  = (c & 15) << 3;     // k
        union { uint32_t u[4]; uint4 q; } H, L;
        #pragma unroll
        for (int j = 0; j < 4; ++j){
            float w0 = ws[(k0 + 2*j    )*128 + row];
            float w1 = ws[(k0 + 2*j + 1)*128 + row];
            split_pair(w0, w1, H.u[j], L.u[j]);
        }
        uint32_t off = (uint32_t)(row*256 + (((k0 >> 3) ^ (row & 7)) << 4));
        *(uint4*)((char*)hi + off) = H.q;
        *(uint4*)((char*)lo + off) = L.q;
    }
}

// ===================== node kernel: PQ (MODE 0) / FFN (MODE 1) ==============
// 32 rows per CTA, 256 threads (8 warps: warp = 16 rows x 32 cols, NP=2)
#define NODE_SMEM 115200
#define N_AH 0u
#define N_AL 8192u
#define N_HH 16384u
#define N_HL 24576u
#define N_BH 32768u
#define N_BL 65536u
#define N_SCR 98304u

template<int MODE>
__global__ void __launch_bounds__(256) node_mma(
    const float* __restrict__ src,            // PQ: nodes ; FFN: g_hV1
    const __nv_bfloat16* __restrict__ imgQ,   // PQ: Wq img ; FFN: WinT chunk base
    const __nv_bfloat16* __restrict__ imgP,   // PQ: Wp img ; FFN: WoutT chunk base
    const float* __restrict__ ba,             // PQ: W1b ; FFN: bin
    const float* __restrict__ bout,
    const float* __restrict__ gam, const float* __restrict__ bet,
    const float* __restrict__ maskV,
    float* __restrict__ outQ, float* __restrict__ outP,   // PQ outputs
    float* __restrict__ outV)                              // FFN output
{
    extern __shared__ char smc[];
    const uint32_t su = smem_u32(smc);
    const int t = threadIdx.x, lane = t & 31, w = t >> 5;
    const int blk = blockIdx.x;
    const int r0g = blk*32;

    // warp geometry: 8 warps = 2 row-groups x 4 col-groups of 32
    const int m0 = (w & 1)*16, ncol0 = (w >> 1)*32;
    const int qrow = lane >> 2, qcol = (lane & 3)*2;
    const int rowA = m0 + qrow, rowB = rowA + 8;
    const int sel = lane >> 3, la7 = lane & 7;
    const int a_row = m0 + la7 + ((sel & 1) << 3);
    const uint32_t a_rbase = (uint32_t)(a_row*256);
    const uint32_t a_rx = (uint32_t)(a_row & 7);
    const int a_k8 = sel >> 1;
    const int b_nin = la7 + ((sel >> 1) << 3);
    const int b_k8 = sel & 1;

    // ---- stage A (32 rows of src, split) -----------------------------------
    for (int c = t; c < 512; c += 256){
        int row = c >> 4, k0 = (c & 15) << 3;
        const float4* s = (const float4*)(src + (size_t)(r0g + row)*128 + k0);
        float4 v0 = s[0], v1 = s[1];
        union { uint32_t u[4]; uint4 q; } H, L;
        split_pair(v0.x, v0.y, H.u[0], L.u[0]);
        split_pair(v0.z, v0.w, H.u[1], L.u[1]);
        split_pair(v1.x, v1.y, H.u[2], L.u[2]);
        split_pair(v1.z, v1.w, H.u[3], L.u[3]);
        uint32_t off = (uint32_t)(row*256 + (((k0 >> 3) ^ (row & 7)) << 4));
        *(uint4*)(smc + N_AH + off) = H.q;
        *(uint4*)(smc + N_AL + off) = L.q;
    }

    if (MODE == 0){
        // ------------------- PQ: two GEMMs ----------------------------------
        #pragma unroll 1
        for (int m = 0; m < 2; ++m){
            __syncthreads();
            const __nv_bfloat16* img = m ? imgP : imgQ;
            {
                const uint4* sH = (const uint4*)img;
                const uint4* sL = sH + 2048;
                uint4* dH = (uint4*)(smc + N_BH);
                uint4* dL = (uint4*)(smc + N_BL);
                #pragma unroll
                for (int i = 0; i < 8; ++i){ dH[t + i*256] = sH[t + i*256]; dL[t + i*256] = sL[t + i*256]; }
            }
            __syncthreads();
            float acc[4][4];
            #pragma unroll
            for (int i = 0; i < 4; ++i){
                if (m == 0){
                    float2 b2 = *(const float2*)(ba + ncol0 + i*8 + qcol);
                    acc[i][0] = b2.x; acc[i][1] = b2.y; acc[i][2] = b2.x; acc[i][3] = b2.y;
                } else {
                    acc[i][0] = acc[i][1] = acc[i][2] = acc[i][3] = 0.f;
                }
            }
            gemm_warp<2>(su, N_AH, N_AL, N_BH, N_BL, a_rbase, a_rx, a_k8, b_nin, b_k8, ncol0, acc);
            float* dst = m ? outP : outQ;
            #pragma unroll
            for (int i = 0; i < 4; ++i){
                int n = ncol0 + i*8 + qcol;
                *(float2*)(dst + (size_t)(r0g + rowA)*128 + n) = make_float2(acc[i][0], acc[i][1]);
                *(float2*)(dst + (size_t)(r0g + rowB)*128 + n) = make_float2(acc[i][2], acc[i][3]);
            }
        }
    } else {
        // ------------------- FFN: 4 chunks of hidden ------------------------
        float out_acc[4][4];
        #pragma unroll
        for (int i = 0; i < 4; ++i){
            float2 b2 = *(const float2*)(bout + ncol0 + i*8 + qcol);
            out_acc[i][0] = b2.x; out_acc[i][1] = b2.y;
            out_acc[i][2] = b2.x; out_acc[i][3] = b2.y;
        }
        #pragma unroll 1
        for (int c = 0; c < 4; ++c){
            __syncthreads();
            {
                const uint4* sH = (const uint4*)(imgQ + (size_t)c*32768);
                const uint4* sL = sH + 2048;
                uint4* dH = (uint4*)(smc + N_BH);
                uint4* dL = (uint4*)(smc + N_BL);
                #pragma unroll
                for (int i = 0; i < 8; ++i){ dH[t + i*256] = sH[t + i*256]; dL[t + i*256] = sL[t + i*256]; }
            }
            __syncthreads();
            float h_acc[4][4];
            #pragma unroll
            for (int i = 0; i < 4; ++i){
                float2 b2 = *(const float2*)(ba + c*128 + ncol0 + i*8 + qcol);
                h_acc[i][0] = b2.x; h_acc[i][1] = b2.y;
                h_acc[i][2] = b2.x; h_acc[i][3] = b2.y;
            }
            gemm_warp<2>(su, N_AH, N_AL, N_BH, N_BL, a_rbase, a_rx, a_k8, b_nin, b_k8, ncol0, h_acc);
            // gelu + split into H tiles
            #pragma unroll
            for (int i = 0; i < 4; ++i){
                int n = ncol0 + i*8 + qcol;
                float g0 = gelu_f(h_acc[i][0]), g1 = gelu_f(h_acc[i][1]);
                float g2v = gelu_f(h_acc[i][2]), g3v = gelu_f(h_acc[i][3]);
                uint32_t hA, lA, hB, lB;
                split_pair(g0, g1, hA, lA);
                split_pair(g2v, g3v, hB, lB);
                uint32_t offA = sw_off(rowA, n), offB = sw_off(rowB, n);
                *(uint32_t*)(smc + N_HH + offA) = hA;
                *(uint32_t*)(smc + N_HL + offA) = lA;
                *(uint32_t*)(smc + N_HH + offB) = hB;
                *(uint32_t*)(smc + N_HL + offB) = lB;
            }
            __syncthreads();
            {
                const uint4* sH = (const uint4*)(imgP + (size_t)c*32768);
                const uint4* sL = sH + 2048;
                uint4* dH = (uint4*)(smc + N_BH);
                uint4* dL = (uint4*)(smc + N_BL);
                #pragma unroll
                for (int i = 0; i < 8; ++i){ dH[t + i*256] = sH[t + i*256]; dL[t + i*256] = sL[t + i*256]; }
            }
            __syncthreads();
            gemm_warp<2>(su, N_HH, N_HL, N_BH, N_BL, a_rbase, a_rx, a_k8, b_nin, b_k8, ncol0, out_acc);
        }
        // ---- epilogue: residual + LN + mask -> outV, g_hV2 -----------------
        __syncthreads();
        float* scr = (float*)(smc + N_SCR);   // [32][132]
        #pragma unroll
        for (int i = 0; i < 4; ++i){
            int n = ncol0 + i*8 + qcol;
            float2 rA = *(const float2*)(src + (size_t)(r0g + rowA)*128 + n);
            float2 rB = *(const float2*)(src + (size_t)(r0g + rowB)*128 + n);
            scr[rowA*132 + n]     = rA.x + out_acc[i][0];
            scr[rowA*132 + n + 1] = rA.y + out_acc[i][1];
            scr[rowB*132 + n]     = rB.x + out_acc[i][2];
            scr[rowB*132 + n + 1] = rB.y + out_acc[i][3];
        }
        __syncthreads();
        #pragma unroll 1
        for (int r8 = 0; r8 < 4; ++r8){
            int r = w*4 + r8;
            int node = r0g + r;
            float x0 = scr[r*132 + lane],      x1 = scr[r*132 + lane + 32];
            float x2 = scr[r*132 + lane + 64], x3 = scr[r*132 + lane + 96];
            float s = warp_sum(x0 + x1 + x2 + x3);
            float q = warp_sum(x0*x0 + x1*x1 + x2*x2 + x3*x3);
            float mean = s * 0.0078125f;
            float var  = q * 0.0078125f - mean*mean;
            float rs = rsqrtf(var + EPSf);
            float mv = maskV[node];
            float y0 = mv*(gam[lane]     *(x0 - mean)*rs + bet[lane]);
            float y1 = mv*(gam[lane + 32]*(x1 - mean)*rs + bet[lane + 32]);
            float y2 = mv*(gam[lane + 64]*(x2 - mean)*rs + bet[lane + 64]);
            float y3 = mv*(gam[lane + 96]*(x3 - mean)*rs + bet[lane + 96]);
            float* o = outV + (size_t)node*128;
            o[lane] = y0; o[lane+32] = y1; o[lane+64] = y2; o[lane+96] = y3;
            float* g = g_hV2 + (size_t)node*128;
            g[lane] = y0; g[lane+32] = y1; g[lane+64] = y2; g[lane+96] = y3;
        }
    }
}

// ======================= edge pass: 4 nodes (192 rows) per CTA ==============
#define EDGE_SMEM 164864
#define E_AH 1024u
#define E_AL 50176u
#define E_BH 99328u
#define E_BL 132096u

template<int MODE>
__global__ void __launch_bounds__(384) edge_mma(
    const float* __restrict__ hE,
    const int*   __restrict__ Eidx,
    const float* __restrict__ maskA,
    const __nv_bfloat16* __restrict__ Wimg,   // 3 layer slots x 32768 bf16
    const float* __restrict__ bb, const float* __restrict__ bc,
    const float* __restrict__ residV,
    const float* __restrict__ gam, const float* __restrict__ bet,
    float* __restrict__ outp)                 // MODE0: g_hV1 ; MODE1: outE
{
    extern __shared__ char smc[];
    const uint32_t su = smem_u32(smc);
    int*   sidx = (int*)smc;                  // 192 ints
    float* s_s  = (float*)(smc + 768);        // [4][4]
    float* s_q  = (float*)(smc + 832);        // [4][4]

    const int t = threadIdx.x, lane = t & 31, wid = t >> 5;
    const int blk = blockIdx.x, node0 = blk*4;
    const int nbase = (node0 >> 11) << 11;

    if (t < 192) sidx[t] = Eidx[(size_t)blk*192 + t];

    // ---- stage A (h_E, 192 rows split) + B layer 0 -------------------------
    for (int c = t; c < 3072; c += 384){
        int row = c >> 4, k0 = (c & 15) << 3;
        const float4* s = (const float4*)(hE + ((size_t)blk*192 + row)*128 + k0);
        float4 v0 = s[0], v1 = s[1];
        union { uint32_t u[4]; uint4 q; } H, L;
        split_pair(v0.x, v0.y, H.u[0], L.u[0]);
        split_pair(v0.z, v0.w, H.u[1], L.u[1]);
        split_pair(v1.x, v1.y, H.u[2], L.u[2]);
        split_pair(v1.z, v1.w, H.u[3], L.u[3]);
        uint32_t off = (uint32_t)(row*256 + (((k0 >> 3) ^ (row & 7)) << 4));
        *(uint4*)(smc + E_AH + off) = H.q;
        *(uint4*)(smc + E_AL + off) = L.q;
    }
    {
        const uint4* sH = (const uint4*)Wimg;
        const uint4* sL = sH + 2048;
        uint4* dH = (uint4*)(smc + E_BH);
        uint4* dL = (uint4*)(smc + E_BL);
        for (int i = t; i < 2048; i += 384){ dH[i] = sH[i]; dL[i] = sL[i]; }
    }
    __syncthreads();

    // warp geometry (warp covers 16 rows x all 128 cols)
    const int m0 = wid*16;
    const int qrow = lane >> 2, qcol = (lane & 3)*2;
    const int rowA = m0 + qrow, rowB = rowA + 8;
    const int sel = lane >> 3, la7 = lane & 7;
    const int a_row = m0 + la7 + ((sel & 1) << 3);
    const uint32_t a_rbase = (uint32_t)(a_row*256);
    const uint32_t a_rx = (uint32_t)(a_row & 7);
    const int a_k8 = sel >> 1;
    const int b_nin = la7 + ((sel >> 1) << 3);
    const int b_k8 = sel & 1;

    float acc[16][4];

    #pragma unroll 1
    for (int l = 0; l < 3; ++l){
        // ---- init accumulators ---------------------------------------------
        if (l == 0){
            const float* qA = g_Q + (size_t)(node0 + rowA/48)*128;
            const float* pA = g_P + (size_t)(nbase + sidx[rowA])*128;
            const float* qB = g_Q + (size_t)(node0 + rowB/48)*128;
            const float* pB = g_P + (size_t)(nbase + sidx[rowB])*128;
            #pragma unroll
            for (int i = 0; i < 16; ++i){
                int n = i*8 + qcol;
                float2 q0 = *(const float2*)(qA + n), p0 = *(const float2*)(pA + n);
                float2 q1 = *(const float2*)(qB + n), p1 = *(const float2*)(pB + n);
                acc[i][0] = q0.x + p0.x; acc[i][1] = q0.y + p0.y;
                acc[i][2] = q1.x + p1.x; acc[i][3] = q1.y + p1.y;
            }
        } else {
            const float* bias = (l == 1) ? bb : bc;
            #pragma unroll
            for (int i = 0; i < 16; ++i){
                float2 b2 = *(const float2*)(bias + i*8 + qcol);
                acc[i][0] = b2.x; acc[i][1] = b2.y;
                acc[i][2] = b2.x; acc[i][3] = b2.y;
            }
        }

        gemm_warp<8>(su, E_AH, E_AL, E_BH, E_BL, a_rbase, a_rx, a_k8, b_nin, b_k8, 0, acc);

        if (l < 2){
            __syncthreads();     // all A/B reads done before overwrite
            #pragma unroll
            for (int i = 0; i < 16; ++i){
                int n = i*8 + qcol;
                float g0 = gelu_f(acc[i][0]), g1 = gelu_f(acc[i][1]);
                float g2v = gelu_f(acc[i][2]), g3v = gelu_f(acc[i][3]);
                uint32_t hA, lA, hB, lB;
                split_pair(g0, g1, hA, lA);
                split_pair(g2v, g3v, hB, lB);
                uint32_t offA = sw_off(rowA, n), offB = sw_off(rowB, n);
                *(uint32_t*)(smc + E_AH + offA) = hA;
                *(uint32_t*)(smc + E_AL + offA) = lA;
                *(uint32_t*)(smc + E_AH + offB) = hB;
                *(uint32_t*)(smc + E_AL + offB) = lB;
            }
            {
                const uint4* sH = (const uint4*)(Wimg + (size_t)(l + 1)*32768);
                const uint4* sL = sH + 2048;
                uint4* dH = (uint4*)(smc + E_BH);
                uint4* dL = (uint4*)(smc + E_BL);
                for (int i = t; i < 2048; i += 384){ dH[i] = sH[i]; dL[i] = sL[i]; }
            }
            __syncthreads();
        }
    }

    // ======================= final epilogue ================================
    if (MODE == 0){
        __syncthreads();                       // B reads done; reuse as scratch
        float* part = (float*)(smc + E_BH);    // [12][132]
        float* xs   = (float*)(smc + E_BH + 8192);  // [512]
        float mA = maskA[(size_t)blk*192 + rowA];
        float mB = maskA[(size_t)blk*192 + rowB];
        #pragma unroll
        for (int i = 0; i < 16; ++i){
            float p0 = mA*acc[i][0] + mB*acc[i][2];
            float p1 = mA*acc[i][1] + mB*acc[i][3];
            #pragma unroll
            for (int o = 4; o <= 16; o <<= 1){
                p0 += __shfl_xor_sync(0xffffffffu, p0, o);
                p1 += __shfl_xor_sync(0xffffffffu, p1, o);
            }
            if (lane < 4){
                part[wid*132 + i*8 + qcol]     = p0;
                part[wid*132 + i*8 + qcol + 1] = p1;
            }
        }
        __syncthreads();
        for (int idx = t; idx < 512; idx += 384){
            int nl = idx >> 7, c = idx & 127;
            float s = part[(nl*3+0)*132 + c] + part[(nl*3+1)*132 + c] + part[(nl*3+2)*132 + c];
            float xv = residV[(size_t)(node0 + nl)*128 + c] + s * INV_SCALE;
            xs[idx] = xv;
            float ws = warp_sum(xv), wq = warp_sum(xv*xv);
            if (lane == 0){ s_s[nl*4 + ((idx >> 5) & 3)] = ws; s_q[nl*4 + ((idx >> 5) & 3)] = wq; }
        }
        __syncthreads();
        for (int idx = t; idx < 512; idx += 384){
            int nl = idx >> 7, c = idx & 127;
            float mean = (s_s[nl*4] + s_s[nl*4+1] + s_s[nl*4+2] + s_s[nl*4+3]) * 0.0078125f;
            float var  = (s_q[nl*4] + s_q[nl*4+1] + s_q[nl*4+2] + s_q[nl*4+3]) * 0.0078125f - mean*mean;
            outp[(size_t)(node0 + nl)*128 + c] =
                gam[c]*(xs[idx] - mean)*rsqrtf(var + EPSf) + bet[c];
        }
    } else {
        // per-edge LN(h_E + msg) -> outp
        float sA = 0.f, qA = 0.f, sB = 0.f, qB = 0.f;
        const float* eA = hE + ((size_t)blk*192 + rowA)*128;
        const float* eB = hE + ((size_t)blk*192 + rowB)*128;
        #pragma unroll
        for (int i = 0; i < 16; ++i){
            int n = i*8 + qcol;
            float2 e0 = *(const float2*)(eA + n);
            float2 e1 = *(const float2*)(eB + n);
            float v0 = e0.x + acc[i][0], v1 = e0.y + acc[i][1];
            float v2 = e1.x + acc[i][2], v3 = e1.y + acc[i][3];
            acc[i][0] = v0; acc[i][1] = v1; acc[i][2] = v2; acc[i][3] = v3;
            sA += v0 + v1; qA += v0*v0 + v1*v1;
            sB += v2 + v3; qB += v2*v2 + v3*v3;
        }
        sA += __shfl_xor_sync(0xffffffffu, sA, 1); sA += __shfl_xor_sync(0xffffffffu, sA, 2);
        qA += __shfl_xor_sync(0xffffffffu, qA, 1); qA += __shfl_xor_sync(0xffffffffu, qA, 2);
        sB += __shfl_xor_sync(0xffffffffu, sB, 1); sB += __shfl_xor_sync(0xffffffffu, sB, 2);
        qB += __shfl_xor_sync(0xffffffffu, qB, 1); qB += __shfl_xor_sync(0xffffffffu, qB, 2);
        {
            float meanA = sA * 0.0078125f;
            float varA  = qA * 0.0078125f - meanA*meanA;
            float rsA   = rsqrtf(varA + EPSf);
            float meanB = sB * 0.0078125f;
            float varB  = qB * 0.0078125f - meanB*meanB;
            float rsB   = rsqrtf(varB + EPSf);
            float* oA = outp + ((size_t)blk*192 + rowA)*128;
            float* oB = outp + ((size_t)blk*192 + rowB)*128;
            #pragma unroll
            for (int i = 0; i < 16; ++i){
                int n = i*8 + qcol;
                float2 g = *(const float2*)(gam + n);
                float2 b = *(const float2*)(bet + n);
                float2 o0, o1;
                o0.x = g.x*(acc[i][0] - meanA)*rsA + b.x;
                o0.y = g.y*(acc[i][1] - meanA)*rsA + b.y;
                o1.x = g.x*(acc[i][2] - meanB)*rsB + b.x;
                o1.y = g.y*(acc[i][3] - meanB)*rsB + b.y;
                *(float2*)(oA + n) = o0;
                *(float2*)(oB + n) = o1;
            }
        }
    }
}

// ---------------------------------------------------------------------------
extern "C" void kernel_launch(void* const* d_in, const int* in_sizes, int n_in,
                              void* d_out, int out_size)
{
    const float* hV    = (const float*)d_in[0];
    const float* hE    = (const float*)d_in[1];
    const int*   Eidx  = (const int*)  d_in[2];
    const float* maskV = (const float*)d_in[3];
    const float* maskA = (const float*)d_in[4];
    const float* W1w   = (const float*)d_in[5];  const float* W1b  = (const float*)d_in[6];
    const float* W2w   = (const float*)d_in[7];  const float* W2b  = (const float*)d_in[8];
    const float* W3w   = (const float*)d_in[9];  const float* W3b  = (const float*)d_in[10];
    const float* W11w  = (const float*)d_in[11]; const float* W11b = (const float*)d_in[12];
    const float* W12w  = (const float*)d_in[13]; const float* W12b = (const float*)d_in[14];
    const float* W13w  = (const float*)d_in[15]; const float* W13b = (const float*)d_in[16];
    const float* Winw  = (const float*)d_in[17]; const float* Winb = (const float*)d_in[18];
    const float* Woutw = (const float*)d_in[19]; const float* Woutb= (const float*)d_in[20];
    const float* g1    = (const float*)d_in[21]; const float* b1   = (const float*)d_in[22];
    const float* g2    = (const float*)d_in[23]; const float* b2   = (const float*)d_in[24];
    const float* g3    = (const float*)d_in[25]; const float* b3   = (const float*)d_in[26];

    float* out  = (float*)d_out;
    float* outV = out;
    float* outE = out + (size_t)NODES*Cc;

    float* hV1p; cudaGetSymbolAddress((void**)&hV1p, g_hV1);
    float* hV2p; cudaGetSymbolAddress((void**)&hV2p, g_hV2);
    float* gQp;  cudaGetSymbolAddress((void**)&gQp,  g_Q);
    float* gPp;  cudaGetSymbolAddress((void**)&gPp,  g_P);
    __nv_bfloat16* wimg; cudaGetSymbolAddress((void**)&wimg, g_Wimg);

    cudaFuncSetAttribute(prep_w,      cudaFuncAttributeMaxDynamicSharedMemorySize, 65536);
    cudaFuncSetAttribute(node_mma<0>, cudaFuncAttributeMaxDynamicSharedMemorySize, NODE_SMEM);
    cudaFuncSetAttribute(node_mma<1>, cudaFuncAttributeMaxDynamicSharedMemorySize, NODE_SMEM);
    cudaFuncSetAttribute(edge_mma<0>, cudaFuncAttributeMaxDynamicSharedMemorySize, EDGE_SMEM);
    cudaFuncSetAttribute(edge_mma<1>, cudaFuncAttributeMaxDynamicSharedMemorySize, EDGE_SMEM);

    prep_w<<<18, 256, 65536>>>(W1w, W2w, W3w, W11w, W12w, W13w, Winw, Woutw);

    // pass 1: node message
    node_mma<0><<<NODES/32, 256, NODE_SMEM>>>(
        hV, wimg + (size_t)6*32768, wimg + (size_t)7*32768,
        W1b, nullptr, nullptr, nullptr, nullptr, gQp, gPp, nullptr);
    edge_mma<0><<<NODES/4, 384, EDGE_SMEM>>>(
        hE, Eidx, maskA, wimg, W2b, W3b, hV, g1, b1, hV1p);

    // FFN + LN2 + mask
    node_mma<1><<<NODES/32, 256, NODE_SMEM>>>(
        hV1p, wimg + (size_t)10*32768, wimg + (size_t)14*32768,
        Winb, Woutb, g2, b2, maskV, nullptr, nullptr, outV);

    // pass 2: edge update
    node_mma<0><<<NODES/32, 256, NODE_SMEM>>>(
        hV2p, wimg + (size_t)8*32768, wimg + (size_t)9*32768,
        W11b, nullptr, nullptr, nullptr, nullptr, gQp, gPp, nullptr);
    edge_mma<1><<<NODES/4, 384, EDGE_SMEM>>>(
        hE, Eidx, maskA, wimg + (size_t)3*32768, W12b, W13b, hE, g3, b3, outE);
}

// round 9
// speedup vs baseline: 3.7044x; 1.0455x over previous
#include <cuda_runtime.h>
#include <cuda_bf16.h>
#include <math.h>
#include <stdint.h>

#define Bb 2
#define Nn 2048
#define Kk 48
#define Cc 128
#define NODES (Bb*Nn)          /* 4096 */
#define EPSf 1e-5f
#define INV_SCALE (1.0f/30.0f)

// device scratch (no allocations allowed)
__device__ float g_hV1[NODES*Cc];
__device__ float g_hV2[NODES*Cc];
__device__ float g_P[NODES*Cc];
__device__ float g_Q[NODES*Cc];
__device__ __nv_bfloat16 g_Wimg[18*32768];   // 18 images x (hi 16384 + lo 16384)

// ---------------- helpers ---------------------------------------------------
static __device__ __forceinline__ float gelu_f(float x){
    return 0.5f * x * (1.0f + erff(x * 0.70710678118654752440f));
}
static __device__ __forceinline__ float warp_sum(float v){
    #pragma unroll
    for (int o = 16; o; o >>= 1) v += __shfl_xor_sync(0xffffffffu, v, o);
    return v;
}
static __device__ __forceinline__ uint32_t smem_u32(const void* p){
    uint32_t a;
    asm("{ .reg .u64 t; cvta.to.shared.u64 t, %1; cvt.u32.u64 %0, t; }" : "=r"(a) : "l"(p));
    return a;
}
static __device__ __forceinline__ void ldsm4(uint32_t* r, uint32_t addr){
    asm volatile("ldmatrix.sync.aligned.m8n8.x4.shared.b16 {%0,%1,%2,%3}, [%4];"
        : "=r"(r[0]), "=r"(r[1]), "=r"(r[2]), "=r"(r[3]) : "r"(addr));
}
static __device__ __forceinline__ void mma16816(float* c, const uint32_t* a, uint32_t b0, uint32_t b1){
    asm volatile("mma.sync.aligned.m16n8k16.row.col.f32.bf16.bf16.f32 "
        "{%0,%1,%2,%3},{%4,%5,%6,%7},{%8,%9},{%0,%1,%2,%3};"
        : "+f"(c[0]), "+f"(c[1]), "+f"(c[2]), "+f"(c[3])
        : "r"(a[0]), "r"(a[1]), "r"(a[2]), "r"(a[3]), "r"(b0), "r"(b1));
}
// swizzled byte offset inside a [rows x 128 bf16] tile (256B rows, 16B xor)
static __device__ __forceinline__ uint32_t sw_off(int row, int k){
    return (uint32_t)(row*256 + ((((k >> 3) ^ (row & 7))) << 4) + (k & 7)*2);
}
static __device__ __forceinline__ uint32_t pack_bf(float a, float b){
    __nv_bfloat162 h = __floats2bfloat162_rn(a, b);
    return *reinterpret_cast<uint32_t*>(&h);
}
static __device__ __forceinline__ void split_pair(float a, float b, uint32_t &hi, uint32_t &lo){
    __nv_bfloat16 ha = __float2bfloat16(a);
    __nv_bfloat16 hb = __float2bfloat16(b);
    __nv_bfloat162 H; H.x = ha; H.y = hb;
    hi = *reinterpret_cast<uint32_t*>(&H);
    lo = pack_bf(a - __bfloat162float(ha), b - __bfloat162float(hb));
}

// templated warp GEMM: 16 rows x (NP*16) cols, K=128, 3 split terms.
template<int NP>
static __device__ __forceinline__ void gemm_warp(
    uint32_t su, uint32_t offAH, uint32_t offAL, uint32_t offBH, uint32_t offBL,
    uint32_t a_rbase, uint32_t a_rx, int a_k8, int b_nin, int b_k8, int ncol0,
    float (*acc)[4])
{
    #pragma unroll 1
    for (int ks = 0; ks < 8; ++ks){
        uint32_t ah[4], al[4];
        uint32_t ak3 = (uint32_t)(ks*2 + a_k8);
        uint32_t aoff = a_rbase + ((ak3 ^ a_rx) << 4);
        ldsm4(ah, su + offAH + aoff);
        ldsm4(al, su + offAL + aoff);
        uint32_t bk3 = (uint32_t)(ks*2 + b_k8);
        uint32_t boffs[NP];
        #pragma unroll
        for (int np = 0; np < NP; ++np){
            int brow = ncol0 + np*16 + b_nin;
            boffs[np] = (uint32_t)(brow*256) + ((bk3 ^ (uint32_t)(brow & 7)) << 4);
        }
        uint32_t bfr[NP][4];
        // sweep 1: ah x bh
        #pragma unroll
        for (int np = 0; np < NP; ++np) ldsm4(bfr[np], su + offBH + boffs[np]);
        #pragma unroll
        for (int np = 0; np < NP; ++np){
            mma16816(acc[2*np],   ah, bfr[np][0], bfr[np][1]);
            mma16816(acc[2*np+1], ah, bfr[np][2], bfr[np][3]);
        }
        // sweep 2: ah x bl
        #pragma unroll
        for (int np = 0; np < NP; ++np) ldsm4(bfr[np], su + offBL + boffs[np]);
        #pragma unroll
        for (int np = 0; np < NP; ++np){
            mma16816(acc[2*np],   ah, bfr[np][0], bfr[np][1]);
            mma16816(acc[2*np+1], ah, bfr[np][2], bfr[np][3]);
        }
        // sweep 3: al x bh
        #pragma unroll
        for (int np = 0; np < NP; ++np) ldsm4(bfr[np], su + offBH + boffs[np]);
        #pragma unroll
        for (int np = 0; np < NP; ++np){
            mma16816(acc[2*np],   al, bfr[np][0], bfr[np][1]);
            mma16816(acc[2*np+1], al, bfr[np][2], bfr[np][3]);
        }
    }
}

// ===================== weight prep: 18 transposed split images ==============
__global__ void __launch_bounds__(256) prep_w(
    const float* __restrict__ W1w,  const float* __restrict__ W2w,
    const float* __restrict__ W3w,  const float* __restrict__ W11w,
    const float* __restrict__ W12w, const float* __restrict__ W13w,
    const float* __restrict__ Winw, const float* __restrict__ Woutw)
{
    extern __shared__ float ws[];   // [128][128]
    const int b = blockIdx.x;
    const float* ptr; int ld = 128;
    switch (b){
        case 0: ptr = W1w + 128*128; break;
        case 1: ptr = W2w;  break;
        case 2: ptr = W3w;  break;
        case 3: ptr = W11w + 128*128; break;
        case 4: ptr = W12w; break;
        case 5: ptr = W13w; break;
        case 6: ptr = W1w;  break;
        case 7: ptr = W1w + 256*128; break;
        case 8: ptr = W11w; break;
        case 9: ptr = W11w + 256*128; break;
        case 10: case 11: case 12: case 13:
            ptr = Winw + (b - 10)*128; ld = 512; break;
        default: // 14..17
            ptr = Woutw + (size_t)(b - 14)*128*128; break;
    }
    const int t = threadIdx.x;
    for (int idx = t; idx < 4096; idx += 256){
        int k = idx >> 5, n4 = (idx & 31)*4;
        *(float4*)(ws + k*128 + n4) = *(const float4*)(ptr + (size_t)k*ld + n4);
    }
    __syncthreads();

    __nv_bfloat16* hi = g_Wimg + (size_t)b * 32768;
    __nv_bfloat16* lo = hi + 16384;
    for (int c = t; c < 2048; c += 256){
        int row = c >> 4;            // n
        int k0  = (c & 15) << 3;     // k
        union { uint32_t u[4]; uint4 q; } H, L;
        #pragma unroll
        for (int j = 0; j < 4; ++j){
            float w0 = ws[(k0 + 2*j    )*128 + row];
            float w1 = ws[(k0 + 2*j + 1)*128 + row];
            split_pair(w0, w1, H.u[j], L.u[j]);
        }
        uint32_t off = (uint32_t)(row*256 + (((k0 >> 3) ^ (row & 7)) << 4));
        *(uint4*)((char*)hi + off) = H.q;
        *(uint4*)((char*)lo + off) = L.q;
    }
}

// ===================== node kernel: PQ (MODE 0) / FFN (MODE 1) ==============
// 16 rows per CTA, 128 threads (4 warps: warp = 16 rows x 32 cols, NP=2)
// 2 CTAs / SM.
#define NODE_SMEM 90368
#define N_AH 0u
#define N_AL 4096u
#define N_HH 8192u
#define N_HL 12288u
#define N_BH 16384u
#define N_BL 49152u
#define N_SCR 81920u

template<int MODE>
__global__ void __launch_bounds__(128, 2) node_mma(
    const float* __restrict__ src,            // PQ: nodes ; FFN: g_hV1
    const __nv_bfloat16* __restrict__ imgQ,   // PQ: Wq img ; FFN: WinT chunk base
    const __nv_bfloat16* __restrict__ imgP,   // PQ: Wp img ; FFN: WoutT chunk base
    const float* __restrict__ ba,             // PQ: W1b ; FFN: bin
    const float* __restrict__ bout,
    const float* __restrict__ gam, const float* __restrict__ bet,
    const float* __restrict__ maskV,
    float* __restrict__ outQ, float* __restrict__ outP,   // PQ outputs
    float* __restrict__ outV)                              // FFN output
{
    extern __shared__ char smc[];
    const uint32_t su = smem_u32(smc);
    const int t = threadIdx.x, lane = t & 31, w = t >> 5;
    const int blk = blockIdx.x;
    const int r0g = blk*16;

    // warp geometry: 4 warps = 4 col-groups of 32, all covering rows 0..15
    const int ncol0 = w*32;
    const int qrow = lane >> 2, qcol = (lane & 3)*2;
    const int rowA = qrow, rowB = rowA + 8;
    const int sel = lane >> 3, la7 = lane & 7;
    const int a_row = la7 + ((sel & 1) << 3);
    const uint32_t a_rbase = (uint32_t)(a_row*256);
    const uint32_t a_rx = (uint32_t)(a_row & 7);
    const int a_k8 = sel >> 1;
    const int b_nin = la7 + ((sel >> 1) << 3);
    const int b_k8 = sel & 1;

    // ---- stage A (16 rows of src, split) -----------------------------------
    for (int c = t; c < 256; c += 128){
        int row = c >> 4, k0 = (c & 15) << 3;
        const float4* s = (const float4*)(src + (size_t)(r0g + row)*128 + k0);
        float4 v0 = s[0], v1 = s[1];
        union { uint32_t u[4]; uint4 q; } H, L;
        split_pair(v0.x, v0.y, H.u[0], L.u[0]);
        split_pair(v0.z, v0.w, H.u[1], L.u[1]);
        split_pair(v1.x, v1.y, H.u[2], L.u[2]);
        split_pair(v1.z, v1.w, H.u[3], L.u[3]);
        uint32_t off = (uint32_t)(row*256 + (((k0 >> 3) ^ (row & 7)) << 4));
        *(uint4*)(smc + N_AH + off) = H.q;
        *(uint4*)(smc + N_AL + off) = L.q;
    }

    if (MODE == 0){
        // ------------------- PQ: two GEMMs ----------------------------------
        #pragma unroll 1
        for (int m = 0; m < 2; ++m){
            __syncthreads();
            const __nv_bfloat16* img = m ? imgP : imgQ;
            {
                const uint4* sH = (const uint4*)img;
                const uint4* sL = sH + 2048;
                uint4* dH = (uint4*)(smc + N_BH);
                uint4* dL = (uint4*)(smc + N_BL);
                #pragma unroll
                for (int i = 0; i < 16; ++i){ dH[t + i*128] = sH[t + i*128]; dL[t + i*128] = sL[t + i*128]; }
            }
            __syncthreads();
            float acc[4][4];
            #pragma unroll
            for (int i = 0; i < 4; ++i){
                if (m == 0){
                    float2 b2 = *(const float2*)(ba + ncol0 + i*8 + qcol);
                    acc[i][0] = b2.x; acc[i][1] = b2.y; acc[i][2] = b2.x; acc[i][3] = b2.y;
                } else {
                    acc[i][0] = acc[i][1] = acc[i][2] = acc[i][3] = 0.f;
                }
            }
            gemm_warp<2>(su, N_AH, N_AL, N_BH, N_BL, a_rbase, a_rx, a_k8, b_nin, b_k8, ncol0, acc);
            float* dst = m ? outP : outQ;
            #pragma unroll
            for (int i = 0; i < 4; ++i){
                int n = ncol0 + i*8 + qcol;
                *(float2*)(dst + (size_t)(r0g + rowA)*128 + n) = make_float2(acc[i][0], acc[i][1]);
                *(float2*)(dst + (size_t)(r0g + rowB)*128 + n) = make_float2(acc[i][2], acc[i][3]);
            }
        }
    } else {
        // ------------------- FFN: 4 chunks of hidden ------------------------
        float out_acc[4][4];
        #pragma unroll
        for (int i = 0; i < 4; ++i){
            float2 b2 = *(const float2*)(bout + ncol0 + i*8 + qcol);
            out_acc[i][0] = b2.x; out_acc[i][1] = b2.y;
            out_acc[i][2] = b2.x; out_acc[i][3] = b2.y;
        }
        #pragma unroll 1
        for (int c = 0; c < 4; ++c){
            __syncthreads();
            {
                const uint4* sH = (const uint4*)(imgQ + (size_t)c*32768);
                const uint4* sL = sH + 2048;
                uint4* dH = (uint4*)(smc + N_BH);
                uint4* dL = (uint4*)(smc + N_BL);
                #pragma unroll
                for (int i = 0; i < 16; ++i){ dH[t + i*128] = sH[t + i*128]; dL[t + i*128] = sL[t + i*128]; }
            }
            __syncthreads();
            float h_acc[4][4];
            #pragma unroll
            for (int i = 0; i < 4; ++i){
                float2 b2 = *(const float2*)(ba + c*128 + ncol0 + i*8 + qcol);
                h_acc[i][0] = b2.x; h_acc[i][1] = b2.y;
                h_acc[i][2] = b2.x; h_acc[i][3] = b2.y;
            }
            gemm_warp<2>(su, N_AH, N_AL, N_BH, N_BL, a_rbase, a_rx, a_k8, b_nin, b_k8, ncol0, h_acc);
            // gelu + split into H tiles
            #pragma unroll
            for (int i = 0; i < 4; ++i){
                int n = ncol0 + i*8 + qcol;
                float g0 = gelu_f(h_acc[i][0]), g1 = gelu_f(h_acc[i][1]);
                float g2v = gelu_f(h_acc[i][2]), g3v = gelu_f(h_acc[i][3]);
                uint32_t hA, lA, hB, lB;
                split_pair(g0, g1, hA, lA);
                split_pair(g2v, g3v, hB, lB);
                uint32_t offA = sw_off(rowA, n), offB = sw_off(rowB, n);
                *(uint32_t*)(smc + N_HH + offA) = hA;
                *(uint32_t*)(smc + N_HL + offA) = lA;
                *(uint32_t*)(smc + N_HH + offB) = hB;
                *(uint32_t*)(smc + N_HL + offB) = lB;
            }
            __syncthreads();
            {
                const uint4* sH = (const uint4*)(imgP + (size_t)c*32768);
                const uint4* sL = sH + 2048;
                uint4* dH = (uint4*)(smc + N_BH);
                uint4* dL = (uint4*)(smc + N_BL);
                #pragma unroll
                for (int i = 0; i < 16; ++i){ dH[t + i*128] = sH[t + i*128]; dL[t + i*128] = sL[t + i*128]; }
            }
            __syncthreads();
            gemm_warp<2>(su, N_HH, N_HL, N_BH, N_BL, a_rbase, a_rx, a_k8, b_nin, b_k8, ncol0, out_acc);
        }
        // ---- epilogue: residual + LN + mask -> outV, g_hV2 -----------------
        __syncthreads();
        float* scr = (float*)(smc + N_SCR);   // [16][132]
        #pragma unroll
        for (int i = 0; i < 4; ++i){
            int n = ncol0 + i*8 + qcol;
            float2 rA = *(const float2*)(src + (size_t)(r0g + rowA)*128 + n);
            float2 rB = *(const float2*)(src + (size_t)(r0g + rowB)*128 + n);
            scr[rowA*132 + n]     = rA.x + out_acc[i][0];
            scr[rowA*132 + n + 1] = rA.y + out_acc[i][1];
            scr[rowB*132 + n]     = rB.x + out_acc[i][2];
            scr[rowB*132 + n + 1] = rB.y + out_acc[i][3];
        }
        __syncthreads();
        #pragma unroll 1
        for (int r8 = 0; r8 < 4; ++r8){
            int r = w*4 + r8;
            int node = r0g + r;
            float x0 = scr[r*132 + lane],      x1 = scr[r*132 + lane + 32];
            float x2 = scr[r*132 + lane + 64], x3 = scr[r*132 + lane + 96];
            float s = warp_sum(x0 + x1 + x2 + x3);
            float q = warp_sum(x0*x0 + x1*x1 + x2*x2 + x3*x3);
            float mean = s * 0.0078125f;
            float var  = q * 0.0078125f - mean*mean;
            float rs = rsqrtf(var + EPSf);
            float mv = maskV[node];
            float y0 = mv*(gam[lane]     *(x0 - mean)*rs + bet[lane]);
            float y1 = mv*(gam[lane + 32]*(x1 - mean)*rs + bet[lane + 32]);
            float y2 = mv*(gam[lane + 64]*(x2 - mean)*rs + bet[lane + 64]);
            float y3 = mv*(gam[lane + 96]*(x3 - mean)*rs + bet[lane + 96]);
            float* o = outV + (size_t)node*128;
            o[lane] = y0; o[lane+32] = y1; o[lane+64] = y2; o[lane+96] = y3;
            float* g = g_hV2 + (size_t)node*128;
            g[lane] = y0; g[lane+32] = y1; g[lane+64] = y2; g[lane+96] = y3;
        }
    }
}

// ======================= edge pass: 2 nodes (96 rows) per CTA ===============
// 192 threads / 6 warps, 112.5KB smem -> 2 CTAs / SM.
#define EDGE_SMEM 115200
#define E_AH 512u
#define E_AL 25088u
#define E_BH 49664u
#define E_BL 82432u

template<int MODE>
__global__ void __launch_bounds__(192, 2) edge_mma(
    const float* __restrict__ hE,
    const int*   __restrict__ Eidx,
    const float* __restrict__ maskA,
    const __nv_bfloat16* __restrict__ Wimg,   // 3 layer slots x 32768 bf16
    const float* __restrict__ bb, const float* __restrict__ bc,
    const float* __restrict__ residV,
    const float* __restrict__ gam, const float* __restrict__ bet,
    float* __restrict__ outp)                 // MODE0: g_hV1 ; MODE1: outE
{
    extern __shared__ char smc[];
    const uint32_t su = smem_u32(smc);
    int*   sidx = (int*)smc;                  // 96 ints (384B)
    float* s_s  = (float*)(smc + 384);        // [2][4]
    float* s_q  = (float*)(smc + 416);        // [2][4]

    const int t = threadIdx.x, lane = t & 31, wid = t >> 5;
    const int blk = blockIdx.x, node0 = blk*2;
    const int nbase = (node0 >> 11) << 11;

    if (t < 96) sidx[t] = Eidx[(size_t)blk*96 + t];

    // ---- stage A (h_E, 96 rows split) + B layer 0 --------------------------
    for (int c = t; c < 1536; c += 192){
        int row = c >> 4, k0 = (c & 15) << 3;
        const float4* s = (const float4*)(hE + ((size_t)blk*96 + row)*128 + k0);
        float4 v0 = s[0], v1 = s[1];
        union { uint32_t u[4]; uint4 q; } H, L;
        split_pair(v0.x, v0.y, H.u[0], L.u[0]);
        split_pair(v0.z, v0.w, H.u[1], L.u[1]);
        split_pair(v1.x, v1.y, H.u[2], L.u[2]);
        split_pair(v1.z, v1.w, H.u[3], L.u[3]);
        uint32_t off = (uint32_t)(row*256 + (((k0 >> 3) ^ (row & 7)) << 4));
        *(uint4*)(smc + E_AH + off) = H.q;
        *(uint4*)(smc + E_AL + off) = L.q;
    }
    {
        const uint4* sH = (const uint4*)Wimg;
        const uint4* sL = sH + 2048;
        uint4* dH = (uint4*)(smc + E_BH);
        uint4* dL = (uint4*)(smc + E_BL);
        for (int i = t; i < 2048; i += 192){ dH[i] = sH[i]; dL[i] = sL[i]; }
    }
    __syncthreads();

    // warp geometry (warp covers 16 rows x all 128 cols)
    const int m0 = wid*16;
    const int qrow = lane >> 2, qcol = (lane & 3)*2;
    const int rowA = m0 + qrow, rowB = rowA + 8;
    const int sel = lane >> 3, la7 = lane & 7;
    const int a_row = m0 + la7 + ((sel & 1) << 3);
    const uint32_t a_rbase = (uint32_t)(a_row*256);
    const uint32_t a_rx = (uint32_t)(a_row & 7);
    const int a_k8 = sel >> 1;
    const int b_nin = la7 + ((sel >> 1) << 3);
    const int b_k8 = sel & 1;

    float acc[16][4];

    #pragma unroll 1
    for (int l = 0; l < 3; ++l){
        // ---- init accumulators ---------------------------------------------
        if (l == 0){
            const float* qA = g_Q + (size_t)(node0 + rowA/48)*128;
            const float* pA = g_P + (size_t)(nbase + sidx[rowA])*128;
            const float* qB = g_Q + (size_t)(node0 + rowB/48)*128;
            const float* pB = g_P + (size_t)(nbase + sidx[rowB])*128;
            #pragma unroll
            for (int i = 0; i < 16; ++i){
                int n = i*8 + qcol;
                float2 q0 = *(const float2*)(qA + n), p0 = *(const float2*)(pA + n);
                float2 q1 = *(const float2*)(qB + n), p1 = *(const float2*)(pB + n);
                acc[i][0] = q0.x + p0.x; acc[i][1] = q0.y + p0.y;
                acc[i][2] = q1.x + p1.x; acc[i][3] = q1.y + p1.y;
            }
        } else {
            const float* bias = (l == 1) ? bb : bc;
            #pragma unroll
            for (int i = 0; i < 16; ++i){
                float2 b2 = *(const float2*)(bias + i*8 + qcol);
                acc[i][0] = b2.x; acc[i][1] = b2.y;
                acc[i][2] = b2.x; acc[i][3] = b2.y;
            }
        }

        gemm_warp<8>(su, E_AH, E_AL, E_BH, E_BL, a_rbase, a_rx, a_k8, b_nin, b_k8, 0, acc);

        if (l < 2){
            __syncthreads();     // all A/B reads done before overwrite
            #pragma unroll
            for (int i = 0; i < 16; ++i){
                int n = i*8 + qcol;
                float g0 = gelu_f(acc[i][0]), g1 = gelu_f(acc[i][1]);
                float g2v = gelu_f(acc[i][2]), g3v = gelu_f(acc[i][3]);
                uint32_t hA, lA, hB, lB;
                split_pair(g0, g1, hA, lA);
                split_pair(g2v, g3v, hB, lB);
                uint32_t offA = sw_off(rowA, n), offB = sw_off(rowB, n);
                *(uint32_t*)(smc + E_AH + offA) = hA;
                *(uint32_t*)(smc + E_AL + offA) = lA;
                *(uint32_t*)(smc + E_AH + offB) = hB;
                *(uint32_t*)(smc + E_AL + offB) = lB;
            }
            {
                const uint4* sH = (const uint4*)(Wimg + (size_t)(l + 1)*32768);
                const uint4* sL = sH + 2048;
                uint4* dH = (uint4*)(smc + E_BH);
                uint4* dL = (uint4*)(smc + E_BL);
                for (int i = t; i < 2048; i += 192){ dH[i] = sH[i]; dL[i] = sL[i]; }
            }
            __syncthreads();
        }
    }

    // ======================= final epilogue ================================
    if (MODE == 0){
        __syncthreads();                       // B reads done; reuse as scratch
        float* part = (float*)(smc + E_BH);    // [6][132]
        float* xs   = (float*)(smc + E_BH + 4096);  // [256]
        float mA = maskA[(size_t)blk*96 + rowA];
        float mB = maskA[(size_t)blk*96 + rowB];
        #pragma unroll
        for (int i = 0; i < 16; ++i){
            float p0 = mA*acc[i][0] + mB*acc[i][2];
            float p1 = mA*acc[i][1] + mB*acc[i][3];
            #pragma unroll
            for (int o = 4; o <= 16; o <<= 1){
                p0 += __shfl_xor_sync(0xffffffffu, p0, o);
                p1 += __shfl_xor_sync(0xffffffffu, p1, o);
            }
            if (lane < 4){
                part[wid*132 + i*8 + qcol]     = p0;
                part[wid*132 + i*8 + qcol + 1] = p1;
            }
        }
        __syncthreads();
        for (int idx = t; idx < 256; idx += 192){
            int nl = idx >> 7, c = idx & 127;
            float s = part[(nl*3+0)*132 + c] + part[(nl*3+1)*132 + c] + part[(nl*3+2)*132 + c];
            float xv = residV[(size_t)(node0 + nl)*128 + c] + s * INV_SCALE;
            xs[idx] = xv;
            float ws = warp_sum(xv), wq = warp_sum(xv*xv);
            if (lane == 0){ s_s[nl*4 + ((idx >> 5) & 3)] = ws; s_q[nl*4 + ((idx >> 5) & 3)] = wq; }
        }
        __syncthreads();
        for (int idx = t; idx < 256; idx += 192){
            int nl = idx >> 7, c = idx & 127;
            float mean = (s_s[nl*4] + s_s[nl*4+1] + s_s[nl*4+2] + s_s[nl*4+3]) * 0.0078125f;
            float var  = (s_q[nl*4] + s_q[nl*4+1] + s_q[nl*4+2] + s_q[nl*4+3]) * 0.0078125f - mean*mean;
            outp[(size_t)(node0 + nl)*128 + c] =
                gam[c]*(xs[idx] - mean)*rsqrtf(var + EPSf) + bet[c];
        }
    } else {
        // per-edge LN(h_E + msg) -> outp
        float sA = 0.f, qA = 0.f, sB = 0.f, qB = 0.f;
        const float* eA = hE + ((size_t)blk*96 + rowA)*128;
        const float* eB = hE + ((size_t)blk*96 + rowB)*128;
        #pragma unroll
        for (int i = 0; i < 16; ++i){
            int n = i*8 + qcol;
            float2 e0 = *(const float2*)(eA + n);
            float2 e1 = *(const float2*)(eB + n);
            float v0 = e0.x + acc[i][0], v1 = e0.y + acc[i][1];
            float v2 = e1.x + acc[i][2], v3 = e1.y + acc[i][3];
            acc[i][0] = v0; acc[i][1] = v1; acc[i][2] = v2; acc[i][3] = v3;
            sA += v0 + v1; qA += v0*v0 + v1*v1;
            sB += v2 + v3; qB += v2*v2 + v3*v3;
        }
        sA += __shfl_xor_sync(0xffffffffu, sA, 1); sA += __shfl_xor_sync(0xffffffffu, sA, 2);
        qA += __shfl_xor_sync(0xffffffffu, qA, 1); qA += __shfl_xor_sync(0xffffffffu, qA, 2);
        sB += __shfl_xor_sync(0xffffffffu, sB, 1); sB += __shfl_xor_sync(0xffffffffu, sB, 2);
        qB += __shfl_xor_sync(0xffffffffu, qB, 1); qB += __shfl_xor_sync(0xffffffffu, qB, 2);
        {
            float meanA = sA * 0.0078125f;
            float varA  = qA * 0.0078125f - meanA*meanA;
            float rsA   = rsqrtf(varA + EPSf);
            float meanB = sB * 0.0078125f;
            float varB  = qB * 0.0078125f - meanB*meanB;
            float rsB   = rsqrtf(varB + EPSf);
            float* oA = outp + ((size_t)blk*96 + rowA)*128;
            float* oB = outp + ((size_t)blk*96 + rowB)*128;
            #pragma unroll
            for (int i = 0; i < 16; ++i){
                int n = i*8 + qcol;
                float2 g = *(const float2*)(gam + n);
                float2 b = *(const float2*)(bet + n);
                float2 o0, o1;
                o0.x = g.x*(acc[i][0] - meanA)*rsA + b.x;
                o0.y = g.y*(acc[i][1] - meanA)*rsA + b.y;
                o1.x = g.x*(acc[i][2] - meanB)*rsB + b.x;
                o1.y = g.y*(acc[i][3] - meanB)*rsB + b.y;
                *(float2*)(oA + n) = o0;
                *(float2*)(oB + n) = o1;
            }
        }
    }
}

// ---------------------------------------------------------------------------
extern "C" void kernel_launch(void* const* d_in, const int* in_sizes, int n_in,
                              void* d_out, int out_size)
{
    const float* hV    = (const float*)d_in[0];
    const float* hE    = (const float*)d_in[1];
    const int*   Eidx  = (const int*)  d_in[2];
    const float* maskV = (const float*)d_in[3];
    const float* maskA = (const float*)d_in[4];
    const float* W1w   = (const float*)d_in[5];  const float* W1b  = (const float*)d_in[6];
    const float* W2w   = (const float*)d_in[7];  const float* W2b  = (const float*)d_in[8];
    const float* W3w   = (const float*)d_in[9];  const float* W3b  = (const float*)d_in[10];
    const float* W11w  = (const float*)d_in[11]; const float* W11b = (const float*)d_in[12];
    const float* W12w  = (const float*)d_in[13]; const float* W12b = (const float*)d_in[14];
    const float* W13w  = (const float*)d_in[15]; const float* W13b = (const float*)d_in[16];
    const float* Winw  = (const float*)d_in[17]; const float* Winb = (const float*)d_in[18];
    const float* Woutw = (const float*)d_in[19]; const float* Woutb= (const float*)d_in[20];
    const float* g1    = (const float*)d_in[21]; const float* b1   = (const float*)d_in[22];
    const float* g2    = (const float*)d_in[23]; const float* b2   = (const float*)d_in[24];
    const float* g3    = (const float*)d_in[25]; const float* b3   = (const float*)d_in[26];

    float* out  = (float*)d_out;
    float* outV = out;
    float* outE = out + (size_t)NODES*Cc;

    float* hV1p; cudaGetSymbolAddress((void**)&hV1p, g_hV1);
    float* hV2p; cudaGetSymbolAddress((void**)&hV2p, g_hV2);
    float* gQp;  cudaGetSymbolAddress((void**)&gQp,  g_Q);
    float* gPp;  cudaGetSymbolAddress((void**)&gPp,  g_P);
    __nv_bfloat16* wimg; cudaGetSymbolAddress((void**)&wimg, g_Wimg);

    cudaFuncSetAttribute(prep_w,      cudaFuncAttributeMaxDynamicSharedMemorySize, 65536);
    cudaFuncSetAttribute(node_mma<0>, cudaFuncAttributeMaxDynamicSharedMemorySize, NODE_SMEM);
    cudaFuncSetAttribute(node_mma<1>, cudaFuncAttributeMaxDynamicSharedMemorySize, NODE_SMEM);
    cudaFuncSetAttribute(edge_mma<0>, cudaFuncAttributeMaxDynamicSharedMemorySize, EDGE_SMEM);
    cudaFuncSetAttribute(edge_mma<1>, cudaFuncAttributeMaxDynamicSharedMemorySize, EDGE_SMEM);

    prep_w<<<18, 256, 65536>>>(W1w, W2w, W3w, W11w, W12w, W13w, Winw, Woutw);

    // pass 1: node message
    node_mma<0><<<NODES/16, 128, NODE_SMEM>>>(
        hV, wimg + (size_t)6*32768, wimg + (size_t)7*32768,
        W1b, nullptr, nullptr, nullptr, nullptr, gQp, gPp, nullptr);
    edge_mma<0><<<NODES/2, 192, EDGE_SMEM>>>(
        hE, Eidx, maskA, wimg, W2b, W3b, hV, g1, b1, hV1p);

    // FFN + LN2 + mask
    node_mma<1><<<NODES/16, 128, NODE_SMEM>>>(
        hV1p, wimg + (size_t)10*32768, wimg + (size_t)14*32768,
        Winb, Woutb, g2, b2, maskV, nullptr, nullptr, outV);

    // pass 2: edge update
    node_mma<0><<<NODES/16, 128, NODE_SMEM>>>(
        hV2p, wimg + (size_t)8*32768, wimg + (size_t)9*32768,
        W11b, nullptr, nullptr, nullptr, nullptr, gQp, gPp, nullptr);
    edge_mma<1><<<NODES/2, 192, EDGE_SMEM>>>(
        hE, Eidx, maskA, wimg + (size_t)3*32768, W12b, W13b, hE, g3, b3, outE);
}

// round 11
// speedup vs baseline: 3.9313x; 1.0613x over previous
#include <cuda_runtime.h>
#include <cuda_bf16.h>
#include <math.h>
#include <stdint.h>

#define Bb 2
#define Nn 2048
#define Kk 48
#define Cc 128
#define NODES (Bb*Nn)          /* 4096 */
#define EPSf 1e-5f
#define INV_SCALE (1.0f/30.0f)

// device scratch (no allocations allowed)
__device__ float g_hV1[NODES*Cc];
__device__ float g_hV2[NODES*Cc];
__device__ float g_P[NODES*Cc];
__device__ float g_Q[NODES*Cc];
__device__ __nv_bfloat16 g_Wimg[18*32768];   // 18 images x (hi 16384 + lo 16384)

// ---------------- helpers ---------------------------------------------------
static __device__ __forceinline__ float gelu_f(float x){
    return 0.5f * x * (1.0f + erff(x * 0.70710678118654752440f));
}
static __device__ __forceinline__ float warp_sum(float v){
    #pragma unroll
    for (int o = 16; o; o >>= 1) v += __shfl_xor_sync(0xffffffffu, v, o);
    return v;
}
static __device__ __forceinline__ uint32_t smem_u32(const void* p){
    uint32_t a;
    asm("{ .reg .u64 t; cvta.to.shared.u64 t, %1; cvt.u32.u64 %0, t; }" : "=r"(a) : "l"(p));
    return a;
}
static __device__ __forceinline__ void ldsm4(uint32_t* r, uint32_t addr){
    asm volatile("ldmatrix.sync.aligned.m8n8.x4.shared.b16 {%0,%1,%2,%3}, [%4];"
        : "=r"(r[0]), "=r"(r[1]), "=r"(r[2]), "=r"(r[3]) : "r"(addr));
}
static __device__ __forceinline__ void mma16816(float* c, const uint32_t* a, uint32_t b0, uint32_t b1){
    asm volatile("mma.sync.aligned.m16n8k16.row.col.f32.bf16.bf16.f32 "
        "{%0,%1,%2,%3},{%4,%5,%6,%7},{%8,%9},{%0,%1,%2,%3};"
        : "+f"(c[0]), "+f"(c[1]), "+f"(c[2]), "+f"(c[3])
        : "r"(a[0]), "r"(a[1]), "r"(a[2]), "r"(a[3]), "r"(b0), "r"(b1));
}
// swizzled byte offset inside a [rows x 128 bf16] tile (256B rows, 16B xor)
static __device__ __forceinline__ uint32_t sw_off(int row, int k){
    return (uint32_t)(row*256 + ((((k >> 3) ^ (row & 7))) << 4) + (k & 7)*2);
}
static __device__ __forceinline__ uint32_t pack_bf(float a, float b){
    __nv_bfloat162 h = __floats2bfloat162_rn(a, b);
    return *reinterpret_cast<uint32_t*>(&h);
}
static __device__ __forceinline__ void split_pair(float a, float b, uint32_t &hi, uint32_t &lo){
    __nv_bfloat16 ha = __float2bfloat16(a);
    __nv_bfloat16 hb = __float2bfloat16(b);
    __nv_bfloat162 H; H.x = ha; H.y = hb;
    hi = *reinterpret_cast<uint32_t*>(&H);
    lo = pack_bf(a - __bfloat162float(ha), b - __bfloat162float(hb));
}

// warp GEMM: MT*16 rows x (NP*16) cols, K=128, 3 split terms.
// Merged-BH mainloop: BH loaded once per k-step and used for ah*bh AND al*bh;
// BL loaded once for ah*bl. 12 ldsm per k-step at MT=2/NP=4 (was 26).
// acc layout: acc[mi*2*NP + 2*np + h][4]
template<int NP, int MT>
static __device__ __forceinline__ void gemm_warp(
    uint32_t su, uint32_t offAH, uint32_t offAL, uint32_t offBH, uint32_t offBL,
    const uint32_t* a_rbase, uint32_t a_rx, int a_k8, int b_nin, int b_k8, int ncol0,
    float (*acc)[4])
{
    #pragma unroll 1
    for (int ks = 0; ks < 8; ++ks){
        uint32_t ah[MT][4], al[MT][4];
        uint32_t ak3 = (uint32_t)(ks*2 + a_k8);
        #pragma unroll
        for (int mi = 0; mi < MT; ++mi){
            uint32_t aoff = a_rbase[mi] + ((ak3 ^ a_rx) << 4);
            ldsm4(ah[mi], su + offAH + aoff);
            ldsm4(al[mi], su + offAL + aoff);
        }
        uint32_t bk3 = (uint32_t)(ks*2 + b_k8);
        uint32_t boffs[NP];
        #pragma unroll
        for (int np = 0; np < NP; ++np){
            int brow = ncol0 + np*16 + b_nin;
            boffs[np] = (uint32_t)(brow*256) + ((bk3 ^ (uint32_t)(brow & 7)) << 4);
        }
        uint32_t bf[NP][4];
        // BH: use for ah*bh and al*bh
        #pragma unroll
        for (int np = 0; np < NP; ++np) ldsm4(bf[np], su + offBH + boffs[np]);
        #pragma unroll
        for (int np = 0; np < NP; ++np)
            #pragma unroll
            for (int mi = 0; mi < MT; ++mi){
                mma16816(acc[mi*2*NP + 2*np],     ah[mi], bf[np][0], bf[np][1]);
                mma16816(acc[mi*2*NP + 2*np + 1], ah[mi], bf[np][2], bf[np][3]);
            }
        #pragma unroll
        for (int np = 0; np < NP; ++np)
            #pragma unroll
            for (int mi = 0; mi < MT; ++mi){
                mma16816(acc[mi*2*NP + 2*np],     al[mi], bf[np][0], bf[np][1]);
                mma16816(acc[mi*2*NP + 2*np + 1], al[mi], bf[np][2], bf[np][3]);
            }
        // BL: ah*bl
        #pragma unroll
        for (int np = 0; np < NP; ++np) ldsm4(bf[np], su + offBL + boffs[np]);
        #pragma unroll
        for (int np = 0; np < NP; ++np)
            #pragma unroll
            for (int mi = 0; mi < MT; ++mi){
                mma16816(acc[mi*2*NP + 2*np],     ah[mi], bf[np][0], bf[np][1]);
                mma16816(acc[mi*2*NP + 2*np + 1], ah[mi], bf[np][2], bf[np][3]);
            }
    }
}

// ===================== weight prep: 18 transposed split images ==============
__global__ void __launch_bounds__(256) prep_w(
    const float* __restrict__ W1w,  const float* __restrict__ W2w,
    const float* __restrict__ W3w,  const float* __restrict__ W11w,
    const float* __restrict__ W12w, const float* __restrict__ W13w,
    const float* __restrict__ Winw, const float* __restrict__ Woutw)
{
    extern __shared__ float ws[];   // [128][128]
    const int b = blockIdx.x;
    const float* ptr; int ld = 128;
    switch (b){
        case 0: ptr = W1w + 128*128; break;
        case 1: ptr = W2w;  break;
        case 2: ptr = W3w;  break;
        case 3: ptr = W11w + 128*128; break;
        case 4: ptr = W12w; break;
        case 5: ptr = W13w; break;
        case 6: ptr = W1w;  break;
        case 7: ptr = W1w + 256*128; break;
        case 8: ptr = W11w; break;
        case 9: ptr = W11w + 256*128; break;
        case 10: case 11: case 12: case 13:
            ptr = Winw + (b - 10)*128; ld = 512; break;
        default: // 14..17
            ptr = Woutw + (size_t)(b - 14)*128*128; break;
    }
    const int t = threadIdx.x;
    for (int idx = t; idx < 4096; idx += 256){
        int k = idx >> 5, n4 = (idx & 31)*4;
        *(float4*)(ws + k*128 + n4) = *(const float4*)(ptr + (size_t)k*ld + n4);
    }
    __syncthreads();

    __nv_bfloat16* hi = g_Wimg + (size_t)b * 32768;
    __nv_bfloat16* lo = hi + 16384;
    for (int c = t; c < 2048; c += 256){
        int row = c >> 4;            // n
        int k0  = (c & 15) << 3;     // k
        union { uint32_t u[4]; uint4 q; } H, L;
        #pragma unroll
        for (int j = 0; j < 4; ++j){
            float w0 = ws[(k0 + 2*j    )*128 + row];
            float w1 = ws[(k0 + 2*j + 1)*128 + row];
            split_pair(w0, w1, H.u[j], L.u[j]);
        }
        uint32_t off = (uint32_t)(row*256 + (((k0 >> 3) ^ (row & 7)) << 4));
        *(uint4*)((char*)hi + off) = H.q;
        *(uint4*)((char*)lo + off) = L.q;
    }
}

// ===================== node kernel: PQ (MODE 0) / FFN (MODE 1) ==============
// 16 rows per CTA, 128 threads (4 warps: warp = 16 rows x 32 cols, NP=2)
#define NODE_SMEM 90368
#define N_AH 0u
#define N_AL 4096u
#define N_HH 8192u
#define N_HL 12288u
#define N_BH 16384u
#define N_BL 49152u
#define N_SCR 81920u

template<int MODE>
__global__ void __launch_bounds__(128, 2) node_mma(
    const float* __restrict__ src,            // PQ: nodes ; FFN: g_hV1
    const __nv_bfloat16* __restrict__ imgQ,   // PQ: Wq img ; FFN: WinT chunk base
    const __nv_bfloat16* __restrict__ imgP,   // PQ: Wp img ; FFN: WoutT chunk base
    const float* __restrict__ ba,             // PQ: W1b ; FFN: bin
    const float* __restrict__ bout,
    const float* __restrict__ gam, const float* __restrict__ bet,
    const float* __restrict__ maskV,
    float* __restrict__ outQ, float* __restrict__ outP,   // PQ outputs
    float* __restrict__ outV)                              // FFN output
{
    extern __shared__ char smc[];
    const uint32_t su = smem_u32(smc);
    const int t = threadIdx.x, lane = t & 31, w = t >> 5;
    const int blk = blockIdx.x;
    const int r0g = blk*16;

    // 4 warps = 4 col-groups of 32, all covering rows 0..15
    const int ncol0 = w*32;
    const int qrow = lane >> 2, qcol = (lane & 3)*2;
    const int rowA = qrow, rowB = rowA + 8;
    const int sel = lane >> 3, la7 = lane & 7;
    const int a_row = la7 + ((sel & 1) << 3);
    uint32_t a_rbase[1] = { (uint32_t)(a_row*256) };
    const uint32_t a_rx = (uint32_t)(a_row & 7);
    const int a_k8 = sel >> 1;
    const int b_nin = la7 + ((sel >> 1) << 3);
    const int b_k8 = sel & 1;

    // ---- stage A (16 rows of src, split) -----------------------------------
    for (int c = t; c < 256; c += 128){
        int row = c >> 4, k0 = (c & 15) << 3;
        const float4* s = (const float4*)(src + (size_t)(r0g + row)*128 + k0);
        float4 v0 = s[0], v1 = s[1];
        union { uint32_t u[4]; uint4 q; } H, L;
        split_pair(v0.x, v0.y, H.u[0], L.u[0]);
        split_pair(v0.z, v0.w, H.u[1], L.u[1]);
        split_pair(v1.x, v1.y, H.u[2], L.u[2]);
        split_pair(v1.z, v1.w, H.u[3], L.u[3]);
        uint32_t off = (uint32_t)(row*256 + (((k0 >> 3) ^ (row & 7)) << 4));
        *(uint4*)(smc + N_AH + off) = H.q;
        *(uint4*)(smc + N_AL + off) = L.q;
    }

    if (MODE == 0){
        // ------------------- PQ: two GEMMs ----------------------------------
        #pragma unroll 1
        for (int m = 0; m < 2; ++m){
            __syncthreads();
            const __nv_bfloat16* img = m ? imgP : imgQ;
            {
                const uint4* sH = (const uint4*)img;
                const uint4* sL = sH + 2048;
                uint4* dH = (uint4*)(smc + N_BH);
                uint4* dL = (uint4*)(smc + N_BL);
                #pragma unroll
                for (int i = 0; i < 16; ++i){ dH[t + i*128] = sH[t + i*128]; dL[t + i*128] = sL[t + i*128]; }
            }
            __syncthreads();
            float acc[4][4];
            #pragma unroll
            for (int i = 0; i < 4; ++i){
                if (m == 0){
                    float2 b2 = *(const float2*)(ba + ncol0 + i*8 + qcol);
                    acc[i][0] = b2.x; acc[i][1] = b2.y; acc[i][2] = b2.x; acc[i][3] = b2.y;
                } else {
                    acc[i][0] = acc[i][1] = acc[i][2] = acc[i][3] = 0.f;
                }
            }
            gemm_warp<2,1>(su, N_AH, N_AL, N_BH, N_BL, a_rbase, a_rx, a_k8, b_nin, b_k8, ncol0, acc);
            float* dst = m ? outP : outQ;
            #pragma unroll
            for (int i = 0; i < 4; ++i){
                int n = ncol0 + i*8 + qcol;
                *(float2*)(dst + (size_t)(r0g + rowA)*128 + n) = make_float2(acc[i][0], acc[i][1]);
                *(float2*)(dst + (size_t)(r0g + rowB)*128 + n) = make_float2(acc[i][2], acc[i][3]);
            }
        }
    } else {
        // ------------------- FFN: 4 chunks of hidden ------------------------
        float out_acc[4][4];
        #pragma unroll
        for (int i = 0; i < 4; ++i){
            float2 b2 = *(const float2*)(bout + ncol0 + i*8 + qcol);
            out_acc[i][0] = b2.x; out_acc[i][1] = b2.y;
            out_acc[i][2] = b2.x; out_acc[i][3] = b2.y;
        }
        #pragma unroll 1
        for (int c = 0; c < 4; ++c){
            __syncthreads();
            {
                const uint4* sH = (const uint4*)(imgQ + (size_t)c*32768);
                const uint4* sL = sH + 2048;
                uint4* dH = (uint4*)(smc + N_BH);
                uint4* dL = (uint4*)(smc + N_BL);
                #pragma unroll
                for (int i = 0; i < 16; ++i){ dH[t + i*128] = sH[t + i*128]; dL[t + i*128] = sL[t + i*128]; }
            }
            __syncthreads();
            float h_acc[4][4];
            #pragma unroll
            for (int i = 0; i < 4; ++i){
                float2 b2 = *(const float2*)(ba + c*128 + ncol0 + i*8 + qcol);
                h_acc[i][0] = b2.x; h_acc[i][1] = b2.y;
                h_acc[i][2] = b2.x; h_acc[i][3] = b2.y;
            }
            gemm_warp<2,1>(su, N_AH, N_AL, N_BH, N_BL, a_rbase, a_rx, a_k8, b_nin, b_k8, ncol0, h_acc);
            // gelu + split into H tiles
            #pragma unroll
            for (int i = 0; i < 4; ++i){
                int n = ncol0 + i*8 + qcol;
                float g0 = gelu_f(h_acc[i][0]), g1 = gelu_f(h_acc[i][1]);
                float g2v = gelu_f(h_acc[i][2]), g3v = gelu_f(h_acc[i][3]);
                uint32_t hA, lA, hB, lB;
                split_pair(g0, g1, hA, lA);
                split_pair(g2v, g3v, hB, lB);
                uint32_t offA = sw_off(rowA, n), offB = sw_off(rowB, n);
                *(uint32_t*)(smc + N_HH + offA) = hA;
                *(uint32_t*)(smc + N_HL + offA) = lA;
                *(uint32_t*)(smc + N_HH + offB) = hB;
                *(uint32_t*)(smc + N_HL + offB) = lB;
            }
            __syncthreads();
            {
                const uint4* sH = (const uint4*)(imgP + (size_t)c*32768);
                const uint4* sL = sH + 2048;
                uint4* dH = (uint4*)(smc + N_BH);
                uint4* dL = (uint4*)(smc + N_BL);
                #pragma unroll
                for (int i = 0; i < 16; ++i){ dH[t + i*128] = sH[t + i*128]; dL[t + i*128] = sL[t + i*128]; }
            }
            __syncthreads();
            gemm_warp<2,1>(su, N_HH, N_HL, N_BH, N_BL, a_rbase, a_rx, a_k8, b_nin, b_k8, ncol0, out_acc);
        }
        // ---- epilogue: residual + LN + mask -> outV, g_hV2 -----------------
        __syncthreads();
        float* scr = (float*)(smc + N_SCR);   // [16][132]
        #pragma unroll
        for (int i = 0; i < 4; ++i){
            int n = ncol0 + i*8 + qcol;
            float2 rA = *(const float2*)(src + (size_t)(r0g + rowA)*128 + n);
            float2 rB = *(const float2*)(src + (size_t)(r0g + rowB)*128 + n);
            scr[rowA*132 + n]     = rA.x + out_acc[i][0];
            scr[rowA*132 + n + 1] = rA.y + out_acc[i][1];
            scr[rowB*132 + n]     = rB.x + out_acc[i][2];
            scr[rowB*132 + n + 1] = rB.y + out_acc[i][3];
        }
        __syncthreads();
        #pragma unroll 1
        for (int r8 = 0; r8 < 4; ++r8){
            int r = w*4 + r8;
            int node = r0g + r;
            float x0 = scr[r*132 + lane],      x1 = scr[r*132 + lane + 32];
            float x2 = scr[r*132 + lane + 64], x3 = scr[r*132 + lane + 96];
            float s = warp_sum(x0 + x1 + x2 + x3);
            float q = warp_sum(x0*x0 + x1*x1 + x2*x2 + x3*x3);
            float mean = s * 0.0078125f;
            float var  = q * 0.0078125f - mean*mean;
            float rs = rsqrtf(var + EPSf);
            float mv = maskV[node];
            float y0 = mv*(gam[lane]     *(x0 - mean)*rs + bet[lane]);
            float y1 = mv*(gam[lane + 32]*(x1 - mean)*rs + bet[lane + 32]);
            float y2 = mv*(gam[lane + 64]*(x2 - mean)*rs + bet[lane + 64]);
            float y3 = mv*(gam[lane + 96]*(x3 - mean)*rs + bet[lane + 96]);
            float* o = outV + (size_t)node*128;
            o[lane] = y0; o[lane+32] = y1; o[lane+64] = y2; o[lane+96] = y3;
            float* g = g_hV2 + (size_t)node*128;
            g[lane] = y0; g[lane+32] = y1; g[lane+64] = y2; g[lane+96] = y3;
        }
    }
}

// ======================= edge pass: 2 nodes (96 rows) per CTA ===============
// 192 threads / 6 warps (3 row-groups x 2 col-groups; warp tile 32x64).
#define EDGE_SMEM 115200
#define E_AH 512u
#define E_AL 25088u
#define E_BH 49664u
#define E_BL 82432u

template<int MODE>
__global__ void __launch_bounds__(192, 2) edge_mma(
    const float* __restrict__ hE,
    const int*   __restrict__ Eidx,
    const float* __restrict__ maskA,
    const __nv_bfloat16* __restrict__ Wimg,   // 3 layer slots x 32768 bf16
    const float* __restrict__ bb, const float* __restrict__ bc,
    const float* __restrict__ residV,
    const float* __restrict__ gam, const float* __restrict__ bet,
    float* __restrict__ outp)                 // MODE0: g_hV1 ; MODE1: outE
{
    extern __shared__ char smc[];
    const uint32_t su = smem_u32(smc);
    int*   sidx = (int*)smc;                  // 96 ints (384B)
    float* s_s  = (float*)(smc + 384);        // [2][4]
    float* s_q  = (float*)(smc + 416);        // [2][4]

    const int t = threadIdx.x, lane = t & 31, wid = t >> 5;
    const int blk = blockIdx.x, node0 = blk*2;
    const int nbase = (node0 >> 11) << 11;

    if (t < 96) sidx[t] = Eidx[(size_t)blk*96 + t];

    // ---- stage A (h_E, 96 rows split) + B layer 0 --------------------------
    for (int c = t; c < 1536; c += 192){
        int row = c >> 4, k0 = (c & 15) << 3;
        const float4* s = (const float4*)(hE + ((size_t)blk*96 + row)*128 + k0);
        float4 v0 = s[0], v1 = s[1];
        union { uint32_t u[4]; uint4 q; } H, L;
        split_pair(v0.x, v0.y, H.u[0], L.u[0]);
        split_pair(v0.z, v0.w, H.u[1], L.u[1]);
        split_pair(v1.x, v1.y, H.u[2], L.u[2]);
        split_pair(v1.z, v1.w, H.u[3], L.u[3]);
        uint32_t off = (uint32_t)(row*256 + (((k0 >> 3) ^ (row & 7)) << 4));
        *(uint4*)(smc + E_AH + off) = H.q;
        *(uint4*)(smc + E_AL + off) = L.q;
    }
    {
        const uint4* sH = (const uint4*)Wimg;
        const uint4* sL = sH + 2048;
        uint4* dH = (uint4*)(smc + E_BH);
        uint4* dL = (uint4*)(smc + E_BL);
        for (int i = t; i < 2048; i += 192){ dH[i] = sH[i]; dL[i] = sL[i]; }
    }
    __syncthreads();

    // warp geometry: warp tile 32 rows x 64 cols
    const int rgrp = wid >> 1, cgrp = wid & 1;
    const int m0 = rgrp*32, ncol0 = cgrp*64;
    const int qrow = lane >> 2, qcol = (lane & 3)*2;
    const int sel = lane >> 3, la7 = lane & 7;
    const int a_row0 = m0 + la7 + ((sel & 1) << 3);
    uint32_t a_rbase[2] = { (uint32_t)(a_row0*256), (uint32_t)((a_row0 + 16)*256) };
    const uint32_t a_rx = (uint32_t)(a_row0 & 7);
    const int a_k8 = sel >> 1;
    const int b_nin = la7 + ((sel >> 1) << 3);
    const int b_k8 = sel & 1;

    float acc[16][4];    // acc[mi*8 + ni][.]  (mi 0..1, ni 0..7)

    #pragma unroll 1
    for (int l = 0; l < 3; ++l){
        // ---- init accumulators ---------------------------------------------
        if (l == 0){
            #pragma unroll
            for (int mi = 0; mi < 2; ++mi){
                int r0 = m0 + mi*16 + qrow, r1 = r0 + 8;
                const float* q0 = g_Q + (size_t)(node0 + r0/48)*128;
                const float* p0 = g_P + (size_t)(nbase + sidx[r0])*128;
                const float* q1 = g_Q + (size_t)(node0 + r1/48)*128;
                const float* p1 = g_P + (size_t)(nbase + sidx[r1])*128;
                #pragma unroll
                for (int ni = 0; ni < 8; ++ni){
                    int n = ncol0 + ni*8 + qcol;
                    float2 qa = *(const float2*)(q0 + n), pa = *(const float2*)(p0 + n);
                    float2 qb = *(const float2*)(q1 + n), pb = *(const float2*)(p1 + n);
                    acc[mi*8+ni][0] = qa.x + pa.x; acc[mi*8+ni][1] = qa.y + pa.y;
                    acc[mi*8+ni][2] = qb.x + pb.x; acc[mi*8+ni][3] = qb.y + pb.y;
                }
            }
        } else {
            const float* bias = (l == 1) ? bb : bc;
            #pragma unroll
            for (int mi = 0; mi < 2; ++mi)
                #pragma unroll
                for (int ni = 0; ni < 8; ++ni){
                    float2 b2 = *(const float2*)(bias + ncol0 + ni*8 + qcol);
                    acc[mi*8+ni][0] = b2.x; acc[mi*8+ni][1] = b2.y;
                    acc[mi*8+ni][2] = b2.x; acc[mi*8+ni][3] = b2.y;
                }
        }

        gemm_warp<4,2>(su, E_AH, E_AL, E_BH, E_BL, a_rbase, a_rx, a_k8, b_nin, b_k8, ncol0, acc);

        if (l < 2){
            __syncthreads();     // all A/B reads done before overwrite
            #pragma unroll
            for (int mi = 0; mi < 2; ++mi){
                int r0 = m0 + mi*16 + qrow, r1 = r0 + 8;
                #pragma unroll
                for (int ni = 0; ni < 8; ++ni){
                    int n = ncol0 + ni*8 + qcol;
                    float g0 = gelu_f(acc[mi*8+ni][0]), g1 = gelu_f(acc[mi*8+ni][1]);
                    float g2v = gelu_f(acc[mi*8+ni][2]), g3v = gelu_f(acc[mi*8+ni][3]);
                    uint32_t hA, lA, hB, lB;
                    split_pair(g0, g1, hA, lA);
                    split_pair(g2v, g3v, hB, lB);
                    uint32_t offA = sw_off(r0, n), offB = sw_off(r1, n);
                    *(uint32_t*)(smc + E_AH + offA) = hA;
                    *(uint32_t*)(smc + E_AL + offA) = lA;
                    *(uint32_t*)(smc + E_AH + offB) = hB;
                    *(uint32_t*)(smc + E_AL + offB) = lB;
                }
            }
            {
                const uint4* sH = (const uint4*)(Wimg + (size_t)(l + 1)*32768);
                const uint4* sL = sH + 2048;
                uint4* dH = (uint4*)(smc + E_BH);
                uint4* dL = (uint4*)(smc + E_BL);
                for (int i = t; i < 2048; i += 192){ dH[i] = sH[i]; dL[i] = sL[i]; }
            }
            __syncthreads();
        }
    }

    // ======================= final epilogue ================================
    if (MODE == 0){
        __syncthreads();                         // B reads done; reuse as scratch
        float* scratch = (float*)(smc + E_BH);   // [96][132] = 50688 B
        float* xs      = (float*)(smc + E_BH + 51200);  // [256]
        #pragma unroll
        for (int mi = 0; mi < 2; ++mi){
            int r0 = m0 + mi*16 + qrow, r1 = r0 + 8;
            float mv0 = maskA[(size_t)blk*96 + r0];
            float mv1 = maskA[(size_t)blk*96 + r1];
            #pragma unroll
            for (int ni = 0; ni < 8; ++ni){
                int n = ncol0 + ni*8 + qcol;
                scratch[r0*132 + n]     = mv0*acc[mi*8+ni][0];
                scratch[r0*132 + n + 1] = mv0*acc[mi*8+ni][1];
                scratch[r1*132 + n]     = mv1*acc[mi*8+ni][2];
                scratch[r1*132 + n + 1] = mv1*acc[mi*8+ni][3];
            }
        }
        __syncthreads();
        for (int idx = t; idx < 256; idx += 192){
            int nl = idx >> 7, c = idx & 127;
            float s = 0.f;
            #pragma unroll 8
            for (int k = 0; k < 48; ++k) s += scratch[(nl*48 + k)*132 + c];
            float xv = residV[(size_t)(node0 + nl)*128 + c] + s * INV_SCALE;
            xs[idx] = xv;
            float ws = warp_sum(xv), wq = warp_sum(xv*xv);
            if (lane == 0){ s_s[nl*4 + ((idx >> 5) & 3)] = ws; s_q[nl*4 + ((idx >> 5) & 3)] = wq; }
        }
        __syncthreads();
        for (int idx = t; idx < 256; idx += 192){
            int nl = idx >> 7, c = idx & 127;
            float mean = (s_s[nl*4] + s_s[nl*4+1] + s_s[nl*4+2] + s_s[nl*4+3]) * 0.0078125f;
            float var  = (s_q[nl*4] + s_q[nl*4+1] + s_q[nl*4+2] + s_q[nl*4+3]) * 0.0078125f - mean*mean;
            outp[(size_t)(node0 + nl)*128 + c] =
                gam[c]*(xs[idx] - mean)*rsqrtf(var + EPSf) + bet[c];
        }
    } else {
        // per-edge LN(h_E + msg): row sums split across 2 col-groups
        __syncthreads();                        // B reads done; reuse
        float* sp = (float*)(smc + E_BH);       // [96][2]
        float* sq = sp + 192;                   // [96][2]
        #pragma unroll
        for (int mi = 0; mi < 2; ++mi){
            int r0 = m0 + mi*16 + qrow, r1 = r0 + 8;
            const float* e0 = hE + ((size_t)blk*96 + r0)*128;
            const float* e1 = hE + ((size_t)blk*96 + r1)*128;
            float s0 = 0.f, q0 = 0.f, s1 = 0.f, q1 = 0.f;
            #pragma unroll
            for (int ni = 0; ni < 8; ++ni){
                int n = ncol0 + ni*8 + qcol;
                float2 ea = *(const float2*)(e0 + n);
                float2 eb = *(const float2*)(e1 + n);
                float v0 = ea.x + acc[mi*8+ni][0], v1 = ea.y + acc[mi*8+ni][1];
                float v2 = eb.x + acc[mi*8+ni][2], v3 = eb.y + acc[mi*8+ni][3];
                acc[mi*8+ni][0] = v0; acc[mi*8+ni][1] = v1;
                acc[mi*8+ni][2] = v2; acc[mi*8+ni][3] = v3;
                s0 += v0 + v1; q0 += v0*v0 + v1*v1;
                s1 += v2 + v3; q1 += v2*v2 + v3*v3;
            }
            s0 += __shfl_xor_sync(0xffffffffu, s0, 1); s0 += __shfl_xor_sync(0xffffffffu, s0, 2);
            q0 += __shfl_xor_sync(0xffffffffu, q0, 1); q0 += __shfl_xor_sync(0xffffffffu, q0, 2);
            s1 += __shfl_xor_sync(0xffffffffu, s1, 1); s1 += __shfl_xor_sync(0xffffffffu, s1, 2);
            q1 += __shfl_xor_sync(0xffffffffu, q1, 1); q1 += __shfl_xor_sync(0xffffffffu, q1, 2);
            if ((lane & 3) == 0){
                sp[r0*2 + cgrp] = s0; sq[r0*2 + cgrp] = q0;
                sp[r1*2 + cgrp] = s1; sq[r1*2 + cgrp] = q1;
            }
        }
        __syncthreads();
        #pragma unroll
        for (int mi = 0; mi < 2; ++mi){
            int r0 = m0 + mi*16 + qrow, r1 = r0 + 8;
            float mean0 = (sp[r0*2] + sp[r0*2+1]) * 0.0078125f;
            float var0  = (sq[r0*2] + sq[r0*2+1]) * 0.0078125f - mean0*mean0;
            float rs0 = rsqrtf(var0 + EPSf);
            float mean1 = (sp[r1*2] + sp[r1*2+1]) * 0.0078125f;
            float var1  = (sq[r1*2] + sq[r1*2+1]) * 0.0078125f - mean1*mean1;
            float rs1 = rsqrtf(var1 + EPSf);
            float* o0 = outp + ((size_t)blk*96 + r0)*128;
            float* o1 = outp + ((size_t)blk*96 + r1)*128;
            #pragma unroll
            for (int ni = 0; ni < 8; ++ni){
                int n = ncol0 + ni*8 + qcol;
                float2 g = *(const float2*)(gam + n);
                float2 b = *(const float2*)(bet + n);
                float2 oA, oB;
                oA.x = g.x*(acc[mi*8+ni][0] - mean0)*rs0 + b.x;
                oA.y = g.y*(acc[mi*8+ni][1] - mean0)*rs0 + b.y;
                oB.x = g.x*(acc[mi*8+ni][2] - mean1)*rs1 + b.x;
                oB.y = g.y*(acc[mi*8+ni][3] - mean1)*rs1 + b.y;
                *(float2*)(o0 + n) = oA;
                *(float2*)(o1 + n) = oB;
            }
        }
    }
}

// ---------------------------------------------------------------------------
extern "C" void kernel_launch(void* const* d_in, const int* in_sizes, int n_in,
                              void* d_out, int out_size)
{
    const float* hV    = (const float*)d_in[0];
    const float* hE    = (const float*)d_in[1];
    const int*   Eidx  = (const int*)  d_in[2];
    const float* maskV = (const float*)d_in[3];
    const float* maskA = (const float*)d_in[4];
    const float* W1w   = (const float*)d_in[5];  const float* W1b  = (const float*)d_in[6];
    const float* W2w   = (const float*)d_in[7];  const float* W2b  = (const float*)d_in[8];
    const float* W3w   = (const float*)d_in[9];  const float* W3b  = (const float*)d_in[10];
    const float* W11w  = (const float*)d_in[11]; const float* W11b = (const float*)d_in[12];
    const float* W12w  = (const float*)d_in[13]; const float* W12b = (const float*)d_in[14];
    const float* W13w  = (const float*)d_in[15]; const float* W13b = (const float*)d_in[16];
    const float* Winw  = (const float*)d_in[17]; const float* Winb = (const float*)d_in[18];
    const float* Woutw = (const float*)d_in[19]; const float* Woutb= (const float*)d_in[20];
    const float* g1    = (const float*)d_in[21]; const float* b1   = (const float*)d_in[22];
    const float* g2    = (const float*)d_in[23]; const float* b2   = (const float*)d_in[24];
    const float* g3    = (const float*)d_in[25]; const float* b3   = (const float*)d_in[26];

    float* out  = (float*)d_out;
    float* outV = out;
    float* outE = out + (size_t)NODES*Cc;

    float* hV1p; cudaGetSymbolAddress((void**)&hV1p, g_hV1);
    float* hV2p; cudaGetSymbolAddress((void**)&hV2p, g_hV2);
    float* gQp;  cudaGetSymbolAddress((void**)&gQp,  g_Q);
    float* gPp;  cudaGetSymbolAddress((void**)&gPp,  g_P);
    __nv_bfloat16* wimg; cudaGetSymbolAddress((void**)&wimg, g_Wimg);

    cudaFuncSetAttribute(prep_w,      cudaFuncAttributeMaxDynamicSharedMemorySize, 65536);
    cudaFuncSetAttribute(node_mma<0>, cudaFuncAttributeMaxDynamicSharedMemorySize, NODE_SMEM);
    cudaFuncSetAttribute(node_mma<1>, cudaFuncAttributeMaxDynamicSharedMemorySize, NODE_SMEM);
    cudaFuncSetAttribute(edge_mma<0>, cudaFuncAttributeMaxDynamicSharedMemorySize, EDGE_SMEM);
    cudaFuncSetAttribute(edge_mma<1>, cudaFuncAttributeMaxDynamicSharedMemorySize, EDGE_SMEM);

    prep_w<<<18, 256, 65536>>>(W1w, W2w, W3w, W11w, W12w, W13w, Winw, Woutw);

    // pass 1: node message
    node_mma<0><<<NODES/16, 128, NODE_SMEM>>>(
        hV, wimg + (size_t)6*32768, wimg + (size_t)7*32768,
        W1b, nullptr, nullptr, nullptr, nullptr, gQp, gPp, nullptr);
    edge_mma<0><<<NODES/2, 192, EDGE_SMEM>>>(
        hE, Eidx, maskA, wimg, W2b, W3b, hV, g1, b1, hV1p);

    // FFN + LN2 + mask
    node_mma<1><<<NODES/16, 128, NODE_SMEM>>>(
        hV1p, wimg + (size_t)10*32768, wimg + (size_t)14*32768,
        Winb, Woutb, g2, b2, maskV, nullptr, nullptr, outV);

    // pass 2: edge update
    node_mma<0><<<NODES/16, 128, NODE_SMEM>>>(
        hV2p, wimg + (size_t)8*32768, wimg + (size_t)9*32768,
        W11b, nullptr, nullptr, nullptr, nullptr, gQp, gPp, nullptr);
    edge_mma<1><<<NODES/2, 192, EDGE_SMEM>>>(
        hE, Eidx, maskA, wimg + (size_t)3*32768, W12b, W13b, hE, g3, b3, outE);
}

// round 12
// speedup vs baseline: 4.6901x; 1.1930x over previous
#include <cuda_runtime.h>
#include <cuda_fp16.h>
#include <math.h>
#include <stdint.h>

#define Bb 2
#define Nn 2048
#define Kk 48
#define Cc 128
#define NODES (Bb*Nn)          /* 4096 */
#define EPSf 1e-5f
#define INV_SCALE (1.0f/30.0f)

// device scratch (no allocations allowed)
__device__ float g_hV1[NODES*Cc];
__device__ float g_hV2[NODES*Cc];
__device__ float g_P[NODES*Cc];
__device__ float g_Q[NODES*Cc];
__device__ __half g_Wimg[18*32768];   // 18 images x (hi 16384 + lo 16384) fp16

// ---------------- helpers ---------------------------------------------------
static __device__ __forceinline__ float gelu_f(float x){
    return 0.5f * x * (1.0f + erff(x * 0.70710678118654752440f));
}
static __device__ __forceinline__ float warp_sum(float v){
    #pragma unroll
    for (int o = 16; o; o >>= 1) v += __shfl_xor_sync(0xffffffffu, v, o);
    return v;
}
static __device__ __forceinline__ uint32_t smem_u32(const void* p){
    uint32_t a;
    asm("{ .reg .u64 t; cvta.to.shared.u64 t, %1; cvt.u32.u64 %0, t; }" : "=r"(a) : "l"(p));
    return a;
}
static __device__ __forceinline__ void ldsm4(uint32_t* r, uint32_t addr){
    asm volatile("ldmatrix.sync.aligned.m8n8.x4.shared.b16 {%0,%1,%2,%3}, [%4];"
        : "=r"(r[0]), "=r"(r[1]), "=r"(r[2]), "=r"(r[3]) : "r"(addr));
}
static __device__ __forceinline__ void mma16816(float* c, const uint32_t* a, uint32_t b0, uint32_t b1){
    asm volatile("mma.sync.aligned.m16n8k16.row.col.f32.f16.f16.f32 "
        "{%0,%1,%2,%3},{%4,%5,%6,%7},{%8,%9},{%0,%1,%2,%3};"
        : "+f"(c[0]), "+f"(c[1]), "+f"(c[2]), "+f"(c[3])
        : "r"(a[0]), "r"(a[1]), "r"(a[2]), "r"(a[3]), "r"(b0), "r"(b1));
}
// swizzled byte offset inside a [rows x 128 fp16] tile (256B rows, 16B xor)
static __device__ __forceinline__ uint32_t sw_off(int row, int k){
    return (uint32_t)(row*256 + ((((k >> 3) ^ (row & 7))) << 4) + (k & 7)*2);
}
static __device__ __forceinline__ uint32_t pack_h(float a, float b){
    __half2 h = __floats2half2_rn(a, b);
    return *reinterpret_cast<uint32_t*>(&h);
}
static __device__ __forceinline__ void split_pair_h(float a, float b, uint32_t &hi, uint32_t &lo){
    __half2 H = __floats2half2_rn(a, b);
    float2 hf = __half22float2(H);
    hi = *reinterpret_cast<uint32_t*>(&H);
    lo = pack_h(a - hf.x, b - hf.y);
}

// warp GEMM: MT*16 rows x (NP*16) cols, K=128, fp16 2-term (A single, B hi+lo).
// acc layout: acc[mi*2*NP + 2*np + h][4]
template<int NP, int MT>
static __device__ __forceinline__ void gemm_warp2(
    uint32_t su, uint32_t offA, uint32_t offBH, uint32_t offBL,
    const uint32_t* a_rbase, uint32_t a_rx, int a_k8, int b_nin, int b_k8, int ncol0,
    float (*acc)[4])
{
    #pragma unroll 1
    for (int ks = 0; ks < 8; ++ks){
        uint32_t ah[MT][4];
        uint32_t ak3 = (uint32_t)(ks*2 + a_k8);
        #pragma unroll
        for (int mi = 0; mi < MT; ++mi){
            uint32_t aoff = a_rbase[mi] + ((ak3 ^ a_rx) << 4);
            ldsm4(ah[mi], su + offA + aoff);
        }
        uint32_t bk3 = (uint32_t)(ks*2 + b_k8);
        uint32_t boffs[NP];
        #pragma unroll
        for (int np = 0; np < NP; ++np){
            int brow = ncol0 + np*16 + b_nin;
            boffs[np] = (uint32_t)(brow*256) + ((bk3 ^ (uint32_t)(brow & 7)) << 4);
        }
        uint32_t bf[NP][4];
        // sweep 1: A x BH
        #pragma unroll
        for (int np = 0; np < NP; ++np) ldsm4(bf[np], su + offBH + boffs[np]);
        #pragma unroll
        for (int np = 0; np < NP; ++np)
            #pragma unroll
            for (int mi = 0; mi < MT; ++mi){
                mma16816(acc[mi*2*NP + 2*np],     ah[mi], bf[np][0], bf[np][1]);
                mma16816(acc[mi*2*NP + 2*np + 1], ah[mi], bf[np][2], bf[np][3]);
            }
        // sweep 2: A x BL
        #pragma unroll
        for (int np = 0; np < NP; ++np) ldsm4(bf[np], su + offBL + boffs[np]);
        #pragma unroll
        for (int np = 0; np < NP; ++np)
            #pragma unroll
            for (int mi = 0; mi < MT; ++mi){
                mma16816(acc[mi*2*NP + 2*np],     ah[mi], bf[np][0], bf[np][1]);
                mma16816(acc[mi*2*NP + 2*np + 1], ah[mi], bf[np][2], bf[np][3]);
            }
    }
}

// ===================== weight prep: 18 transposed split images ==============
__global__ void __launch_bounds__(256) prep_w(
    const float* __restrict__ W1w,  const float* __restrict__ W2w,
    const float* __restrict__ W3w,  const float* __restrict__ W11w,
    const float* __restrict__ W12w, const float* __restrict__ W13w,
    const float* __restrict__ Winw, const float* __restrict__ Woutw)
{
    extern __shared__ float ws[];   // [128][128]
    const int b = blockIdx.x;
    const float* ptr; int ld = 128;
    switch (b){
        case 0: ptr = W1w + 128*128; break;
        case 1: ptr = W2w;  break;
        case 2: ptr = W3w;  break;
        case 3: ptr = W11w + 128*128; break;
        case 4: ptr = W12w; break;
        case 5: ptr = W13w; break;
        case 6: ptr = W1w;  break;
        case 7: ptr = W1w + 256*128; break;
        case 8: ptr = W11w; break;
        case 9: ptr = W11w + 256*128; break;
        case 10: case 11: case 12: case 13:
            ptr = Winw + (b - 10)*128; ld = 512; break;
        default: // 14..17
            ptr = Woutw + (size_t)(b - 14)*128*128; break;
    }
    const int t = threadIdx.x;
    for (int idx = t; idx < 4096; idx += 256){
        int k = idx >> 5, n4 = (idx & 31)*4;
        *(float4*)(ws + k*128 + n4) = *(const float4*)(ptr + (size_t)k*ld + n4);
    }
    __syncthreads();

    __half* hi = g_Wimg + (size_t)b * 32768;
    __half* lo = hi + 16384;
    for (int c = t; c < 2048; c += 256){
        int row = c >> 4;            // n
        int k0  = (c & 15) << 3;     // k
        union { uint32_t u[4]; uint4 q; } H, L;
        #pragma unroll
        for (int j = 0; j < 4; ++j){
            float w0 = ws[(k0 + 2*j    )*128 + row];
            float w1 = ws[(k0 + 2*j + 1)*128 + row];
            split_pair_h(w0, w1, H.u[j], L.u[j]);
        }
        uint32_t off = (uint32_t)(row*256 + (((k0 >> 3) ^ (row & 7)) << 4));
        *(uint4*)((char*)hi + off) = H.q;
        *(uint4*)((char*)lo + off) = L.q;
    }
}

// ===================== node kernel: PQ (MODE 0) / FFN (MODE 1) ==============
// 16 rows per CTA, 128 threads (4 warps: warp = 16 rows x 32 cols, NP=2)
#define NODE_SMEM 90368
#define N_A  0u
#define N_H  4096u
#define N_BH 8192u
#define N_BL 40960u
#define N_SCR 73728u

template<int MODE>
__global__ void __launch_bounds__(128, 2) node_mma(
    const float* __restrict__ src,            // PQ: nodes ; FFN: g_hV1
    const __half* __restrict__ imgQ,          // PQ: Wq img ; FFN: WinT chunk base
    const __half* __restrict__ imgP,          // PQ: Wp img ; FFN: WoutT chunk base
    const float* __restrict__ ba,             // PQ: W1b ; FFN: bin
    const float* __restrict__ bout,
    const float* __restrict__ gam, const float* __restrict__ bet,
    const float* __restrict__ maskV,
    float* __restrict__ outQ, float* __restrict__ outP,   // PQ outputs
    float* __restrict__ outV)                              // FFN output
{
    extern __shared__ char smc[];
    const uint32_t su = smem_u32(smc);
    const int t = threadIdx.x, lane = t & 31, w = t >> 5;
    const int blk = blockIdx.x;
    const int r0g = blk*16;

    // 4 warps = 4 col-groups of 32, all covering rows 0..15
    const int ncol0 = w*32;
    const int qrow = lane >> 2, qcol = (lane & 3)*2;
    const int rowA = qrow, rowB = rowA + 8;
    const int sel = lane >> 3, la7 = lane & 7;
    const int a_row = la7 + ((sel & 1) << 3);
    uint32_t a_rbase[1] = { (uint32_t)(a_row*256) };
    const uint32_t a_rx = (uint32_t)(a_row & 7);
    const int a_k8 = sel >> 1;
    const int b_nin = la7 + ((sel >> 1) << 3);
    const int b_k8 = sel & 1;

    // ---- stage A (16 rows of src, fp16) ------------------------------------
    for (int c = t; c < 256; c += 128){
        int row = c >> 4, k0 = (c & 15) << 3;
        const float4* s = (const float4*)(src + (size_t)(r0g + row)*128 + k0);
        float4 v0 = s[0], v1 = s[1];
        union { uint32_t u[4]; uint4 q; } H;
        H.u[0] = pack_h(v0.x, v0.y);
        H.u[1] = pack_h(v0.z, v0.w);
        H.u[2] = pack_h(v1.x, v1.y);
        H.u[3] = pack_h(v1.z, v1.w);
        uint32_t off = (uint32_t)(row*256 + (((k0 >> 3) ^ (row & 7)) << 4));
        *(uint4*)(smc + N_A + off) = H.q;
    }

    if (MODE == 0){
        // ------------------- PQ: two GEMMs ----------------------------------
        #pragma unroll 1
        for (int m = 0; m < 2; ++m){
            __syncthreads();
            const __half* img = m ? imgP : imgQ;
            {
                const uint4* sH = (const uint4*)img;
                const uint4* sL = sH + 2048;
                uint4* dH = (uint4*)(smc + N_BH);
                uint4* dL = (uint4*)(smc + N_BL);
                #pragma unroll
                for (int i = 0; i < 16; ++i){ dH[t + i*128] = sH[t + i*128]; dL[t + i*128] = sL[t + i*128]; }
            }
            __syncthreads();
            float acc[4][4];
            #pragma unroll
            for (int i = 0; i < 4; ++i){
                if (m == 0){
                    float2 b2 = *(const float2*)(ba + ncol0 + i*8 + qcol);
                    acc[i][0] = b2.x; acc[i][1] = b2.y; acc[i][2] = b2.x; acc[i][3] = b2.y;
                } else {
                    acc[i][0] = acc[i][1] = acc[i][2] = acc[i][3] = 0.f;
                }
            }
            gemm_warp2<2,1>(su, N_A, N_BH, N_BL, a_rbase, a_rx, a_k8, b_nin, b_k8, ncol0, acc);
            float* dst = m ? outP : outQ;
            #pragma unroll
            for (int i = 0; i < 4; ++i){
                int n = ncol0 + i*8 + qcol;
                *(float2*)(dst + (size_t)(r0g + rowA)*128 + n) = make_float2(acc[i][0], acc[i][1]);
                *(float2*)(dst + (size_t)(r0g + rowB)*128 + n) = make_float2(acc[i][2], acc[i][3]);
            }
        }
    } else {
        // ------------------- FFN: 4 chunks of hidden ------------------------
        float out_acc[4][4];
        #pragma unroll
        for (int i = 0; i < 4; ++i){
            float2 b2 = *(const float2*)(bout + ncol0 + i*8 + qcol);
            out_acc[i][0] = b2.x; out_acc[i][1] = b2.y;
            out_acc[i][2] = b2.x; out_acc[i][3] = b2.y;
        }
        #pragma unroll 1
        for (int c = 0; c < 4; ++c){
            __syncthreads();
            {
                const uint4* sH = (const uint4*)(imgQ + (size_t)c*32768);
                const uint4* sL = sH + 2048;
                uint4* dH = (uint4*)(smc + N_BH);
                uint4* dL = (uint4*)(smc + N_BL);
                #pragma unroll
                for (int i = 0; i < 16; ++i){ dH[t + i*128] = sH[t + i*128]; dL[t + i*128] = sL[t + i*128]; }
            }
            __syncthreads();
            float h_acc[4][4];
            #pragma unroll
            for (int i = 0; i < 4; ++i){
                float2 b2 = *(const float2*)(ba + c*128 + ncol0 + i*8 + qcol);
                h_acc[i][0] = b2.x; h_acc[i][1] = b2.y;
                h_acc[i][2] = b2.x; h_acc[i][3] = b2.y;
            }
            gemm_warp2<2,1>(su, N_A, N_BH, N_BL, a_rbase, a_rx, a_k8, b_nin, b_k8, ncol0, h_acc);
            // gelu + fp16 into H tile
            #pragma unroll
            for (int i = 0; i < 4; ++i){
                int n = ncol0 + i*8 + qcol;
                uint32_t hA = pack_h(gelu_f(h_acc[i][0]), gelu_f(h_acc[i][1]));
                uint32_t hB = pack_h(gelu_f(h_acc[i][2]), gelu_f(h_acc[i][3]));
                *(uint32_t*)(smc + N_H + sw_off(rowA, n)) = hA;
                *(uint32_t*)(smc + N_H + sw_off(rowB, n)) = hB;
            }
            __syncthreads();
            {
                const uint4* sH = (const uint4*)(imgP + (size_t)c*32768);
                const uint4* sL = sH + 2048;
                uint4* dH = (uint4*)(smc + N_BH);
                uint4* dL = (uint4*)(smc + N_BL);
                #pragma unroll
                for (int i = 0; i < 16; ++i){ dH[t + i*128] = sH[t + i*128]; dL[t + i*128] = sL[t + i*128]; }
            }
            __syncthreads();
            gemm_warp2<2,1>(su, N_H, N_BH, N_BL, a_rbase, a_rx, a_k8, b_nin, b_k8, ncol0, out_acc);
        }
        // ---- epilogue: residual + LN + mask -> outV, g_hV2 -----------------
        __syncthreads();
        float* scr = (float*)(smc + N_SCR);   // [16][132]
        #pragma unroll
        for (int i = 0; i < 4; ++i){
            int n = ncol0 + i*8 + qcol;
            float2 rA = *(const float2*)(src + (size_t)(r0g + rowA)*128 + n);
            float2 rB = *(const float2*)(src + (size_t)(r0g + rowB)*128 + n);
            scr[rowA*132 + n]     = rA.x + out_acc[i][0];
            scr[rowA*132 + n + 1] = rA.y + out_acc[i][1];
            scr[rowB*132 + n]     = rB.x + out_acc[i][2];
            scr[rowB*132 + n + 1] = rB.y + out_acc[i][3];
        }
        __syncthreads();
        #pragma unroll 1
        for (int r8 = 0; r8 < 4; ++r8){
            int r = w*4 + r8;
            int node = r0g + r;
            float x0 = scr[r*132 + lane],      x1 = scr[r*132 + lane + 32];
            float x2 = scr[r*132 + lane + 64], x3 = scr[r*132 + lane + 96];
            float s = warp_sum(x0 + x1 + x2 + x3);
            float q = warp_sum(x0*x0 + x1*x1 + x2*x2 + x3*x3);
            float mean = s * 0.0078125f;
            float var  = q * 0.0078125f - mean*mean;
            float rs = rsqrtf(var + EPSf);
            float mv = maskV[node];
            float y0 = mv*(gam[lane]     *(x0 - mean)*rs + bet[lane]);
            float y1 = mv*(gam[lane + 32]*(x1 - mean)*rs + bet[lane + 32]);
            float y2 = mv*(gam[lane + 64]*(x2 - mean)*rs + bet[lane + 64]);
            float y3 = mv*(gam[lane + 96]*(x3 - mean)*rs + bet[lane + 96]);
            float* o = outV + (size_t)node*128;
            o[lane] = y0; o[lane+32] = y1; o[lane+64] = y2; o[lane+96] = y3;
            float* g = g_hV2 + (size_t)node*128;
            g[lane] = y0; g[lane+32] = y1; g[lane+64] = y2; g[lane+96] = y3;
        }
    }
}

// ======================= edge pass: 2 nodes (96 rows) per CTA ===============
// 192 threads / 6 warps (3 row-groups x 2 col-groups; warp tile 32x64).
// smem 90112B = 11 x 8KB -> 2 CTAs/SM.
#define EDGE_SMEM 90112
#define E_A  0u
#define E_BH 24576u
#define E_BL 57344u

template<int MODE>
__global__ void __launch_bounds__(192, 2) edge_mma(
    const float* __restrict__ hE,
    const int*   __restrict__ Eidx,
    const float* __restrict__ maskA,
    const __half* __restrict__ Wimg,          // 3 layer slots x 32768 fp16
    const float* __restrict__ bb, const float* __restrict__ bc,
    const float* __restrict__ residV,
    const float* __restrict__ gam, const float* __restrict__ bet,
    float* __restrict__ outp)                 // MODE0: g_hV1 ; MODE1: outE
{
    extern __shared__ char smc[];
    const uint32_t su = smem_u32(smc);

    const int t = threadIdx.x, lane = t & 31, wid = t >> 5;
    const int blk = blockIdx.x, node0 = blk*2;
    const int nbase = (node0 >> 11) << 11;

    // ---- stage A (h_E, 96 rows fp16) + B layer 0 ---------------------------
    for (int c = t; c < 1536; c += 192){
        int row = c >> 4, k0 = (c & 15) << 3;
        const float4* s = (const float4*)(hE + ((size_t)blk*96 + row)*128 + k0);
        float4 v0 = s[0], v1 = s[1];
        union { uint32_t u[4]; uint4 q; } H;
        H.u[0] = pack_h(v0.x, v0.y);
        H.u[1] = pack_h(v0.z, v0.w);
        H.u[2] = pack_h(v1.x, v1.y);
        H.u[3] = pack_h(v1.z, v1.w);
        uint32_t off = (uint32_t)(row*256 + (((k0 >> 3) ^ (row & 7)) << 4));
        *(uint4*)(smc + E_A + off) = H.q;
    }
    {
        const uint4* sH = (const uint4*)Wimg;
        const uint4* sL = sH + 2048;
        uint4* dH = (uint4*)(smc + E_BH);
        uint4* dL = (uint4*)(smc + E_BL);
        for (int i = t; i < 2048; i += 192){ dH[i] = sH[i]; dL[i] = sL[i]; }
    }
    __syncthreads();

    // warp geometry: warp tile 32 rows x 64 cols
    const int rgrp = wid >> 1, cgrp = wid & 1;
    const int m0 = rgrp*32, ncol0 = cgrp*64;
    const int qrow = lane >> 2, qcol = (lane & 3)*2;
    const int sel = lane >> 3, la7 = lane & 7;
    const int a_row0 = m0 + la7 + ((sel & 1) << 3);
    uint32_t a_rbase[2] = { (uint32_t)(a_row0*256), (uint32_t)((a_row0 + 16)*256) };
    const uint32_t a_rx = (uint32_t)(a_row0 & 7);
    const int a_k8 = sel >> 1;
    const int b_nin = la7 + ((sel >> 1) << 3);
    const int b_k8 = sel & 1;

    float acc[16][4];    // acc[mi*8 + ni][.]  (mi 0..1, ni 0..7)

    #pragma unroll 1
    for (int l = 0; l < 3; ++l){
        // ---- init accumulators ---------------------------------------------
        if (l == 0){
            #pragma unroll
            for (int mi = 0; mi < 2; ++mi){
                int r0 = m0 + mi*16 + qrow, r1 = r0 + 8;
                int i0 = Eidx[(size_t)blk*96 + r0];
                int i1 = Eidx[(size_t)blk*96 + r1];
                const float* q0 = g_Q + (size_t)(node0 + r0/48)*128;
                const float* p0 = g_P + (size_t)(nbase + i0)*128;
                const float* q1 = g_Q + (size_t)(node0 + r1/48)*128;
                const float* p1 = g_P + (size_t)(nbase + i1)*128;
                #pragma unroll
                for (int ni = 0; ni < 8; ++ni){
                    int n = ncol0 + ni*8 + qcol;
                    float2 qa = *(const float2*)(q0 + n), pa = *(const float2*)(p0 + n);
                    float2 qb = *(const float2*)(q1 + n), pb = *(const float2*)(p1 + n);
                    acc[mi*8+ni][0] = qa.x + pa.x; acc[mi*8+ni][1] = qa.y + pa.y;
                    acc[mi*8+ni][2] = qb.x + pb.x; acc[mi*8+ni][3] = qb.y + pb.y;
                }
            }
        } else {
            const float* bias = (l == 1) ? bb : bc;
            #pragma unroll
            for (int mi = 0; mi < 2; ++mi)
                #pragma unroll
                for (int ni = 0; ni < 8; ++ni){
                    float2 b2 = *(const float2*)(bias + ncol0 + ni*8 + qcol);
                    acc[mi*8+ni][0] = b2.x; acc[mi*8+ni][1] = b2.y;
                    acc[mi*8+ni][2] = b2.x; acc[mi*8+ni][3] = b2.y;
                }
        }

        gemm_warp2<4,2>(su, E_A, E_BH, E_BL, a_rbase, a_rx, a_k8, b_nin, b_k8, ncol0, acc);

        if (l < 2){
            __syncthreads();     // all A/B reads done before overwrite
            #pragma unroll
            for (int mi = 0; mi < 2; ++mi){
                int r0 = m0 + mi*16 + qrow, r1 = r0 + 8;
                #pragma unroll
                for (int ni = 0; ni < 8; ++ni){
                    int n = ncol0 + ni*8 + qcol;
                    uint32_t hA = pack_h(gelu_f(acc[mi*8+ni][0]), gelu_f(acc[mi*8+ni][1]));
                    uint32_t hB = pack_h(gelu_f(acc[mi*8+ni][2]), gelu_f(acc[mi*8+ni][3]));
                    *(uint32_t*)(smc + E_A + sw_off(r0, n)) = hA;
                    *(uint32_t*)(smc + E_A + sw_off(r1, n)) = hB;
                }
            }
            {
                const uint4* sH = (const uint4*)(Wimg + (size_t)(l + 1)*32768);
                const uint4* sL = sH + 2048;
                uint4* dH = (uint4*)(smc + E_BH);
                uint4* dL = (uint4*)(smc + E_BL);
                for (int i = t; i < 2048; i += 192){ dH[i] = sH[i]; dL[i] = sL[i]; }
            }
            __syncthreads();
        }
    }

    // ======================= final epilogue ================================
    if (MODE == 0){
        __syncthreads();                         // tiles dead; reuse as scratch
        float* scratch = (float*)(smc);          // [96][132] = 50688 B
        float* xs      = (float*)(smc + 50688);  // [256]
        float* s_s     = (float*)(smc + 51712);  // [2][4]
        float* s_q     = (float*)(smc + 51744);  // [2][4]
        #pragma unroll
        for (int mi = 0; mi < 2; ++mi){
            int r0 = m0 + mi*16 + qrow, r1 = r0 + 8;
            float mv0 = maskA[(size_t)blk*96 + r0];
            float mv1 = maskA[(size_t)blk*96 + r1];
            #pragma unroll
            for (int ni = 0; ni < 8; ++ni){
                int n = ncol0 + ni*8 + qcol;
                scratch[r0*132 + n]     = mv0*acc[mi*8+ni][0];
                scratch[r0*132 + n + 1] = mv0*acc[mi*8+ni][1];
                scratch[r1*132 + n]     = mv1*acc[mi*8+ni][2];
                scratch[r1*132 + n + 1] = mv1*acc[mi*8+ni][3];
            }
        }
        __syncthreads();
        for (int idx = t; idx < 256; idx += 192){
            int nl = idx >> 7, c = idx & 127;
            float s = 0.f;
            #pragma unroll 8
            for (int k = 0; k < 48; ++k) s += scratch[(nl*48 + k)*132 + c];
            float xv = residV[(size_t)(node0 + nl)*128 + c] + s * INV_SCALE;
            xs[idx] = xv;
            float ws = warp_sum(xv), wq = warp_sum(xv*xv);
            if (lane == 0){ s_s[nl*4 + ((idx >> 5) & 3)] = ws; s_q[nl*4 + ((idx >> 5) & 3)] = wq; }
        }
        __syncthreads();
        for (int idx = t; idx < 256; idx += 192){
            int nl = idx >> 7, c = idx & 127;
            float mean = (s_s[nl*4] + s_s[nl*4+1] + s_s[nl*4+2] + s_s[nl*4+3]) * 0.0078125f;
            float var  = (s_q[nl*4] + s_q[nl*4+1] + s_q[nl*4+2] + s_q[nl*4+3]) * 0.0078125f - mean*mean;
            outp[(size_t)(node0 + nl)*128 + c] =
                gam[c]*(xs[idx] - mean)*rsqrtf(var + EPSf) + bet[c];
        }
    } else {
        // per-edge LN(h_E + msg): row sums split across 2 col-groups
        __syncthreads();                        // tiles dead; reuse
        float* sp = (float*)(smc);              // [96][2]
        float* sq = sp + 192;                   // [96][2]
        #pragma unroll
        for (int mi = 0; mi < 2; ++mi){
            int r0 = m0 + mi*16 + qrow, r1 = r0 + 8;
            const float* e0 = hE + ((size_t)blk*96 + r0)*128;
            const float* e1 = hE + ((size_t)blk*96 + r1)*128;
            float s0 = 0.f, q0 = 0.f, s1 = 0.f, q1 = 0.f;
            #pragma unroll
            for (int ni = 0; ni < 8; ++ni){
                int n = ncol0 + ni*8 + qcol;
                float2 ea = *(const float2*)(e0 + n);
                float2 eb = *(const float2*)(e1 + n);
                float v0 = ea.x + acc[mi*8+ni][0], v1 = ea.y + acc[mi*8+ni][1];
                float v2 = eb.x + acc[mi*8+ni][2], v3 = eb.y + acc[mi*8+ni][3];
                acc[mi*8+ni][0] = v0; acc[mi*8+ni][1] = v1;
                acc[mi*8+ni][2] = v2; acc[mi*8+ni][3] = v3;
                s0 += v0 + v1; q0 += v0*v0 + v1*v1;
                s1 += v2 + v3; q1 += v2*v2 + v3*v3;
            }
            s0 += __shfl_xor_sync(0xffffffffu, s0, 1); s0 += __shfl_xor_sync(0xffffffffu, s0, 2);
            q0 += __shfl_xor_sync(0xffffffffu, q0, 1); q0 += __shfl_xor_sync(0xffffffffu, q0, 2);
            s1 += __shfl_xor_sync(0xffffffffu, s1, 1); s1 += __shfl_xor_sync(0xffffffffu, s1, 2);
            q1 += __shfl_xor_sync(0xffffffffu, q1, 1); q1 += __shfl_xor_sync(0xffffffffu, q1, 2);
            if ((lane & 3) == 0){
                sp[r0*2 + cgrp] = s0; sq[r0*2 + cgrp] = q0;
                sp[r1*2 + cgrp] = s1; sq[r1*2 + cgrp] = q1;
            }
        }
        __syncthreads();
        #pragma unroll
        for (int mi = 0; mi < 2; ++mi){
            int r0 = m0 + mi*16 + qrow, r1 = r0 + 8;
            float mean0 = (sp[r0*2] + sp[r0*2+1]) * 0.0078125f;
            float var0  = (sq[r0*2] + sq[r0*2+1]) * 0.0078125f - mean0*mean0;
            float rs0 = rsqrtf(var0 + EPSf);
            float mean1 = (sp[r1*2] + sp[r1*2+1]) * 0.0078125f;
            float var1  = (sq[r1*2] + sq[r1*2+1]) * 0.0078125f - mean1*mean1;
            float rs1 = rsqrtf(var1 + EPSf);
            float* o0 = outp + ((size_t)blk*96 + r0)*128;
            float* o1 = outp + ((size_t)blk*96 + r1)*128;
            #pragma unroll
            for (int ni = 0; ni < 8; ++ni){
                int n = ncol0 + ni*8 + qcol;
                float2 g = *(const float2*)(gam + n);
                float2 b = *(const float2*)(bet + n);
                float2 oA, oB;
                oA.x = g.x*(acc[mi*8+ni][0] - mean0)*rs0 + b.x;
                oA.y = g.y*(acc[mi*8+ni][1] - mean0)*rs0 + b.y;
                oB.x = g.x*(acc[mi*8+ni][2] - mean1)*rs1 + b.x;
                oB.y = g.y*(acc[mi*8+ni][3] - mean1)*rs1 + b.y;
                *(float2*)(o0 + n) = oA;
                *(float2*)(o1 + n) = oB;
            }
        }
    }
}

// ---------------------------------------------------------------------------
extern "C" void kernel_launch(void* const* d_in, const int* in_sizes, int n_in,
                              void* d_out, int out_size)
{
    const float* hV    = (const float*)d_in[0];
    const float* hE    = (const float*)d_in[1];
    const int*   Eidx  = (const int*)  d_in[2];
    const float* maskV = (const float*)d_in[3];
    const float* maskA = (const float*)d_in[4];
    const float* W1w   = (const float*)d_in[5];  const float* W1b  = (const float*)d_in[6];
    const float* W2w   = (const float*)d_in[7];  const float* W2b  = (const float*)d_in[8];
    const float* W3w   = (const float*)d_in[9];  const float* W3b  = (const float*)d_in[10];
    const float* W11w  = (const float*)d_in[11]; const float* W11b = (const float*)d_in[12];
    const float* W12w  = (const float*)d_in[13]; const float* W12b = (const float*)d_in[14];
    const float* W13w  = (const float*)d_in[15]; const float* W13b = (const float*)d_in[16];
    const float* Winw  = (const float*)d_in[17]; const float* Winb = (const float*)d_in[18];
    const float* Woutw = (const float*)d_in[19]; const float* Woutb= (const float*)d_in[20];
    const float* g1    = (const float*)d_in[21]; const float* b1   = (const float*)d_in[22];
    const float* g2    = (const float*)d_in[23]; const float* b2   = (const float*)d_in[24];
    const float* g3    = (const float*)d_in[25]; const float* b3   = (const float*)d_in[26];

    float* out  = (float*)d_out;
    float* outV = out;
    float* outE = out + (size_t)NODES*Cc;

    float* hV1p; cudaGetSymbolAddress((void**)&hV1p, g_hV1);
    float* hV2p; cudaGetSymbolAddress((void**)&hV2p, g_hV2);
    float* gQp;  cudaGetSymbolAddress((void**)&gQp,  g_Q);
    float* gPp;  cudaGetSymbolAddress((void**)&gPp,  g_P);
    __half* wimg; cudaGetSymbolAddress((void**)&wimg, g_Wimg);

    cudaFuncSetAttribute(prep_w,      cudaFuncAttributeMaxDynamicSharedMemorySize, 65536);
    cudaFuncSetAttribute(node_mma<0>, cudaFuncAttributeMaxDynamicSharedMemorySize, NODE_SMEM);
    cudaFuncSetAttribute(node_mma<1>, cudaFuncAttributeMaxDynamicSharedMemorySize, NODE_SMEM);
    cudaFuncSetAttribute(edge_mma<0>, cudaFuncAttributeMaxDynamicSharedMemorySize, EDGE_SMEM);
    cudaFuncSetAttribute(edge_mma<1>, cudaFuncAttributeMaxDynamicSharedMemorySize, EDGE_SMEM);

    prep_w<<<18, 256, 65536>>>(W1w, W2w, W3w, W11w, W12w, W13w, Winw, Woutw);

    // pass 1: node message
    node_mma<0><<<NODES/16, 128, NODE_SMEM>>>(
        hV, wimg + (size_t)6*32768, wimg + (size_t)7*32768,
        W1b, nullptr, nullptr, nullptr, nullptr, gQp, gPp, nullptr);
    edge_mma<0><<<NODES/2, 192, EDGE_SMEM>>>(
        hE, Eidx, maskA, wimg, W2b, W3b, hV, g1, b1, hV1p);

    // FFN + LN2 + mask
    node_mma<1><<<NODES/16, 128, NODE_SMEM>>>(
        hV1p, wimg + (size_t)10*32768, wimg + (size_t)14*32768,
        Winb, Woutb, g2, b2, maskV, nullptr, nullptr, outV);

    // pass 2: edge update
    node_mma<0><<<NODES/16, 128, NODE_SMEM>>>(
        hV2p, wimg + (size_t)8*32768, wimg + (size_t)9*32768,
        W11b, nullptr, nullptr, nullptr, nullptr, gQp, gPp, nullptr);
    edge_mma<1><<<NODES/2, 192, EDGE_SMEM>>>(
        hE, Eidx, maskA, wimg + (size_t)3*32768, W12b, W13b, hE, g3, b3, outE);
}